// round 1
// baseline (speedup 1.0000x reference)
#include <cuda_runtime.h>
#include <math.h>

#define B_   4
#define SEQ_ 12
#define NN   1024
#define SL   3
#define SG   4
#define HID  64
#define FFD  2048
#define DKk  32
#define LAY  2
#define TOK  (B_*NN*SG)   /* 16384 */
#define GRP  (B_*SG)      /* 16 */

// ---------------- scratch (static device memory, no runtime allocation) ----------------
__device__ float d_Z[TOK*HID];        // activations [b][n][seg][h]
__device__ float d_Qb[GRP*NN*DKk];
__device__ float d_Kb[GRP*NN*DKk];
__device__ float d_Vb[GRP*NN*HID];
__device__ float d_ATT[GRP*NN*HID];
__device__ float d_ENC[B_*NN*2*HID];
__device__ float d_Q2[B_*NN*DKk];
__device__ float d_K2[B_*NN*DKk];
__device__ float d_V2[B_*NN*HID];

// ---------------- patch embedding + positional encoding ----------------
// z[b,n,seg,h] = sum_l pw[h,l]*x[b, seg*3+l, n] + pb[h] + pe[seg,h]
__global__ __launch_bounds__(256) void patch_kernel(const float* __restrict__ x,
                                                    const float* __restrict__ pw,
                                                    const float* __restrict__ pb,
                                                    float* __restrict__ Z) {
    int bn = blockIdx.x;                 // 0..4095  (b*1024+n)
    int b  = bn >> 10, n = bn & 1023;
    int t  = threadIdx.x;                // 0..255
    int seg = t >> 6, h = t & 63;
    float acc = pb[h];
#pragma unroll
    for (int l = 0; l < SL; l++)
        acc += pw[h*SL + l] * x[(b*SEQ_ + seg*SL + l)*NN + n];
    int he = h & ~1;
    float dv = expf(-(float)he * (9.210340371976184f / (float)HID));  // ln(10000)/64
    float ang = (float)seg * dv;
    acc += (h & 1) ? cosf(ang) : sinf(ang);
    Z[(bn*SG + seg)*HID + h] = acc;
}

// ---------------- temporal encoder: MHA + residual + LN1 (4 tokens per block) ----------------
__global__ __launch_bounds__(128) void mha_kernel(float* __restrict__ Z,
        const float* __restrict__ mw, const float* __restrict__ mb,
        const float* __restrict__ ow, const float* __restrict__ ob,
        const float* __restrict__ g1, const float* __restrict__ b1) {
    __shared__ float xs[SG][HID];
    __shared__ float qk[SG][3*HID];
    __shared__ float sc[8*SG*SG];     // [head][qi][kj] = 128
    __shared__ float os[SG][HID];
    __shared__ float ys[SG][HID];
    int bn = blockIdx.x, tid = threadIdx.x;
    float* zb = Z + (size_t)bn * SG * HID;

    for (int idx = tid; idx < SG*HID; idx += 128) xs[idx>>6][idx&63] = zb[idx];
    __syncthreads();

    // qkv = x @ W^T + b   (768 outputs)
    for (int idx = tid; idx < SG*192; idx += 128) {
        int r = idx / 192, c = idx % 192;
        const float* wr = mw + c*HID;
        float a = mb[c];
#pragma unroll 16
        for (int k = 0; k < HID; k++) a += xs[r][k] * wr[k];
        qk[r][c] = a;
    }
    __syncthreads();

    // scores (8 heads x 4 x 4), scale 1/sqrt(8)
    {
        int h = tid >> 4, i = (tid >> 2) & 3, j = tid & 3;
        float s = 0.f;
#pragma unroll
        for (int d = 0; d < 8; d++) s += qk[i][h*8 + d] * qk[j][HID + h*8 + d];
        sc[tid] = s * 0.3535533905932738f;
    }
    __syncthreads();
    if (tid < 32) {   // softmax per (head, query) row
        float* row = sc + tid*4;
        float m = fmaxf(fmaxf(row[0], row[1]), fmaxf(row[2], row[3]));
        float e0 = expf(row[0]-m), e1 = expf(row[1]-m), e2 = expf(row[2]-m), e3 = expf(row[3]-m);
        float inv = 1.f / (e0+e1+e2+e3);
        row[0]=e0*inv; row[1]=e1*inv; row[2]=e2*inv; row[3]=e3*inv;
    }
    __syncthreads();
    // o = att @ v (merged heads)
    for (int idx = tid; idx < SG*HID; idx += 128) {
        int i = idx >> 6, c = idx & 63, h = c >> 3;
        const float* a = sc + h*16 + i*4;
        os[i][c] = a[0]*qk[0][128+c] + a[1]*qk[1][128+c] + a[2]*qk[2][128+c] + a[3]*qk[3][128+c];
    }
    __syncthreads();
    // out proj + residual
    for (int idx = tid; idx < SG*HID; idx += 128) {
        int i = idx >> 6, c = idx & 63;
        const float* wr = ow + c*HID;
        float a = ob[c];
#pragma unroll 16
        for (int k = 0; k < HID; k++) a += os[i][k] * wr[k];
        ys[i][c] = xs[i][c] + a;
    }
    __syncthreads();
    // LayerNorm: warp w -> token row w
    int w = tid >> 5, lane = tid & 31;
    float v0 = ys[w][lane], v1 = ys[w][lane+32];
    float s = v0 + v1, q = v0*v0 + v1*v1;
#pragma unroll
    for (int o = 16; o; o >>= 1) { s += __shfl_xor_sync(0xffffffffu, s, o); q += __shfl_xor_sync(0xffffffffu, q, o); }
    float mean = s * (1.f/64.f);
    float var  = q * (1.f/64.f) - mean*mean;
    float rstd = rsqrtf(var + 1e-5f);
    zb[w*HID + lane]      = (v0 - mean)*rstd*g1[lane]    + b1[lane];
    zb[w*HID + lane + 32] = (v1 - mean)*rstd*g1[lane+32] + b1[lane+32];
}

// ---------------- fused FF (relu) + residual + LN, row-wise over 64-dim tokens ----------------
// y = LN(x + relu(x@W1^T + b1)@W2^T + b2) * g + bb ; 64 tokens/block, FF chunked by 32
__global__ __launch_bounds__(256) void ff_ln_kernel(float* __restrict__ Z,
        const float* __restrict__ w1, const float* __restrict__ b1,
        const float* __restrict__ w2, const float* __restrict__ b2,
        const float* __restrict__ g, const float* __restrict__ bb) {
    __shared__ float xs[64][65];
    __shared__ float hs[64][33];
    __shared__ float w1s[32][65];
    __shared__ float w2s[64][33];
    int tid = threadIdx.x;
    int t0  = blockIdx.x * 64;
    int ty = tid >> 4, tx = tid & 15;

    for (int idx = tid; idx < 64*64; idx += 256) xs[idx>>6][idx&63] = Z[(size_t)t0*64 + idx];

    float acc[4][4];
#pragma unroll
    for (int i = 0; i < 4; i++)
#pragma unroll
        for (int j = 0; j < 4; j++) acc[i][j] = 0.f;

    for (int fc = 0; fc < FFD; fc += 32) {
        __syncthreads();
        for (int idx = tid; idx < 32*64; idx += 256) { int r = idx>>6, c = idx&63; w1s[r][c] = w1[(size_t)(fc+r)*64 + c]; }
        for (int idx = tid; idx < 64*32; idx += 256) { int r = idx>>5, c = idx&31; w2s[r][c] = w2[(size_t)r*FFD + fc + c]; }
        __syncthreads();
        // H[64][32] = relu(X @ W1c^T + b1c) ; thread: rows 4*ty+i, cols tx+16*j
        float h4[4][2];
        float bv0 = b1[fc + tx], bv1 = b1[fc + tx + 16];
#pragma unroll
        for (int i = 0; i < 4; i++) { h4[i][0] = bv0; h4[i][1] = bv1; }
#pragma unroll 8
        for (int k = 0; k < 64; k++) {
            float x0 = xs[4*ty+0][k], x1 = xs[4*ty+1][k], x2 = xs[4*ty+2][k], x3 = xs[4*ty+3][k];
            float wv0 = w1s[tx][k], wv1 = w1s[tx+16][k];
            h4[0][0] += x0*wv0; h4[0][1] += x0*wv1;
            h4[1][0] += x1*wv0; h4[1][1] += x1*wv1;
            h4[2][0] += x2*wv0; h4[2][1] += x2*wv1;
            h4[3][0] += x3*wv0; h4[3][1] += x3*wv1;
        }
#pragma unroll
        for (int i = 0; i < 4; i++) {
            hs[4*ty+i][tx]    = fmaxf(h4[i][0], 0.f);
            hs[4*ty+i][tx+16] = fmaxf(h4[i][1], 0.f);
        }
        __syncthreads();
        // O[64][64] += H @ W2c^T ; thread: rows 4*ty+i, cols tx+16*j
#pragma unroll 4
        for (int c = 0; c < 32; c++) {
            float hv0 = hs[4*ty+0][c], hv1 = hs[4*ty+1][c], hv2 = hs[4*ty+2][c], hv3 = hs[4*ty+3][c];
            float wv0 = w2s[tx][c], wv1 = w2s[tx+16][c], wv2 = w2s[tx+32][c], wv3 = w2s[tx+48][c];
            acc[0][0]+=hv0*wv0; acc[0][1]+=hv0*wv1; acc[0][2]+=hv0*wv2; acc[0][3]+=hv0*wv3;
            acc[1][0]+=hv1*wv0; acc[1][1]+=hv1*wv1; acc[1][2]+=hv1*wv2; acc[1][3]+=hv1*wv3;
            acc[2][0]+=hv2*wv0; acc[2][1]+=hv2*wv1; acc[2][2]+=hv2*wv2; acc[2][3]+=hv2*wv3;
            acc[3][0]+=hv3*wv0; acc[3][1]+=hv3*wv1; acc[3][2]+=hv3*wv2; acc[3][3]+=hv3*wv3;
        }
    }
    __syncthreads();
    // residual into xs (each element has exactly one owner)
#pragma unroll
    for (int i = 0; i < 4; i++)
#pragma unroll
        for (int j = 0; j < 4; j++) {
            int r = 4*ty + i, c = tx + 16*j;
            xs[r][c] = acc[i][j] + b2[c] + xs[r][c];
        }
    __syncthreads();
    // LN: 8 warps, 8 rows each
    int w = tid >> 5, lane = tid & 31;
#pragma unroll
    for (int rr = 0; rr < 8; rr++) {
        int r = w*8 + rr;
        float v0 = xs[r][lane], v1 = xs[r][lane+32];
        float s = v0 + v1, q = v0*v0 + v1*v1;
#pragma unroll
        for (int o = 16; o; o >>= 1) { s += __shfl_xor_sync(0xffffffffu, s, o); q += __shfl_xor_sync(0xffffffffu, q, o); }
        float mean = s * (1.f/64.f);
        float var  = q * (1.f/64.f) - mean*mean;
        float rstd = rsqrtf(var + 1e-5f);
        Z[(size_t)(t0+r)*64 + lane]      = (v0 - mean)*rstd*g[lane]    + bb[lane];
        Z[(size_t)(t0+r)*64 + lane + 32] = (v1 - mean)*rstd*g[lane+32] + bb[lane+32];
    }
}

// ---------------- graph-attention QKV projection (strided read from Z) ----------------
__global__ __launch_bounds__(128) void ga_qkv_kernel(const float* __restrict__ Z,
        const float* __restrict__ wq, const float* __restrict__ wk, const float* __restrict__ wv,
        float* __restrict__ Q, float* __restrict__ K, float* __restrict__ V) {
    __shared__ float xs[16][65];
    int tid = threadIdx.x;
    int r0 = blockIdx.x * 16;
    for (int idx = tid; idx < 16*64; idx += 128) {
        int r = idx >> 6, c = idx & 63;
        int gr = r0 + r;
        int g2 = gr >> 10, n = gr & 1023;
        int b = g2 >> 2, seg = g2 & 3;
        xs[r][c] = Z[(size_t)(((b<<10)+n)*SG + seg)*HID + c];
    }
    __syncthreads();
    for (int o = tid; o < 16*128; o += 128) {
        int r = o >> 7, c = o & 127;
        const float* wr;
        if (c < 32) wr = wq + c*64; else if (c < 64) wr = wk + (c-32)*64; else wr = wv + (c-64)*64;
        float a = 0.f;
#pragma unroll 16
        for (int k = 0; k < 64; k++) a += xs[r][k] * wr[k];
        int gr = r0 + r;
        if (c < 32) Q[(size_t)gr*32 + c] = a;
        else if (c < 64) K[(size_t)gr*32 + c - 32] = a;
        else V[(size_t)gr*64 + c - 64] = a;
    }
}

// ---------------- attention: softmax(QK^T*scale)@V  (dk=32, dv=64, N=1024 per group) ----------------
__global__ __launch_bounds__(256) void attn_kernel(const float* __restrict__ Q,
        const float* __restrict__ K, const float* __restrict__ V,
        float* __restrict__ O, float scale) {
    __shared__ float qs[64][32];
    __shared__ float ks[32][33];
    __shared__ float vs[32][64];
    __shared__ float ps[64][33];
    int g2 = blockIdx.x;
    int q0 = blockIdx.y * 64;
    int tid = threadIdx.x;
    int ty = tid >> 4, tx = tid & 15;
    const float* Qg = Q + (size_t)g2*NN*32;
    const float* Kg = K + (size_t)g2*NN*32;
    const float* Vg = V + (size_t)g2*NN*64;

    for (int idx = tid; idx < 64*32; idx += 256) qs[idx>>5][idx&31] = Qg[(size_t)q0*32 + idx];

    float mrow[4] = {-1e30f, -1e30f, -1e30f, -1e30f};
    // pass 1: row max
    for (int kt = 0; kt < NN; kt += 32) {
        __syncthreads();
        for (int idx = tid; idx < 32*32; idx += 256) ks[idx>>5][idx&31] = Kg[(size_t)kt*32 + idx];
        __syncthreads();
#pragma unroll
        for (int i = 0; i < 4; i++) {
            int r = 4*ty + i;
#pragma unroll
            for (int j = 0; j < 2; j++) {
                int c = tx + 16*j;
                float s = 0.f;
#pragma unroll 8
                for (int d = 0; d < 32; d++) s += qs[r][d] * ks[c][d];
                mrow[i] = fmaxf(mrow[i], s * scale);
            }
        }
    }
#pragma unroll
    for (int o = 8; o; o >>= 1)
#pragma unroll
        for (int i = 0; i < 4; i++) mrow[i] = fmaxf(mrow[i], __shfl_xor_sync(0xffffffffu, mrow[i], o));

    float acc[4][4];
#pragma unroll
    for (int i = 0; i < 4; i++)
#pragma unroll
        for (int j = 0; j < 4; j++) acc[i][j] = 0.f;
    float lsum[4] = {0.f, 0.f, 0.f, 0.f};

    // pass 2: exp + accumulate
    for (int kt = 0; kt < NN; kt += 32) {
        __syncthreads();
        for (int idx = tid; idx < 32*32; idx += 256) ks[idx>>5][idx&31] = Kg[(size_t)kt*32 + idx];
        for (int idx = tid; idx < 32*64; idx += 256) vs[idx>>6][idx&63] = Vg[(size_t)kt*64 + idx];
        __syncthreads();
#pragma unroll
        for (int i = 0; i < 4; i++) {
            int r = 4*ty + i;
#pragma unroll
            for (int j = 0; j < 2; j++) {
                int c = tx + 16*j;
                float s = 0.f;
#pragma unroll 8
                for (int d = 0; d < 32; d++) s += qs[r][d] * ks[c][d];
                float p = expf(s * scale - mrow[i]);
                ps[r][c] = p;
                lsum[i] += p;
            }
        }
        __syncthreads();
#pragma unroll 4
        for (int c = 0; c < 32; c++) {
            float hv0 = ps[4*ty+0][c], hv1 = ps[4*ty+1][c], hv2 = ps[4*ty+2][c], hv3 = ps[4*ty+3][c];
            float wv0 = vs[c][tx], wv1 = vs[c][tx+16], wv2 = vs[c][tx+32], wv3 = vs[c][tx+48];
            acc[0][0]+=hv0*wv0; acc[0][1]+=hv0*wv1; acc[0][2]+=hv0*wv2; acc[0][3]+=hv0*wv3;
            acc[1][0]+=hv1*wv0; acc[1][1]+=hv1*wv1; acc[1][2]+=hv1*wv2; acc[1][3]+=hv1*wv3;
            acc[2][0]+=hv2*wv0; acc[2][1]+=hv2*wv1; acc[2][2]+=hv2*wv2; acc[2][3]+=hv2*wv3;
            acc[3][0]+=hv3*wv0; acc[3][1]+=hv3*wv1; acc[3][2]+=hv3*wv2; acc[3][3]+=hv3*wv3;
        }
    }
#pragma unroll
    for (int o = 8; o; o >>= 1)
#pragma unroll
        for (int i = 0; i < 4; i++) lsum[i] += __shfl_xor_sync(0xffffffffu, lsum[i], o);
#pragma unroll
    for (int i = 0; i < 4; i++) {
        float inv = 1.f / lsum[i];
#pragma unroll
        for (int j = 0; j < 4; j++)
            O[(size_t)(g2*NN + q0 + 4*ty + i)*64 + tx + 16*j] = acc[i][j] * inv;
    }
}

// ---------------- GA epilogue: att = LN(att)*g+b + x   (write into Z) ----------------
__global__ __launch_bounds__(256) void ga_epi_kernel(const float* __restrict__ ATT,
        float* __restrict__ Z, const float* __restrict__ g, const float* __restrict__ bb) {
    int w = threadIdx.x >> 5, lane = threadIdx.x & 31;
    int r = blockIdx.x * 8 + w;               // 0..16383
    int g2 = r >> 10, n = r & 1023, b = g2 >> 2, seg = g2 & 3;
    float* zp = Z + (size_t)(((b<<10)+n)*SG + seg)*HID;
    const float* ap = ATT + (size_t)r*HID;
    float v0 = ap[lane], v1 = ap[lane+32];
    float s = v0 + v1, q = v0*v0 + v1*v1;
#pragma unroll
    for (int o = 16; o; o >>= 1) { s += __shfl_xor_sync(0xffffffffu, s, o); q += __shfl_xor_sync(0xffffffffu, q, o); }
    float mean = s * (1.f/64.f);
    float var  = q * (1.f/64.f) - mean*mean;
    float rstd = rsqrtf(var + 1e-5f);
    zp[lane]      = (v0 - mean)*rstd*g[lane]    + bb[lane]    + zp[lane];
    zp[lane + 32] = (v1 - mean)*rstd*g[lane+32] + bb[lane+32] + zp[lane+32];
}

// ---------------- mean-pool over segments + concat into ENC ----------------
__global__ __launch_bounds__(256) void pool_kernel(const float* __restrict__ Z,
        float* __restrict__ ENC, int s) {
    int idx = blockIdx.x * 256 + threadIdx.x;   // over B*NN*64
    int bn = idx >> 6, h = idx & 63;
    float a = 0.25f * (Z[(size_t)(bn*4+0)*64+h] + Z[(size_t)(bn*4+1)*64+h] +
                       Z[(size_t)(bn*4+2)*64+h] + Z[(size_t)(bn*4+3)*64+h]);
    ENC[(size_t)bn*128 + s*64 + h] = a;
}

// ---------------- final cross-attention projections (in dim = 128) ----------------
__global__ __launch_bounds__(128) void fproj_kernel(const float* __restrict__ ENC,
        const float* __restrict__ wq, const float* __restrict__ wk, const float* __restrict__ wv,
        float* __restrict__ Q, float* __restrict__ K, float* __restrict__ V) {
    __shared__ float xs[16][129];
    int tid = threadIdx.x;
    int r0 = blockIdx.x * 16;
    for (int idx = tid; idx < 16*128; idx += 128) xs[idx>>7][idx&127] = ENC[(size_t)r0*128 + idx];
    __syncthreads();
    for (int o = tid; o < 16*128; o += 128) {
        int r = o >> 7, c = o & 127;
        const float* wr;
        if (c < 32) wr = wq + c*128; else if (c < 64) wr = wk + (c-32)*128; else wr = wv + (c-64)*128;
        float a = 0.f;
#pragma unroll 16
        for (int k = 0; k < 128; k++) a += xs[r][k] * wr[k];
        int gr = r0 + r;
        if (c < 32) Q[(size_t)gr*32 + c] = a;
        else if (c < 64) K[(size_t)gr*32 + c - 32] = a;
        else V[(size_t)gr*64 + c - 64] = a;
    }
}

// ---------------- host launcher ----------------
extern "C" void kernel_launch(void* const* d_in, const int* in_sizes, int n_in,
                              void* d_out, int out_size) {
    const float* traffic  = (const float*)d_in[0];
    const float* user     = (const float*)d_in[1];
    const float* patch_w  = (const float*)d_in[2];
    const float* patch_b  = (const float*)d_in[3];
    const float* mha_w    = (const float*)d_in[4];
    const float* mha_b    = (const float*)d_in[5];
    const float* out_w    = (const float*)d_in[6];
    const float* out_b    = (const float*)d_in[7];
    const float* ff1_w    = (const float*)d_in[8];
    const float* ff1_b    = (const float*)d_in[9];
    const float* ff2_w    = (const float*)d_in[10];
    const float* ff2_b    = (const float*)d_in[11];
    const float* ln1_g    = (const float*)d_in[12];
    const float* ln1_b    = (const float*)d_in[13];
    const float* ln2_g    = (const float*)d_in[14];
    const float* ln2_b    = (const float*)d_in[15];
    const float* ga_wq    = (const float*)d_in[16];
    const float* ga_wk    = (const float*)d_in[17];
    const float* ga_wv    = (const float*)d_in[18];
    const float* ga_ff1_w = (const float*)d_in[19];
    const float* ga_ff1_b = (const float*)d_in[20];
    const float* ga_ff2_w = (const float*)d_in[21];
    const float* ga_ff2_b = (const float*)d_in[22];
    const float* ga_ln1_g = (const float*)d_in[23];
    const float* ga_ln1_b = (const float*)d_in[24];
    const float* ga_ln2_g = (const float*)d_in[25];
    const float* ga_ln2_b = (const float*)d_in[26];
    const float* ca_wq    = (const float*)d_in[27];
    const float* ca_wk    = (const float*)d_in[28];
    const float* ca_wv    = (const float*)d_in[29];

    float *Z, *Qb, *Kb, *Vb, *ATT, *ENC, *Q2, *K2, *V2;
    cudaGetSymbolAddress((void**)&Z,   d_Z);
    cudaGetSymbolAddress((void**)&Qb,  d_Qb);
    cudaGetSymbolAddress((void**)&Kb,  d_Kb);
    cudaGetSymbolAddress((void**)&Vb,  d_Vb);
    cudaGetSymbolAddress((void**)&ATT, d_ATT);
    cudaGetSymbolAddress((void**)&ENC, d_ENC);
    cudaGetSymbolAddress((void**)&Q2,  d_Q2);
    cudaGetSymbolAddress((void**)&K2,  d_K2);
    cudaGetSymbolAddress((void**)&V2,  d_V2);

    const float SCALE32 = 0.17677669529663687f;   // 1/sqrt(32)

    for (int s = 0; s < 2; s++) {
        const float* xin = (s == 0) ? traffic : user;
        patch_kernel<<<B_*NN, 256>>>(xin, patch_w + s*HID*SL, patch_b + s*HID, Z);
        for (int i = 0; i < LAY; i++) {
            int o = s*LAY + i;
            mha_kernel<<<B_*NN, 128>>>(Z,
                mha_w + (size_t)o*192*64, mha_b + (size_t)o*192,
                out_w + (size_t)o*64*64,  out_b + (size_t)o*64,
                ln1_g + (size_t)o*64,     ln1_b + (size_t)o*64);
            ff_ln_kernel<<<TOK/64, 256>>>(Z,
                ff1_w + (size_t)o*FFD*64, ff1_b + (size_t)o*FFD,
                ff2_w + (size_t)o*64*FFD, ff2_b + (size_t)o*64,
                ln2_g + (size_t)o*64,     ln2_b + (size_t)o*64);
            ga_qkv_kernel<<<GRP*NN/16, 128>>>(Z,
                ga_wq + (size_t)o*DKk*64, ga_wk + (size_t)o*DKk*64, ga_wv + (size_t)o*64*64,
                Qb, Kb, Vb);
            attn_kernel<<<dim3(GRP, NN/64), 256>>>(Qb, Kb, Vb, ATT, SCALE32);
            ga_epi_kernel<<<TOK/8, 256>>>(ATT, Z,
                ga_ln1_g + (size_t)o*64, ga_ln1_b + (size_t)o*64);
            ff_ln_kernel<<<TOK/64, 256>>>(Z,
                ga_ff1_w + (size_t)o*FFD*64, ga_ff1_b + (size_t)o*FFD,
                ga_ff2_w + (size_t)o*64*FFD, ga_ff2_b + (size_t)o*64,
                ga_ln2_g + (size_t)o*64,     ga_ln2_b + (size_t)o*64);
        }
        pool_kernel<<<B_*NN*HID/256, 256>>>(Z, ENC, s);
    }
    fproj_kernel<<<B_*NN/16, 128>>>(ENC, ca_wq, ca_wk, ca_wv, Q2, K2, V2);
    attn_kernel<<<dim3(B_, NN/64), 256>>>(Q2, K2, V2, (float*)d_out, SCALE32);
}

// round 4
// speedup vs baseline: 2.4824x; 2.4824x over previous
#include <cuda_runtime.h>
#include <math.h>

#define B_   4
#define SEQ_ 12
#define NN   1024
#define SL   3
#define SG   4
#define HID  64
#define FFD  2048
#define DKk  32
#define LAY  2
#define TOK  (B_*NN*SG)   /* 16384 */
#define GRP  (B_*SG)      /* 16 */

// ---------------- scratch (static device memory, no runtime allocation) ----------------
__device__ float d_Z[TOK*HID];        // activations [b][n][seg][h]
__device__ float d_Qb[GRP*NN*DKk];
__device__ float d_Kb[GRP*NN*DKk];
__device__ float d_Vb[GRP*NN*HID];
__device__ float d_ATT[GRP*NN*HID];
__device__ float d_ENC[B_*NN*2*HID];
__device__ float d_Q2[B_*NN*DKk];
__device__ float d_K2[B_*NN*DKk];
__device__ float d_V2[B_*NN*HID];

// ---------------- patch embedding + positional encoding ----------------
__global__ __launch_bounds__(256) void patch_kernel(const float* __restrict__ x,
                                                    const float* __restrict__ pw,
                                                    const float* __restrict__ pb,
                                                    float* __restrict__ Z) {
    int bn = blockIdx.x;                 // 0..4095  (b*1024+n)
    int b  = bn >> 10, n = bn & 1023;
    int t  = threadIdx.x;                // 0..255
    int seg = t >> 6, h = t & 63;
    float acc = pb[h];
#pragma unroll
    for (int l = 0; l < SL; l++)
        acc += pw[h*SL + l] * x[(b*SEQ_ + seg*SL + l)*NN + n];
    int he = h & ~1;
    float dv = expf(-(float)he * (9.210340371976184f / (float)HID));
    float ang = (float)seg * dv;
    acc += (h & 1) ? cosf(ang) : sinf(ang);
    Z[(bn*SG + seg)*HID + h] = acc;
}

// ---------------- temporal encoder: MHA + residual + LN1; 64 tokens (16 groups) / block ----------------
// dynamic smem: xs[64][68] | wb[64][68] | qkv[64][200] | ps[2048] | os[64][68]
#define MHA_SMEM_FLOATS (4352 + 4352 + 12800 + 2048 + 4352)
__global__ __launch_bounds__(256) void mha_kernel(float* __restrict__ Z,
        const float* __restrict__ mw, const float* __restrict__ mb,
        const float* __restrict__ ow, const float* __restrict__ ob,
        const float* __restrict__ g1, const float* __restrict__ b1) {
    extern __shared__ float sm[];
    float (*xs)[68]  = (float(*)[68])sm;
    float (*wb)[68]  = (float(*)[68])(sm + 4352);
    float (*qkv)[200]= (float(*)[200])(sm + 8704);
    float *ps        = sm + 21504;
    float (*os)[68]  = (float(*)[68])(sm + 23552);

    int tid = threadIdx.x;
    int ty = tid >> 4, tx = tid & 15;
    int t0 = blockIdx.x * 64;               // 64 consecutive tokens
    float* zb = Z + (size_t)t0 * HID;

    for (int idx = tid; idx < 64*64; idx += 256) xs[idx>>6][idx&63] = zb[idx];

    // ---- QKV = X @ W^T + b  (out 64x192, in 3 chunks of 64 cols) ----
    for (int cc = 0; cc < 3; cc++) {
        __syncthreads();
        for (int idx = tid; idx < 64*64; idx += 256) {
            int r = idx >> 6, c = idx & 63;
            wb[r][c] = mw[(size_t)(cc*64 + r)*64 + c];
        }
        __syncthreads();
        float acc[4][4];
#pragma unroll
        for (int j = 0; j < 4; j++) {
            float bv = mb[cc*64 + tx + 16*j];
#pragma unroll
            for (int i = 0; i < 4; i++) acc[i][j] = bv;
        }
#pragma unroll 4
        for (int k = 0; k < 64; k += 4) {
            float4 xv[4], wv[4];
#pragma unroll
            for (int i = 0; i < 4; i++) xv[i] = *(const float4*)&xs[4*ty+i][k];
#pragma unroll
            for (int j = 0; j < 4; j++) wv[j] = *(const float4*)&wb[tx+16*j][k];
#pragma unroll
            for (int i = 0; i < 4; i++)
#pragma unroll
                for (int j = 0; j < 4; j++)
                    acc[i][j] += xv[i].x*wv[j].x + xv[i].y*wv[j].y + xv[i].z*wv[j].z + xv[i].w*wv[j].w;
        }
#pragma unroll
        for (int i = 0; i < 4; i++)
#pragma unroll
            for (int j = 0; j < 4; j++)
                qkv[4*ty+i][cc*64 + tx + 16*j] = acc[i][j];
    }
    __syncthreads();

    // ---- scores + softmax: 512 (group,head,query) rows, 2 per thread ----
    for (int T = tid; T < 512; T += 256) {
        int g = T >> 5, h = (T >> 2) & 7, i = T & 3;
        const float* q = &qkv[g*4 + i][h*8];
        float s[4];
#pragma unroll
        for (int j = 0; j < 4; j++) {
            const float* kk = &qkv[g*4 + j][64 + h*8];
            float a = 0.f;
#pragma unroll
            for (int d = 0; d < 8; d++) a += q[d] * kk[d];
            s[j] = a * 0.3535533905932738f;
        }
        float m = fmaxf(fmaxf(s[0], s[1]), fmaxf(s[2], s[3]));
        float e0 = __expf(s[0]-m), e1 = __expf(s[1]-m), e2 = __expf(s[2]-m), e3 = __expf(s[3]-m);
        float inv = 1.f / (e0+e1+e2+e3);
        ps[T*4+0] = e0*inv; ps[T*4+1] = e1*inv; ps[T*4+2] = e2*inv; ps[T*4+3] = e3*inv;
    }
    __syncthreads();

    // ---- O = att @ V (merged heads) ----
#pragma unroll
    for (int i = 0; i < 4; i++) {
        int r = 4*ty + i;
        int g = r >> 2, ii = r & 3;
#pragma unroll
        for (int j = 0; j < 4; j++) {
            int c = tx + 16*j;
            int h = c >> 3;
            const float* a = ps + (((g*8 + h)*4) + ii)*4;
            os[r][c] = a[0]*qkv[g*4+0][128+c] + a[1]*qkv[g*4+1][128+c]
                     + a[2]*qkv[g*4+2][128+c] + a[3]*qkv[g*4+3][128+c];
        }
    }
    __syncthreads();

    // ---- out proj + residual ----
    for (int idx = tid; idx < 64*64; idx += 256) {
        int r = idx >> 6, c = idx & 63;
        wb[r][c] = ow[(size_t)r*64 + c];
    }
    __syncthreads();
    {
        float acc[4][4];
#pragma unroll
        for (int j = 0; j < 4; j++) {
            float bv = ob[tx + 16*j];
#pragma unroll
            for (int i = 0; i < 4; i++) acc[i][j] = bv;
        }
#pragma unroll 4
        for (int k = 0; k < 64; k += 4) {
            float4 xv[4], wv[4];
#pragma unroll
            for (int i = 0; i < 4; i++) xv[i] = *(const float4*)&os[4*ty+i][k];
#pragma unroll
            for (int j = 0; j < 4; j++) wv[j] = *(const float4*)&wb[tx+16*j][k];
#pragma unroll
            for (int i = 0; i < 4; i++)
#pragma unroll
                for (int j = 0; j < 4; j++)
                    acc[i][j] += xv[i].x*wv[j].x + xv[i].y*wv[j].y + xv[i].z*wv[j].z + xv[i].w*wv[j].w;
        }
        __syncthreads();
#pragma unroll
        for (int i = 0; i < 4; i++)
#pragma unroll
            for (int j = 0; j < 4; j++) {
                int r = 4*ty + i, c = tx + 16*j;
                xs[r][c] += acc[i][j];
            }
    }
    __syncthreads();
    // ---- LN ----
    int w = tid >> 5, lane = tid & 31;
#pragma unroll
    for (int rr = 0; rr < 8; rr++) {
        int r = w*8 + rr;
        float v0 = xs[r][lane], v1 = xs[r][lane+32];
        float s = v0 + v1, q = v0*v0 + v1*v1;
#pragma unroll
        for (int o = 16; o; o >>= 1) { s += __shfl_xor_sync(0xffffffffu, s, o); q += __shfl_xor_sync(0xffffffffu, q, o); }
        float mean = s * (1.f/64.f);
        float var  = q * (1.f/64.f) - mean*mean;
        float rstd = rsqrtf(var + 1e-5f);
        zb[(size_t)r*64 + lane]      = (v0 - mean)*rstd*g1[lane]    + b1[lane];
        zb[(size_t)r*64 + lane + 32] = (v1 - mean)*rstd*g1[lane+32] + b1[lane+32];
    }
}

// ---------------- fused FF (relu) + residual + LN: 128 tokens/block, 256 threads ----------------
// dynamic smem: xs[128][68] | hs[128][36] | w1s[32][68] | w2s[64][36]
#define FF_SMEM_FLOATS (8704 + 4608 + 2176 + 2304)
__global__ __launch_bounds__(256) void ff_ln_kernel(float* __restrict__ Z,
        const float* __restrict__ w1, const float* __restrict__ b1,
        const float* __restrict__ w2, const float* __restrict__ b2,
        const float* __restrict__ g, const float* __restrict__ bb) {
    extern __shared__ float sm[];
    float (*xs)[68]  = (float(*)[68])sm;
    float (*hs)[36]  = (float(*)[36])(sm + 8704);
    float (*w1s)[68] = (float(*)[68])(sm + 13312);
    float (*w2s)[36] = (float(*)[36])(sm + 15488);

    int tid = threadIdx.x;
    int t0  = blockIdx.x * 128;
    int ty = tid >> 4, tx = tid & 15;   // ty 0..15 -> 8 rows each

    for (int idx = tid; idx < 128*64; idx += 256) xs[idx>>6][idx&63] = Z[(size_t)t0*64 + idx];

    float acc[8][4];
#pragma unroll
    for (int i = 0; i < 8; i++)
#pragma unroll
        for (int j = 0; j < 4; j++) acc[i][j] = 0.f;

    for (int fc = 0; fc < FFD; fc += 32) {
        __syncthreads();
        for (int idx = tid; idx < 32*64; idx += 256) { int r = idx>>6, c = idx&63; w1s[r][c] = w1[(size_t)(fc+r)*64 + c]; }
        for (int idx = tid; idx < 64*32; idx += 256) { int r = idx>>5, c = idx&31; w2s[r][c] = w2[(size_t)r*FFD + fc + c]; }
        __syncthreads();
        // H[128][32] = relu(X @ W1c^T + b1c) ; thread: rows 8ty+i, cols tx, tx+16
        float h8[8][2];
        float bv0 = b1[fc + tx], bv1 = b1[fc + tx + 16];
#pragma unroll
        for (int i = 0; i < 8; i++) { h8[i][0] = bv0; h8[i][1] = bv1; }
#pragma unroll 4
        for (int k = 0; k < 64; k += 4) {
            float4 wv0 = *(const float4*)&w1s[tx][k];
            float4 wv1 = *(const float4*)&w1s[tx+16][k];
#pragma unroll
            for (int i = 0; i < 8; i++) {
                float4 xv = *(const float4*)&xs[8*ty+i][k];
                h8[i][0] += xv.x*wv0.x + xv.y*wv0.y + xv.z*wv0.z + xv.w*wv0.w;
                h8[i][1] += xv.x*wv1.x + xv.y*wv1.y + xv.z*wv1.z + xv.w*wv1.w;
            }
        }
#pragma unroll
        for (int i = 0; i < 8; i++) {
            hs[8*ty+i][tx]    = fmaxf(h8[i][0], 0.f);
            hs[8*ty+i][tx+16] = fmaxf(h8[i][1], 0.f);
        }
        __syncthreads();
        // O[128][64] += H @ W2c^T ; rows 8ty+i, cols tx+16j
#pragma unroll 2
        for (int c = 0; c < 32; c += 4) {
            float4 wv[4];
#pragma unroll
            for (int j = 0; j < 4; j++) wv[j] = *(const float4*)&w2s[tx+16*j][c];
#pragma unroll
            for (int i = 0; i < 8; i++) {
                float4 hv = *(const float4*)&hs[8*ty+i][c];
#pragma unroll
                for (int j = 0; j < 4; j++)
                    acc[i][j] += hv.x*wv[j].x + hv.y*wv[j].y + hv.z*wv[j].z + hv.w*wv[j].w;
            }
        }
    }
    __syncthreads();
#pragma unroll
    for (int i = 0; i < 8; i++)
#pragma unroll
        for (int j = 0; j < 4; j++) {
            int r = 8*ty + i, c = tx + 16*j;
            xs[r][c] = acc[i][j] + b2[c] + xs[r][c];
        }
    __syncthreads();
    int w = tid >> 5, lane = tid & 31;
#pragma unroll
    for (int rr = 0; rr < 16; rr++) {
        int r = w*16 + rr;
        float v0 = xs[r][lane], v1 = xs[r][lane+32];
        float s = v0 + v1, q = v0*v0 + v1*v1;
#pragma unroll
        for (int o = 16; o; o >>= 1) { s += __shfl_xor_sync(0xffffffffu, s, o); q += __shfl_xor_sync(0xffffffffu, q, o); }
        float mean = s * (1.f/64.f);
        float var  = q * (1.f/64.f) - mean*mean;
        float rstd = rsqrtf(var + 1e-5f);
        Z[(size_t)(t0+r)*64 + lane]      = (v0 - mean)*rstd*g[lane]    + bb[lane];
        Z[(size_t)(t0+r)*64 + lane + 32] = (v1 - mean)*rstd*g[lane+32] + bb[lane+32];
    }
}

// ---------------- graph-attention QKV projection: 64 rows/block, register tiled ----------------
__global__ __launch_bounds__(256) void ga_qkv_kernel(const float* __restrict__ Z,
        const float* __restrict__ wq, const float* __restrict__ wk, const float* __restrict__ wv,
        float* __restrict__ Q, float* __restrict__ K, float* __restrict__ V) {
    __shared__ float xs[64][68];
    __shared__ float ws[64][68];
    int tid = threadIdx.x;
    int r0 = blockIdx.x * 64;
    int ty = tid >> 4, tx = tid & 15;

    for (int idx = tid; idx < 64*64; idx += 256) {
        int r = idx >> 6, c = idx & 63;
        int gr = r0 + r;
        int g2 = gr >> 10, n = gr & 1023;
        int b = g2 >> 2, seg = g2 & 3;
        xs[r][c] = Z[(size_t)(((b<<10)+n)*SG + seg)*HID + c];
    }
    for (int chunk = 0; chunk < 2; chunk++) {
        __syncthreads();
        for (int idx = tid; idx < 64*64; idx += 256) {
            int r = idx >> 6, c = idx & 63;
            ws[r][c] = (chunk == 0) ? (r < 32 ? wq[r*64 + c] : wk[(r-32)*64 + c])
                                    : wv[r*64 + c];
        }
        __syncthreads();
        float acc[4][4];
#pragma unroll
        for (int i = 0; i < 4; i++)
#pragma unroll
            for (int j = 0; j < 4; j++) acc[i][j] = 0.f;
#pragma unroll 4
        for (int k = 0; k < 64; k += 4) {
            float4 xv[4], wv4[4];
#pragma unroll
            for (int i = 0; i < 4; i++) xv[i] = *(const float4*)&xs[4*ty+i][k];
#pragma unroll
            for (int j = 0; j < 4; j++) wv4[j] = *(const float4*)&ws[tx+16*j][k];
#pragma unroll
            for (int i = 0; i < 4; i++)
#pragma unroll
                for (int j = 0; j < 4; j++)
                    acc[i][j] += xv[i].x*wv4[j].x + xv[i].y*wv4[j].y + xv[i].z*wv4[j].z + xv[i].w*wv4[j].w;
        }
#pragma unroll
        for (int i = 0; i < 4; i++) {
            int gr = r0 + 4*ty + i;
#pragma unroll
            for (int j = 0; j < 4; j++) {
                int c = tx + 16*j;
                if (chunk == 0) {
                    if (c < 32) Q[(size_t)gr*32 + c] = acc[i][j];
                    else        K[(size_t)gr*32 + (c-32)] = acc[i][j];
                } else V[(size_t)gr*64 + c] = acc[i][j];
            }
        }
    }
}

// ---------------- attention: single-pass online softmax; dk=32, dv=64, N=1024/group ----------------
__global__ __launch_bounds__(256) void attn_kernel(const float* __restrict__ Q,
        const float* __restrict__ K, const float* __restrict__ V,
        float* __restrict__ O, float scale) {
    __shared__ float qs[64][32];
    __shared__ float ks[32][36];
    __shared__ float vs[32][64];
    __shared__ float ps[64][33];
    int g2 = blockIdx.x;
    int q0 = blockIdx.y * 64;
    int tid = threadIdx.x;
    int ty = tid >> 4, tx = tid & 15;
    const float* Qg = Q + (size_t)g2*NN*32;
    const float* Kg = K + (size_t)g2*NN*32;
    const float* Vg = V + (size_t)g2*NN*64;

    for (int idx = tid; idx < 64*32; idx += 256) qs[idx>>5][idx&31] = Qg[(size_t)q0*32 + idx];

    float m[4]   = {-1e30f, -1e30f, -1e30f, -1e30f};
    float l[4]   = {0.f, 0.f, 0.f, 0.f};
    float acc[4][4];
#pragma unroll
    for (int i = 0; i < 4; i++)
#pragma unroll
        for (int j = 0; j < 4; j++) acc[i][j] = 0.f;

    for (int kt = 0; kt < NN; kt += 32) {
        __syncthreads();
        for (int idx = tid; idx < 32*32; idx += 256) ks[idx>>5][idx&31] = Kg[(size_t)kt*32 + idx];
        for (int idx = tid; idx < 32*64; idx += 256) vs[idx>>6][idx&63] = Vg[(size_t)kt*64 + idx];
        __syncthreads();
        float s[4][2];
#pragma unroll
        for (int i = 0; i < 4; i++) {
            int r = 4*ty + i;
#pragma unroll
            for (int j = 0; j < 2; j++) {
                int c = tx + 16*j;
                float a = 0.f;
#pragma unroll
                for (int d = 0; d < 32; d += 4) {
                    float4 qv = *(const float4*)&qs[r][d];
                    float4 kv = *(const float4*)&ks[c][d];
                    a += qv.x*kv.x + qv.y*kv.y + qv.z*kv.z + qv.w*kv.w;
                }
                s[i][j] = a * scale;
            }
        }
        // row max across the 16 tx lanes, online update
#pragma unroll
        for (int i = 0; i < 4; i++) {
            float tm = fmaxf(s[i][0], s[i][1]);
#pragma unroll
            for (int o = 8; o; o >>= 1) tm = fmaxf(tm, __shfl_xor_sync(0xffffffffu, tm, o));
            float newm = fmaxf(m[i], tm);
            float factor = __expf(m[i] - newm);
            m[i] = newm;
            l[i] *= factor;
#pragma unroll
            for (int j = 0; j < 4; j++) acc[i][j] *= factor;
            int r = 4*ty + i;
#pragma unroll
            for (int j = 0; j < 2; j++) {
                float p = __expf(s[i][j] - newm);
                ps[r][tx + 16*j] = p;
                l[i] += p;
            }
        }
        __syncthreads();
#pragma unroll 4
        for (int c = 0; c < 32; c++) {
            float hv0 = ps[4*ty+0][c], hv1 = ps[4*ty+1][c], hv2 = ps[4*ty+2][c], hv3 = ps[4*ty+3][c];
            float wv0 = vs[c][tx], wv1 = vs[c][tx+16], wv2 = vs[c][tx+32], wv3 = vs[c][tx+48];
            acc[0][0]+=hv0*wv0; acc[0][1]+=hv0*wv1; acc[0][2]+=hv0*wv2; acc[0][3]+=hv0*wv3;
            acc[1][0]+=hv1*wv0; acc[1][1]+=hv1*wv1; acc[1][2]+=hv1*wv2; acc[1][3]+=hv1*wv3;
            acc[2][0]+=hv2*wv0; acc[2][1]+=hv2*wv1; acc[2][2]+=hv2*wv2; acc[2][3]+=hv2*wv3;
            acc[3][0]+=hv3*wv0; acc[3][1]+=hv3*wv1; acc[3][2]+=hv3*wv2; acc[3][3]+=hv3*wv3;
        }
    }
#pragma unroll
    for (int o = 8; o; o >>= 1)
#pragma unroll
        for (int i = 0; i < 4; i++) l[i] += __shfl_xor_sync(0xffffffffu, l[i], o);
#pragma unroll
    for (int i = 0; i < 4; i++) {
        float inv = 1.f / l[i];
#pragma unroll
        for (int j = 0; j < 4; j++)
            O[(size_t)(g2*NN + q0 + 4*ty + i)*64 + tx + 16*j] = acc[i][j] * inv;
    }
}

// ---------------- GA epilogue: att = LN(att)*g+b + x ----------------
__global__ __launch_bounds__(256) void ga_epi_kernel(const float* __restrict__ ATT,
        float* __restrict__ Z, const float* __restrict__ g, const float* __restrict__ bb) {
    int w = threadIdx.x >> 5, lane = threadIdx.x & 31;
    int r = blockIdx.x * 8 + w;
    int g2 = r >> 10, n = r & 1023, b = g2 >> 2, seg = g2 & 3;
    float* zp = Z + (size_t)(((b<<10)+n)*SG + seg)*HID;
    const float* ap = ATT + (size_t)r*HID;
    float v0 = ap[lane], v1 = ap[lane+32];
    float s = v0 + v1, q = v0*v0 + v1*v1;
#pragma unroll
    for (int o = 16; o; o >>= 1) { s += __shfl_xor_sync(0xffffffffu, s, o); q += __shfl_xor_sync(0xffffffffu, q, o); }
    float mean = s * (1.f/64.f);
    float var  = q * (1.f/64.f) - mean*mean;
    float rstd = rsqrtf(var + 1e-5f);
    zp[lane]      = (v0 - mean)*rstd*g[lane]    + bb[lane]    + zp[lane];
    zp[lane + 32] = (v1 - mean)*rstd*g[lane+32] + bb[lane+32] + zp[lane+32];
}

// ---------------- mean-pool over segments + concat ----------------
__global__ __launch_bounds__(256) void pool_kernel(const float* __restrict__ Z,
        float* __restrict__ ENC, int s) {
    int idx = blockIdx.x * 256 + threadIdx.x;
    int bn = idx >> 6, h = idx & 63;
    float a = 0.25f * (Z[(size_t)(bn*4+0)*64+h] + Z[(size_t)(bn*4+1)*64+h] +
                       Z[(size_t)(bn*4+2)*64+h] + Z[(size_t)(bn*4+3)*64+h]);
    ENC[(size_t)bn*128 + s*64 + h] = a;
}

// ---------------- final cross-attention projections (in dim = 128), register tiled ----------------
__global__ __launch_bounds__(256) void fproj_kernel(const float* __restrict__ ENC,
        const float* __restrict__ wq, const float* __restrict__ wk, const float* __restrict__ wv,
        float* __restrict__ Q, float* __restrict__ K, float* __restrict__ V) {
    __shared__ float xs[64][68];
    __shared__ float ws[64][68];
    int tid = threadIdx.x;
    int r0 = blockIdx.x * 64;
    int ty = tid >> 4, tx = tid & 15;
    float acc[2][4][4];
#pragma unroll
    for (int oc = 0; oc < 2; oc++)
#pragma unroll
        for (int i = 0; i < 4; i++)
#pragma unroll
            for (int j = 0; j < 4; j++) acc[oc][i][j] = 0.f;

    for (int kc = 0; kc < 2; kc++) {
        __syncthreads();
        for (int idx = tid; idx < 64*64; idx += 256) {
            int r = idx >> 6, c = idx & 63;
            xs[r][c] = ENC[(size_t)(r0+r)*128 + kc*64 + c];
        }
        for (int oc = 0; oc < 2; oc++) {
            __syncthreads();
            for (int idx = tid; idx < 64*64; idx += 256) {
                int r = idx >> 6, c = idx & 63;
                int gc = oc*64 + r;
                int k  = kc*64 + c;
                ws[r][c] = (gc < 32) ? wq[gc*128 + k] : (gc < 64) ? wk[(gc-32)*128 + k] : wv[(gc-64)*128 + k];
            }
            __syncthreads();
#pragma unroll 4
            for (int k = 0; k < 64; k += 4) {
                float4 xv[4], wv4[4];
#pragma unroll
                for (int i = 0; i < 4; i++) xv[i] = *(const float4*)&xs[4*ty+i][k];
#pragma unroll
                for (int j = 0; j < 4; j++) wv4[j] = *(const float4*)&ws[tx+16*j][k];
#pragma unroll
                for (int i = 0; i < 4; i++)
#pragma unroll
                    for (int j = 0; j < 4; j++)
                        acc[oc][i][j] += xv[i].x*wv4[j].x + xv[i].y*wv4[j].y + xv[i].z*wv4[j].z + xv[i].w*wv4[j].w;
            }
        }
    }
#pragma unroll
    for (int oc = 0; oc < 2; oc++)
#pragma unroll
        for (int i = 0; i < 4; i++) {
            int gr = r0 + 4*ty + i;
#pragma unroll
            for (int j = 0; j < 4; j++) {
                int gc = oc*64 + tx + 16*j;
                float v = acc[oc][i][j];
                if (gc < 32)      Q[(size_t)gr*32 + gc] = v;
                else if (gc < 64) K[(size_t)gr*32 + gc - 32] = v;
                else              V[(size_t)gr*64 + gc - 64] = v;
            }
        }
}

// ---------------- host launcher ----------------
extern "C" void kernel_launch(void* const* d_in, const int* in_sizes, int n_in,
                              void* d_out, int out_size) {
    const float* traffic  = (const float*)d_in[0];
    const float* user     = (const float*)d_in[1];
    const float* patch_w  = (const float*)d_in[2];
    const float* patch_b  = (const float*)d_in[3];
    const float* mha_w    = (const float*)d_in[4];
    const float* mha_b    = (const float*)d_in[5];
    const float* out_w    = (const float*)d_in[6];
    const float* out_b    = (const float*)d_in[7];
    const float* ff1_w    = (const float*)d_in[8];
    const float* ff1_b    = (const float*)d_in[9];
    const float* ff2_w    = (const float*)d_in[10];
    const float* ff2_b    = (const float*)d_in[11];
    const float* ln1_g    = (const float*)d_in[12];
    const float* ln1_b    = (const float*)d_in[13];
    const float* ln2_g    = (const float*)d_in[14];
    const float* ln2_b    = (const float*)d_in[15];
    const float* ga_wq    = (const float*)d_in[16];
    const float* ga_wk    = (const float*)d_in[17];
    const float* ga_wv    = (const float*)d_in[18];
    const float* ga_ff1_w = (const float*)d_in[19];
    const float* ga_ff1_b = (const float*)d_in[20];
    const float* ga_ff2_w = (const float*)d_in[21];
    const float* ga_ff2_b = (const float*)d_in[22];
    const float* ga_ln1_g = (const float*)d_in[23];
    const float* ga_ln1_b = (const float*)d_in[24];
    const float* ga_ln2_g = (const float*)d_in[25];
    const float* ga_ln2_b = (const float*)d_in[26];
    const float* ca_wq    = (const float*)d_in[27];
    const float* ca_wk    = (const float*)d_in[28];
    const float* ca_wv    = (const float*)d_in[29];

    float *Z, *Qb, *Kb, *Vb, *ATT, *ENC, *Q2, *K2, *V2;
    cudaGetSymbolAddress((void**)&Z,   d_Z);
    cudaGetSymbolAddress((void**)&Qb,  d_Qb);
    cudaGetSymbolAddress((void**)&Kb,  d_Kb);
    cudaGetSymbolAddress((void**)&Vb,  d_Vb);
    cudaGetSymbolAddress((void**)&ATT, d_ATT);
    cudaGetSymbolAddress((void**)&ENC, d_ENC);
    cudaGetSymbolAddress((void**)&Q2,  d_Q2);
    cudaGetSymbolAddress((void**)&K2,  d_K2);
    cudaGetSymbolAddress((void**)&V2,  d_V2);

    const int MHA_SMEM = MHA_SMEM_FLOATS * 4;   // 111,616 B
    const int FF_SMEM  = FF_SMEM_FLOATS * 4;    //  71,168 B
    cudaFuncSetAttribute(mha_kernel,  cudaFuncAttributeMaxDynamicSharedMemorySize, MHA_SMEM);
    cudaFuncSetAttribute(ff_ln_kernel, cudaFuncAttributeMaxDynamicSharedMemorySize, FF_SMEM);

    const float SCALE32 = 0.17677669529663687f;   // 1/sqrt(32)

    for (int s = 0; s < 2; s++) {
        const float* xin = (s == 0) ? traffic : user;
        patch_kernel<<<B_*NN, 256>>>(xin, patch_w + s*HID*SL, patch_b + s*HID, Z);
        for (int i = 0; i < LAY; i++) {
            int o = s*LAY + i;
            mha_kernel<<<TOK/64, 256, MHA_SMEM>>>(Z,
                mha_w + (size_t)o*192*64, mha_b + (size_t)o*192,
                out_w + (size_t)o*64*64,  out_b + (size_t)o*64,
                ln1_g + (size_t)o*64,     ln1_b + (size_t)o*64);
            ff_ln_kernel<<<TOK/128, 256, FF_SMEM>>>(Z,
                ff1_w + (size_t)o*FFD*64, ff1_b + (size_t)o*FFD,
                ff2_w + (size_t)o*64*FFD, ff2_b + (size_t)o*64,
                ln2_g + (size_t)o*64,     ln2_b + (size_t)o*64);
            ga_qkv_kernel<<<TOK/64, 256>>>(Z,
                ga_wq + (size_t)o*DKk*64, ga_wk + (size_t)o*DKk*64, ga_wv + (size_t)o*64*64,
                Qb, Kb, Vb);
            attn_kernel<<<dim3(GRP, NN/64), 256>>>(Qb, Kb, Vb, ATT, SCALE32);
            ga_epi_kernel<<<TOK/8, 256>>>(ATT, Z,
                ga_ln1_g + (size_t)o*64, ga_ln1_b + (size_t)o*64);
            ff_ln_kernel<<<TOK/128, 256, FF_SMEM>>>(Z,
                ga_ff1_w + (size_t)o*FFD*64, ga_ff1_b + (size_t)o*FFD,
                ga_ff2_w + (size_t)o*64*FFD, ga_ff2_b + (size_t)o*64,
                ga_ln2_g + (size_t)o*64,     ga_ln2_b + (size_t)o*64);
        }
        pool_kernel<<<B_*NN*HID/256, 256>>>(Z, ENC, s);
    }
    fproj_kernel<<<B_*NN/64, 256>>>(ENC, ca_wq, ca_wk, ca_wv, Q2, K2, V2);
    attn_kernel<<<dim3(B_, NN/64), 256>>>(Q2, K2, V2, (float*)d_out, SCALE32);
}

// round 6
// speedup vs baseline: 3.4810x; 1.4023x over previous
#include <cuda_runtime.h>
#include <math.h>

#define B_   4
#define SEQ_ 12
#define NN   1024
#define SL   3
#define SG   4
#define HID  64
#define FFD  2048
#define DKk  32
#define LAY  2
#define TOK  (B_*NN*SG)   /* 16384 per stream */
#define GRP  (B_*SG)      /* 16 per stream */

// ---------------- scratch (static device memory) ----------------
__device__ float d_Z[2*TOK*HID];          // [s][b][n][seg][h]
__device__ float d_Qb[2*GRP*NN*DKk];
__device__ float d_Kb[2*GRP*NN*DKk];
__device__ float d_Vb[2*GRP*NN*HID];
__device__ float d_ATT[2*GRP*NN*HID];
__device__ float d_ENC[B_*NN*2*HID];
__device__ float d_Q2[B_*NN*DKk];
__device__ float d_K2[B_*NN*DKk];
__device__ float d_V2[B_*NN*HID];

// ---------------- patch embedding + positional encoding (both streams) ----------------
__global__ __launch_bounds__(256) void patch_kernel(const float* __restrict__ traffic,
                                                    const float* __restrict__ user,
                                                    const float* __restrict__ pw,
                                                    const float* __restrict__ pb,
                                                    float* __restrict__ Z) {
    int blk = blockIdx.x;                // 0..8191
    int s   = blk >> 12;
    int bn  = blk & 4095;
    int b   = bn >> 10, n = bn & 1023;
    const float* x = s ? user : traffic;
    const float* pws = pw + s*HID*SL;
    const float* pbs = pb + s*HID;
    int t   = threadIdx.x;
    int seg = t >> 6, h = t & 63;
    float acc = pbs[h];
#pragma unroll
    for (int l = 0; l < SL; l++)
        acc += pws[h*SL + l] * x[(b*SEQ_ + seg*SL + l)*NN + n];
    int he = h & ~1;
    float dv = expf(-(float)he * (9.210340371976184f / (float)HID));
    float ang = (float)seg * dv;
    acc += (h & 1) ? cosf(ang) : sinf(ang);
    Z[(size_t)(s*TOK + bn*SG + seg)*HID + h] = acc;
}

// ---------------- temporal encoder: MHA + residual + LN1; 64 tokens / block ----------------
#define MHA_SMEM_FLOATS (4352 + 4352 + 12800 + 2048 + 4352)
__global__ __launch_bounds__(256) void mha_kernel(float* __restrict__ Z,
        const float* __restrict__ mw_, const float* __restrict__ mb_,
        const float* __restrict__ ow_, const float* __restrict__ ob_,
        const float* __restrict__ g1_, const float* __restrict__ b1_, int layer) {
    extern __shared__ float sm[];
    float (*xs)[68]  = (float(*)[68])sm;
    float (*wb)[68]  = (float(*)[68])(sm + 4352);
    float (*qkv)[200]= (float(*)[200])(sm + 8704);
    float *ps        = sm + 21504;
    float (*os)[68]  = (float(*)[68])(sm + 23552);

    int tid = threadIdx.x;
    int ty = tid >> 4, tx = tid & 15;
    int s  = blockIdx.x >> 8;                 // 512 blocks, 256 per stream
    int o  = s*LAY + layer;
    const float* mw = mw_ + (size_t)o*192*64;
    const float* mb = mb_ + (size_t)o*192;
    const float* ow = ow_ + (size_t)o*64*64;
    const float* ob = ob_ + (size_t)o*64;
    const float* g1 = g1_ + (size_t)o*64;
    const float* b1 = b1_ + (size_t)o*64;
    size_t t0 = (size_t)blockIdx.x * 64;
    float* zb = Z + t0 * HID;

    for (int idx = tid; idx < 64*16; idx += 256) {
        int r = idx >> 4, c4 = idx & 15;
        *(float4*)&xs[r][4*c4] = *(const float4*)&zb[(size_t)r*64 + 4*c4];
    }

    // ---- QKV = X @ W^T + b ----
    for (int cc = 0; cc < 3; cc++) {
        __syncthreads();
        for (int idx = tid; idx < 64*16; idx += 256) {
            int r = idx >> 4, c4 = idx & 15;
            *(float4*)&wb[r][4*c4] = *(const float4*)&mw[(size_t)(cc*64 + r)*64 + 4*c4];
        }
        __syncthreads();
        float acc[4][4];
#pragma unroll
        for (int j = 0; j < 4; j++) {
            float bv = mb[cc*64 + tx + 16*j];
#pragma unroll
            for (int i = 0; i < 4; i++) acc[i][j] = bv;
        }
#pragma unroll 4
        for (int k = 0; k < 64; k += 4) {
            float4 xv[4], wv[4];
#pragma unroll
            for (int i = 0; i < 4; i++) xv[i] = *(const float4*)&xs[4*ty+i][k];
#pragma unroll
            for (int j = 0; j < 4; j++) wv[j] = *(const float4*)&wb[tx+16*j][k];
#pragma unroll
            for (int i = 0; i < 4; i++)
#pragma unroll
                for (int j = 0; j < 4; j++)
                    acc[i][j] += xv[i].x*wv[j].x + xv[i].y*wv[j].y + xv[i].z*wv[j].z + xv[i].w*wv[j].w;
        }
#pragma unroll
        for (int i = 0; i < 4; i++)
#pragma unroll
            for (int j = 0; j < 4; j++)
                qkv[4*ty+i][cc*64 + tx + 16*j] = acc[i][j];
    }
    __syncthreads();

    // ---- scores + softmax ----
    for (int T = tid; T < 512; T += 256) {
        int g = T >> 5, h = (T >> 2) & 7, i = T & 3;
        const float* q = &qkv[g*4 + i][h*8];
        float sc[4];
#pragma unroll
        for (int j = 0; j < 4; j++) {
            const float* kk = &qkv[g*4 + j][64 + h*8];
            float a = 0.f;
#pragma unroll
            for (int d = 0; d < 8; d++) a += q[d] * kk[d];
            sc[j] = a * 0.3535533905932738f;
        }
        float m = fmaxf(fmaxf(sc[0], sc[1]), fmaxf(sc[2], sc[3]));
        float e0 = __expf(sc[0]-m), e1 = __expf(sc[1]-m), e2 = __expf(sc[2]-m), e3 = __expf(sc[3]-m);
        float inv = 1.f / (e0+e1+e2+e3);
        ps[T*4+0] = e0*inv; ps[T*4+1] = e1*inv; ps[T*4+2] = e2*inv; ps[T*4+3] = e3*inv;
    }
    __syncthreads();

    // ---- O = att @ V ----
#pragma unroll
    for (int i = 0; i < 4; i++) {
        int r = 4*ty + i;
        int g = r >> 2, ii = r & 3;
#pragma unroll
        for (int j = 0; j < 4; j++) {
            int c = tx + 16*j;
            int h = c >> 3;
            const float* a = ps + (((g*8 + h)*4) + ii)*4;
            os[r][c] = a[0]*qkv[g*4+0][128+c] + a[1]*qkv[g*4+1][128+c]
                     + a[2]*qkv[g*4+2][128+c] + a[3]*qkv[g*4+3][128+c];
        }
    }
    __syncthreads();

    // ---- out proj + residual ----
    for (int idx = tid; idx < 64*16; idx += 256) {
        int r = idx >> 4, c4 = idx & 15;
        *(float4*)&wb[r][4*c4] = *(const float4*)&ow[(size_t)r*64 + 4*c4];
    }
    __syncthreads();
    {
        float acc[4][4];
#pragma unroll
        for (int j = 0; j < 4; j++) {
            float bv = ob[tx + 16*j];
#pragma unroll
            for (int i = 0; i < 4; i++) acc[i][j] = bv;
        }
#pragma unroll 4
        for (int k = 0; k < 64; k += 4) {
            float4 xv[4], wv[4];
#pragma unroll
            for (int i = 0; i < 4; i++) xv[i] = *(const float4*)&os[4*ty+i][k];
#pragma unroll
            for (int j = 0; j < 4; j++) wv[j] = *(const float4*)&wb[tx+16*j][k];
#pragma unroll
            for (int i = 0; i < 4; i++)
#pragma unroll
                for (int j = 0; j < 4; j++)
                    acc[i][j] += xv[i].x*wv[j].x + xv[i].y*wv[j].y + xv[i].z*wv[j].z + xv[i].w*wv[j].w;
        }
        __syncthreads();
#pragma unroll
        for (int i = 0; i < 4; i++)
#pragma unroll
            for (int j = 0; j < 4; j++)
                xs[4*ty+i][tx+16*j] += acc[i][j];
    }
    __syncthreads();
    // ---- LN ----
    int w = tid >> 5, lane = tid & 31;
#pragma unroll
    for (int rr = 0; rr < 8; rr++) {
        int r = w*8 + rr;
        float v0 = xs[r][lane], v1 = xs[r][lane+32];
        float ssum = v0 + v1, q = v0*v0 + v1*v1;
#pragma unroll
        for (int off = 16; off; off >>= 1) { ssum += __shfl_xor_sync(0xffffffffu, ssum, off); q += __shfl_xor_sync(0xffffffffu, q, off); }
        float mean = ssum * (1.f/64.f);
        float var  = q * (1.f/64.f) - mean*mean;
        float rstd = rsqrtf(var + 1e-5f);
        zb[(size_t)r*64 + lane]      = (v0 - mean)*rstd*g1[lane]    + b1[lane];
        zb[(size_t)r*64 + lane + 32] = (v1 - mean)*rstd*g1[lane+32] + b1[lane+32];
    }
}

// ---------------- fused FF (relu) + residual + LN: 128 tokens/block, FF chunk 128 ----------------
// smem: xs[128][68] | hs[128][132] | w1s[128][68] | w2s[64][132]
#define FF_SMEM_FLOATS (8704 + 16896 + 8704 + 8448)
__global__ __launch_bounds__(256) void ff_ln_kernel(float* __restrict__ Z,
        const float* __restrict__ w1_, const float* __restrict__ b1_,
        const float* __restrict__ w2_, const float* __restrict__ b2_,
        const float* __restrict__ g_, const float* __restrict__ bb_, int layer) {
    extern __shared__ float sm[];
    float (*xs)[68]   = (float(*)[68])sm;
    float (*hs)[132]  = (float(*)[132])(sm + 8704);
    float (*w1s)[68]  = (float(*)[68])(sm + 8704 + 16896);
    float (*w2s)[132] = (float(*)[132])(sm + 8704 + 16896 + 8704);

    int tid = threadIdx.x;
    int s   = blockIdx.x >> 7;           // 256 blocks, 128 per stream
    int o   = s*LAY + layer;
    const float* w1 = w1_ + (size_t)o*FFD*64;
    const float* b1 = b1_ + (size_t)o*FFD;
    const float* w2 = w2_ + (size_t)o*64*FFD;
    const float* b2 = b2_ + (size_t)o*64;
    const float* g  = g_  + (size_t)o*64;
    const float* bb = bb_ + (size_t)o*64;
    size_t t0 = (size_t)blockIdx.x * 128;
    int ty = tid >> 4, tx = tid & 15;

    for (int idx = tid; idx < 128*16; idx += 256) {
        int r = idx >> 4, c4 = idx & 15;
        *(float4*)&xs[r][4*c4] = *(const float4*)&Z[(t0 + r)*64 + 4*c4];
    }

    float acc[8][4];
#pragma unroll
    for (int i = 0; i < 8; i++)
#pragma unroll
        for (int j = 0; j < 4; j++) acc[i][j] = 0.f;

    for (int fc = 0; fc < FFD; fc += 128) {
        __syncthreads();
        for (int idx = tid; idx < 128*16; idx += 256) {
            int r = idx >> 4, c4 = idx & 15;
            *(float4*)&w1s[r][4*c4] = *(const float4*)&w1[(size_t)(fc+r)*64 + 4*c4];
        }
        for (int idx = tid; idx < 64*32; idx += 256) {
            int r = idx >> 5, c4 = idx & 31;
            *(float4*)&w2s[r][4*c4] = *(const float4*)&w2[(size_t)r*FFD + fc + 4*c4];
        }
        __syncthreads();
        // H[128][128] = relu(X @ W1c^T + b1c); tile 8 rows x 8 cols per thread
        float h8[8][8];
#pragma unroll
        for (int j = 0; j < 8; j++) {
            float bv = b1[fc + tx + 16*j];
#pragma unroll
            for (int i = 0; i < 8; i++) h8[i][j] = bv;
        }
#pragma unroll 4
        for (int k = 0; k < 64; k += 4) {
            float4 wv[8];
#pragma unroll
            for (int j = 0; j < 8; j++) wv[j] = *(const float4*)&w1s[tx+16*j][k];
#pragma unroll
            for (int i = 0; i < 8; i++) {
                float4 xv = *(const float4*)&xs[8*ty+i][k];
#pragma unroll
                for (int j = 0; j < 8; j++)
                    h8[i][j] += xv.x*wv[j].x + xv.y*wv[j].y + xv.z*wv[j].z + xv.w*wv[j].w;
            }
        }
#pragma unroll
        for (int i = 0; i < 8; i++)
#pragma unroll
            for (int j = 0; j < 8; j++)
                hs[8*ty+i][tx+16*j] = fmaxf(h8[i][j], 0.f);
        __syncthreads();
        // O[128][64] += H @ W2c^T ; tile 8 rows x 4 cols
#pragma unroll 4
        for (int c = 0; c < 128; c += 4) {
            float4 wv[4];
#pragma unroll
            for (int j = 0; j < 4; j++) wv[j] = *(const float4*)&w2s[tx+16*j][c];
#pragma unroll
            for (int i = 0; i < 8; i++) {
                float4 hv = *(const float4*)&hs[8*ty+i][c];
#pragma unroll
                for (int j = 0; j < 4; j++)
                    acc[i][j] += hv.x*wv[j].x + hv.y*wv[j].y + hv.z*wv[j].z + hv.w*wv[j].w;
            }
        }
    }
    __syncthreads();
#pragma unroll
    for (int i = 0; i < 8; i++)
#pragma unroll
        for (int j = 0; j < 4; j++) {
            int r = 8*ty + i, c = tx + 16*j;
            xs[r][c] = acc[i][j] + b2[c] + xs[r][c];
        }
    __syncthreads();
    int w = tid >> 5, lane = tid & 31;
#pragma unroll
    for (int rr = 0; rr < 16; rr++) {
        int r = w*16 + rr;
        float v0 = xs[r][lane], v1 = xs[r][lane+32];
        float ssum = v0 + v1, q = v0*v0 + v1*v1;
#pragma unroll
        for (int off = 16; off; off >>= 1) { ssum += __shfl_xor_sync(0xffffffffu, ssum, off); q += __shfl_xor_sync(0xffffffffu, q, off); }
        float mean = ssum * (1.f/64.f);
        float var  = q * (1.f/64.f) - mean*mean;
        float rstd = rsqrtf(var + 1e-5f);
        Z[(t0+r)*64 + lane]      = (v0 - mean)*rstd*g[lane]    + bb[lane];
        Z[(t0+r)*64 + lane + 32] = (v1 - mean)*rstd*g[lane+32] + bb[lane+32];
    }
}

// ---------------- graph-attention QKV projection: 64 rows/block ----------------
__global__ __launch_bounds__(256) void ga_qkv_kernel(const float* __restrict__ Z,
        const float* __restrict__ wq_, const float* __restrict__ wk_, const float* __restrict__ wv_,
        float* __restrict__ Q, float* __restrict__ K, float* __restrict__ V, int layer) {
    __shared__ float xs[64][68];
    __shared__ float ws[64][68];
    int tid = threadIdx.x;
    int r0 = blockIdx.x * 64;
    int s  = r0 >> 14;
    int o  = s*LAY + layer;
    const float* wq = wq_ + (size_t)o*DKk*64;
    const float* wk = wk_ + (size_t)o*DKk*64;
    const float* wv = wv_ + (size_t)o*64*64;
    int ty = tid >> 4, tx = tid & 15;

    for (int idx = tid; idx < 64*64; idx += 256) {
        int r = idx >> 6, c = idx & 63;
        int gr = r0 + r;
        int q  = gr & 16383;
        int g2 = q >> 10, n = q & 1023;
        int b = g2 >> 2, seg = g2 & 3;
        xs[r][c] = Z[(size_t)(s*TOK + ((b<<10)+n)*SG + seg)*HID + c];
    }
    for (int chunk = 0; chunk < 2; chunk++) {
        __syncthreads();
        for (int idx = tid; idx < 64*64; idx += 256) {
            int r = idx >> 6, c = idx & 63;
            ws[r][c] = (chunk == 0) ? (r < 32 ? wq[r*64 + c] : wk[(r-32)*64 + c])
                                    : wv[r*64 + c];
        }
        __syncthreads();
        float acc[4][4];
#pragma unroll
        for (int i = 0; i < 4; i++)
#pragma unroll
            for (int j = 0; j < 4; j++) acc[i][j] = 0.f;
#pragma unroll 4
        for (int k = 0; k < 64; k += 4) {
            float4 xv[4], wv4[4];
#pragma unroll
            for (int i = 0; i < 4; i++) xv[i] = *(const float4*)&xs[4*ty+i][k];
#pragma unroll
            for (int j = 0; j < 4; j++) wv4[j] = *(const float4*)&ws[tx+16*j][k];
#pragma unroll
            for (int i = 0; i < 4; i++)
#pragma unroll
                for (int j = 0; j < 4; j++)
                    acc[i][j] += xv[i].x*wv4[j].x + xv[i].y*wv4[j].y + xv[i].z*wv4[j].z + xv[i].w*wv4[j].w;
        }
#pragma unroll
        for (int i = 0; i < 4; i++) {
            int gr = r0 + 4*ty + i;
#pragma unroll
            for (int j = 0; j < 4; j++) {
                int c = tx + 16*j;
                if (chunk == 0) {
                    if (c < 32) Q[(size_t)gr*32 + c] = acc[i][j];
                    else        K[(size_t)gr*32 + (c-32)] = acc[i][j];
                } else V[(size_t)gr*64 + c] = acc[i][j];
            }
        }
    }
}

// ---------------- attention: single-pass online softmax; dk=32, dv=64, N=1024/group ----------------
__global__ __launch_bounds__(256) void attn_kernel(const float* __restrict__ Q,
        const float* __restrict__ K, const float* __restrict__ V,
        float* __restrict__ O, float scale) {
    __shared__ float qs[64][32];
    __shared__ float ks[32][36];
    __shared__ float vs[32][64];
    __shared__ float ps[64][33];
    int g2 = blockIdx.x;
    int q0 = blockIdx.y * 64;
    int tid = threadIdx.x;
    int ty = tid >> 4, tx = tid & 15;
    const float* Qg = Q + (size_t)g2*NN*32;
    const float* Kg = K + (size_t)g2*NN*32;
    const float* Vg = V + (size_t)g2*NN*64;

    for (int idx = tid; idx < 64*32; idx += 256) qs[idx>>5][idx&31] = Qg[(size_t)q0*32 + idx];

    float m[4]   = {-1e30f, -1e30f, -1e30f, -1e30f};
    float l[4]   = {0.f, 0.f, 0.f, 0.f};
    float acc[4][4];
#pragma unroll
    for (int i = 0; i < 4; i++)
#pragma unroll
        for (int j = 0; j < 4; j++) acc[i][j] = 0.f;

    for (int kt = 0; kt < NN; kt += 32) {
        __syncthreads();
        for (int idx = tid; idx < 32*32; idx += 256) ks[idx>>5][idx&31] = Kg[(size_t)kt*32 + idx];
        for (int idx = tid; idx < 32*64; idx += 256) vs[idx>>6][idx&63] = Vg[(size_t)kt*64 + idx];
        __syncthreads();
        float sv[4][2];
#pragma unroll
        for (int i = 0; i < 4; i++) {
            int r = 4*ty + i;
#pragma unroll
            for (int j = 0; j < 2; j++) {
                int c = tx + 16*j;
                float a = 0.f;
#pragma unroll
                for (int d = 0; d < 32; d += 4) {
                    float4 qv = *(const float4*)&qs[r][d];
                    float4 kv = *(const float4*)&ks[c][d];
                    a += qv.x*kv.x + qv.y*kv.y + qv.z*kv.z + qv.w*kv.w;
                }
                sv[i][j] = a * scale;
            }
        }
#pragma unroll
        for (int i = 0; i < 4; i++) {
            float tm = fmaxf(sv[i][0], sv[i][1]);
#pragma unroll
            for (int off = 8; off; off >>= 1) tm = fmaxf(tm, __shfl_xor_sync(0xffffffffu, tm, off));
            float newm = fmaxf(m[i], tm);
            float factor = __expf(m[i] - newm);
            m[i] = newm;
            l[i] *= factor;
#pragma unroll
            for (int j = 0; j < 4; j++) acc[i][j] *= factor;
            int r = 4*ty + i;
#pragma unroll
            for (int j = 0; j < 2; j++) {
                float p = __expf(sv[i][j] - newm);
                ps[r][tx + 16*j] = p;
                l[i] += p;
            }
        }
        __syncthreads();
#pragma unroll 4
        for (int c = 0; c < 32; c++) {
            float hv0 = ps[4*ty+0][c], hv1 = ps[4*ty+1][c], hv2 = ps[4*ty+2][c], hv3 = ps[4*ty+3][c];
            float wv0 = vs[c][tx], wv1 = vs[c][tx+16], wv2 = vs[c][tx+32], wv3 = vs[c][tx+48];
            acc[0][0]+=hv0*wv0; acc[0][1]+=hv0*wv1; acc[0][2]+=hv0*wv2; acc[0][3]+=hv0*wv3;
            acc[1][0]+=hv1*wv0; acc[1][1]+=hv1*wv1; acc[1][2]+=hv1*wv2; acc[1][3]+=hv1*wv3;
            acc[2][0]+=hv2*wv0; acc[2][1]+=hv2*wv1; acc[2][2]+=hv2*wv2; acc[2][3]+=hv2*wv3;
            acc[3][0]+=hv3*wv0; acc[3][1]+=hv3*wv1; acc[3][2]+=hv3*wv2; acc[3][3]+=hv3*wv3;
        }
    }
#pragma unroll
    for (int off = 8; off; off >>= 1)
#pragma unroll
        for (int i = 0; i < 4; i++) l[i] += __shfl_xor_sync(0xffffffffu, l[i], off);
#pragma unroll
    for (int i = 0; i < 4; i++) {
        float inv = 1.f / l[i];
#pragma unroll
        for (int j = 0; j < 4; j++)
            O[(size_t)(g2*NN + q0 + 4*ty + i)*64 + tx + 16*j] = acc[i][j] * inv;
    }
}

// ---------------- GA epilogue: att = LN(att)*g+b + x ----------------
__global__ __launch_bounds__(256) void ga_epi_kernel(const float* __restrict__ ATT,
        float* __restrict__ Z, const float* __restrict__ g_, const float* __restrict__ bb_, int layer) {
    int w = threadIdx.x >> 5, lane = threadIdx.x & 31;
    int r = blockIdx.x * 8 + w;               // 0..32767
    int s = r >> 14;
    int o = s*LAY + layer;
    const float* g  = g_  + (size_t)o*64;
    const float* bb = bb_ + (size_t)o*64;
    int q = r & 16383;
    int g2 = q >> 10, n = q & 1023, b = g2 >> 2, seg = g2 & 3;
    float* zp = Z + (size_t)(s*TOK + ((b<<10)+n)*SG + seg)*HID;
    const float* ap = ATT + (size_t)r*HID;
    float v0 = ap[lane], v1 = ap[lane+32];
    float ssum = v0 + v1, qq = v0*v0 + v1*v1;
#pragma unroll
    for (int off = 16; off; off >>= 1) { ssum += __shfl_xor_sync(0xffffffffu, ssum, off); qq += __shfl_xor_sync(0xffffffffu, qq, off); }
    float mean = ssum * (1.f/64.f);
    float var  = qq * (1.f/64.f) - mean*mean;
    float rstd = rsqrtf(var + 1e-5f);
    zp[lane]      = (v0 - mean)*rstd*g[lane]    + bb[lane]    + zp[lane];
    zp[lane + 32] = (v1 - mean)*rstd*g[lane+32] + bb[lane+32] + zp[lane+32];
}

// ---------------- mean-pool over segments + concat (both streams) ----------------
__global__ __launch_bounds__(256) void pool_kernel(const float* __restrict__ Z,
        float* __restrict__ ENC) {
    int idx = blockIdx.x * 256 + threadIdx.x;   // over 2*B*NN*64
    int s  = idx >> 18;
    int rem = idx & 262143;
    int bn = rem >> 6, h = rem & 63;
    const float* zp = Z + (size_t)(s*TOK + bn*4)*64;
    float a = 0.25f * (zp[0*64+h] + zp[1*64+h] + zp[2*64+h] + zp[3*64+h]);
    ENC[(size_t)bn*128 + s*64 + h] = a;
}

// ---------------- final cross-attention projections (in dim = 128) ----------------
__global__ __launch_bounds__(256) void fproj_kernel(const float* __restrict__ ENC,
        const float* __restrict__ wq, const float* __restrict__ wk, const float* __restrict__ wv,
        float* __restrict__ Q, float* __restrict__ K, float* __restrict__ V) {
    __shared__ float xs[64][68];
    __shared__ float ws[64][68];
    int tid = threadIdx.x;
    int r0 = blockIdx.x * 64;
    int ty = tid >> 4, tx = tid & 15;
    float acc[2][4][4];
#pragma unroll
    for (int oc = 0; oc < 2; oc++)
#pragma unroll
        for (int i = 0; i < 4; i++)
#pragma unroll
            for (int j = 0; j < 4; j++) acc[oc][i][j] = 0.f;

    for (int kc = 0; kc < 2; kc++) {
        __syncthreads();
        for (int idx = tid; idx < 64*64; idx += 256) {
            int r = idx >> 6, c = idx & 63;
            xs[r][c] = ENC[(size_t)(r0+r)*128 + kc*64 + c];
        }
        for (int oc = 0; oc < 2; oc++) {
            __syncthreads();
            for (int idx = tid; idx < 64*64; idx += 256) {
                int r = idx >> 6, c = idx & 63;
                int gc = oc*64 + r;
                int k  = kc*64 + c;
                ws[r][c] = (gc < 32) ? wq[gc*128 + k] : (gc < 64) ? wk[(gc-32)*128 + k] : wv[(gc-64)*128 + k];
            }
            __syncthreads();
#pragma unroll 4
            for (int k = 0; k < 64; k += 4) {
                float4 xv[4], wv4[4];
#pragma unroll
                for (int i = 0; i < 4; i++) xv[i] = *(const float4*)&xs[4*ty+i][k];
#pragma unroll
                for (int j = 0; j < 4; j++) wv4[j] = *(const float4*)&ws[tx+16*j][k];
#pragma unroll
                for (int i = 0; i < 4; i++)
#pragma unroll
                    for (int j = 0; j < 4; j++)
                        acc[oc][i][j] += xv[i].x*wv4[j].x + xv[i].y*wv4[j].y + xv[i].z*wv4[j].z + xv[i].w*wv4[j].w;
            }
        }
    }
#pragma unroll
    for (int oc = 0; oc < 2; oc++)
#pragma unroll
        for (int i = 0; i < 4; i++) {
            int gr = r0 + 4*ty + i;
#pragma unroll
            for (int j = 0; j < 4; j++) {
                int gc = oc*64 + tx + 16*j;
                float v = acc[oc][i][j];
                if (gc < 32)      Q[(size_t)gr*32 + gc] = v;
                else if (gc < 64) K[(size_t)gr*32 + gc - 32] = v;
                else              V[(size_t)gr*64 + gc - 64] = v;
            }
        }
}

// ---------------- host launcher ----------------
extern "C" void kernel_launch(void* const* d_in, const int* in_sizes, int n_in,
                              void* d_out, int out_size) {
    const float* traffic  = (const float*)d_in[0];
    const float* user     = (const float*)d_in[1];
    const float* patch_w  = (const float*)d_in[2];
    const float* patch_b  = (const float*)d_in[3];
    const float* mha_w    = (const float*)d_in[4];
    const float* mha_b    = (const float*)d_in[5];
    const float* out_w    = (const float*)d_in[6];
    const float* out_b    = (const float*)d_in[7];
    const float* ff1_w    = (const float*)d_in[8];
    const float* ff1_b    = (const float*)d_in[9];
    const float* ff2_w    = (const float*)d_in[10];
    const float* ff2_b    = (const float*)d_in[11];
    const float* ln1_g    = (const float*)d_in[12];
    const float* ln1_b    = (const float*)d_in[13];
    const float* ln2_g    = (const float*)d_in[14];
    const float* ln2_b    = (const float*)d_in[15];
    const float* ga_wq    = (const float*)d_in[16];
    const float* ga_wk    = (const float*)d_in[17];
    const float* ga_wv    = (const float*)d_in[18];
    const float* ga_ff1_w = (const float*)d_in[19];
    const float* ga_ff1_b = (const float*)d_in[20];
    const float* ga_ff2_w = (const float*)d_in[21];
    const float* ga_ff2_b = (const float*)d_in[22];
    const float* ga_ln1_g = (const float*)d_in[23];
    const float* ga_ln1_b = (const float*)d_in[24];
    const float* ga_ln2_g = (const float*)d_in[25];
    const float* ga_ln2_b = (const float*)d_in[26];
    const float* ca_wq    = (const float*)d_in[27];
    const float* ca_wk    = (const float*)d_in[28];
    const float* ca_wv    = (const float*)d_in[29];

    float *Z, *Qb, *Kb, *Vb, *ATT, *ENC, *Q2, *K2, *V2;
    cudaGetSymbolAddress((void**)&Z,   d_Z);
    cudaGetSymbolAddress((void**)&Qb,  d_Qb);
    cudaGetSymbolAddress((void**)&Kb,  d_Kb);
    cudaGetSymbolAddress((void**)&Vb,  d_Vb);
    cudaGetSymbolAddress((void**)&ATT, d_ATT);
    cudaGetSymbolAddress((void**)&ENC, d_ENC);
    cudaGetSymbolAddress((void**)&Q2,  d_Q2);
    cudaGetSymbolAddress((void**)&K2,  d_K2);
    cudaGetSymbolAddress((void**)&V2,  d_V2);

    const int MHA_SMEM = MHA_SMEM_FLOATS * 4;   // 111,616 B
    const int FF_SMEM  = FF_SMEM_FLOATS * 4;    // 171,008 B
    cudaFuncSetAttribute(mha_kernel,   cudaFuncAttributeMaxDynamicSharedMemorySize, MHA_SMEM);
    cudaFuncSetAttribute(ff_ln_kernel, cudaFuncAttributeMaxDynamicSharedMemorySize, FF_SMEM);

    const float SCALE32 = 0.17677669529663687f;   // 1/sqrt(32)

    patch_kernel<<<2*B_*NN, 256>>>(traffic, user, patch_w, patch_b, Z);
    for (int i = 0; i < LAY; i++) {
        mha_kernel<<<2*TOK/64, 256, MHA_SMEM>>>(Z, mha_w, mha_b, out_w, out_b, ln1_g, ln1_b, i);
        ff_ln_kernel<<<2*TOK/128, 256, FF_SMEM>>>(Z, ff1_w, ff1_b, ff2_w, ff2_b, ln2_g, ln2_b, i);
        ga_qkv_kernel<<<2*TOK/64, 256>>>(Z, ga_wq, ga_wk, ga_wv, Qb, Kb, Vb, i);
        attn_kernel<<<dim3(2*GRP, NN/64), 256>>>(Qb, Kb, Vb, ATT, SCALE32);
        ga_epi_kernel<<<2*TOK/8, 256>>>(ATT, Z, ga_ln1_g, ga_ln1_b, i);
        ff_ln_kernel<<<2*TOK/128, 256, FF_SMEM>>>(Z, ga_ff1_w, ga_ff1_b, ga_ff2_w, ga_ff2_b, ga_ln2_g, ga_ln2_b, i);
    }
    pool_kernel<<<2*B_*NN*HID/256, 256>>>(Z, ENC);
    fproj_kernel<<<B_*NN/64, 256>>>(ENC, ca_wq, ca_wk, ca_wv, Q2, K2, V2);
    attn_kernel<<<dim3(B_, NN/64), 256>>>(Q2, K2, V2, (float*)d_out, SCALE32);
}

// round 7
// speedup vs baseline: 6.3315x; 1.8189x over previous
#include <cuda_runtime.h>
#include <math.h>

#define B_   4
#define SEQ_ 12
#define NN   1024
#define SL   3
#define SG   4
#define HID  64
#define FFD  2048
#define DKk  32
#define LAY  2
#define TOK  (B_*NN*SG)   /* 16384 per stream */
#define GRP  (B_*SG)      /* 16 per stream */

// ---------------- scratch (static device memory) ----------------
__device__ float d_Z[2*TOK*HID];          // [s][b][n][seg][h]
__device__ float d_Qb[2*GRP*NN*DKk];
__device__ float d_Kb[2*GRP*NN*DKk];
__device__ float d_Vb[2*GRP*NN*HID];
__device__ float d_ATT[2*GRP*NN*HID];
__device__ float d_ENC[B_*NN*2*HID];
__device__ float d_Q2[B_*NN*DKk];
__device__ float d_K2[B_*NN*DKk];
__device__ float d_V2[B_*NN*HID];

// ---------------- tf32 helpers ----------------
__device__ __forceinline__ unsigned f2tf32(float x) {
    unsigned r;
    asm("cvt.rna.tf32.f32 %0, %1;" : "=r"(r) : "f"(x));
    return r;
}
__device__ __forceinline__ void mma_tf32(float* c,
        unsigned a0, unsigned a1, unsigned a2, unsigned a3,
        unsigned b0, unsigned b1) {
    asm volatile("mma.sync.aligned.m16n8k8.row.col.f32.tf32.tf32.f32 "
        "{%0,%1,%2,%3}, {%4,%5,%6,%7}, {%8,%9}, {%0,%1,%2,%3};"
        : "+f"(c[0]), "+f"(c[1]), "+f"(c[2]), "+f"(c[3])
        : "r"(a0), "r"(a1), "r"(a2), "r"(a3), "r"(b0), "r"(b1));
}

// ---------------- patch embedding + positional encoding (both streams) ----------------
__global__ __launch_bounds__(256) void patch_kernel(const float* __restrict__ traffic,
                                                    const float* __restrict__ user,
                                                    const float* __restrict__ pw,
                                                    const float* __restrict__ pb,
                                                    float* __restrict__ Z) {
    int blk = blockIdx.x;                // 0..8191
    int s   = blk >> 12;
    int bn  = blk & 4095;
    int b   = bn >> 10, n = bn & 1023;
    const float* x = s ? user : traffic;
    const float* pws = pw + s*HID*SL;
    const float* pbs = pb + s*HID;
    int t   = threadIdx.x;
    int seg = t >> 6, h = t & 63;
    float acc = pbs[h];
#pragma unroll
    for (int l = 0; l < SL; l++)
        acc += pws[h*SL + l] * x[(b*SEQ_ + seg*SL + l)*NN + n];
    int he = h & ~1;
    float dv = expf(-(float)he * (9.210340371976184f / (float)HID));
    float ang = (float)seg * dv;
    acc += (h & 1) ? cosf(ang) : sinf(ang);
    Z[(size_t)(s*TOK + bn*SG + seg)*HID + h] = acc;
}

// ---------------- temporal encoder: MHA + residual + LN1; 64 tokens / block ----------------
#define MHA_SMEM_FLOATS (4352 + 4352 + 12800 + 2048 + 4352)
__global__ __launch_bounds__(256) void mha_kernel(float* __restrict__ Z,
        const float* __restrict__ mw_, const float* __restrict__ mb_,
        const float* __restrict__ ow_, const float* __restrict__ ob_,
        const float* __restrict__ g1_, const float* __restrict__ b1_, int layer) {
    extern __shared__ float sm[];
    float (*xs)[68]  = (float(*)[68])sm;
    float (*wb)[68]  = (float(*)[68])(sm + 4352);
    float (*qkv)[200]= (float(*)[200])(sm + 8704);
    float *ps        = sm + 21504;
    float (*os)[68]  = (float(*)[68])(sm + 23552);

    int tid = threadIdx.x;
    int ty = tid >> 4, tx = tid & 15;
    int s  = blockIdx.x >> 8;                 // 512 blocks, 256 per stream
    int o  = s*LAY + layer;
    const float* mw = mw_ + (size_t)o*192*64;
    const float* mb = mb_ + (size_t)o*192;
    const float* ow = ow_ + (size_t)o*64*64;
    const float* ob = ob_ + (size_t)o*64;
    const float* g1 = g1_ + (size_t)o*64;
    const float* b1 = b1_ + (size_t)o*64;
    size_t t0 = (size_t)blockIdx.x * 64;
    float* zb = Z + t0 * HID;

    for (int idx = tid; idx < 64*16; idx += 256) {
        int r = idx >> 4, c4 = idx & 15;
        *(float4*)&xs[r][4*c4] = *(const float4*)&zb[(size_t)r*64 + 4*c4];
    }

    // ---- QKV = X @ W^T + b ----
    for (int cc = 0; cc < 3; cc++) {
        __syncthreads();
        for (int idx = tid; idx < 64*16; idx += 256) {
            int r = idx >> 4, c4 = idx & 15;
            *(float4*)&wb[r][4*c4] = *(const float4*)&mw[(size_t)(cc*64 + r)*64 + 4*c4];
        }
        __syncthreads();
        float acc[4][4];
#pragma unroll
        for (int j = 0; j < 4; j++) {
            float bv = mb[cc*64 + tx + 16*j];
#pragma unroll
            for (int i = 0; i < 4; i++) acc[i][j] = bv;
        }
#pragma unroll 4
        for (int k = 0; k < 64; k += 4) {
            float4 xv[4], wv[4];
#pragma unroll
            for (int i = 0; i < 4; i++) xv[i] = *(const float4*)&xs[4*ty+i][k];
#pragma unroll
            for (int j = 0; j < 4; j++) wv[j] = *(const float4*)&wb[tx+16*j][k];
#pragma unroll
            for (int i = 0; i < 4; i++)
#pragma unroll
                for (int j = 0; j < 4; j++)
                    acc[i][j] += xv[i].x*wv[j].x + xv[i].y*wv[j].y + xv[i].z*wv[j].z + xv[i].w*wv[j].w;
        }
#pragma unroll
        for (int i = 0; i < 4; i++)
#pragma unroll
            for (int j = 0; j < 4; j++)
                qkv[4*ty+i][cc*64 + tx + 16*j] = acc[i][j];
    }
    __syncthreads();

    // ---- scores + softmax ----
    for (int T = tid; T < 512; T += 256) {
        int g = T >> 5, h = (T >> 2) & 7, i = T & 3;
        const float* q = &qkv[g*4 + i][h*8];
        float sc[4];
#pragma unroll
        for (int j = 0; j < 4; j++) {
            const float* kk = &qkv[g*4 + j][64 + h*8];
            float a = 0.f;
#pragma unroll
            for (int d = 0; d < 8; d++) a += q[d] * kk[d];
            sc[j] = a * 0.3535533905932738f;
        }
        float m = fmaxf(fmaxf(sc[0], sc[1]), fmaxf(sc[2], sc[3]));
        float e0 = __expf(sc[0]-m), e1 = __expf(sc[1]-m), e2 = __expf(sc[2]-m), e3 = __expf(sc[3]-m);
        float inv = 1.f / (e0+e1+e2+e3);
        ps[T*4+0] = e0*inv; ps[T*4+1] = e1*inv; ps[T*4+2] = e2*inv; ps[T*4+3] = e3*inv;
    }
    __syncthreads();

    // ---- O = att @ V ----
#pragma unroll
    for (int i = 0; i < 4; i++) {
        int r = 4*ty + i;
        int g = r >> 2, ii = r & 3;
#pragma unroll
        for (int j = 0; j < 4; j++) {
            int c = tx + 16*j;
            int h = c >> 3;
            const float* a = ps + (((g*8 + h)*4) + ii)*4;
            os[r][c] = a[0]*qkv[g*4+0][128+c] + a[1]*qkv[g*4+1][128+c]
                     + a[2]*qkv[g*4+2][128+c] + a[3]*qkv[g*4+3][128+c];
        }
    }
    __syncthreads();

    // ---- out proj + residual ----
    for (int idx = tid; idx < 64*16; idx += 256) {
        int r = idx >> 4, c4 = idx & 15;
        *(float4*)&wb[r][4*c4] = *(const float4*)&ow[(size_t)r*64 + 4*c4];
    }
    __syncthreads();
    {
        float acc[4][4];
#pragma unroll
        for (int j = 0; j < 4; j++) {
            float bv = ob[tx + 16*j];
#pragma unroll
            for (int i = 0; i < 4; i++) acc[i][j] = bv;
        }
#pragma unroll 4
        for (int k = 0; k < 64; k += 4) {
            float4 xv[4], wv[4];
#pragma unroll
            for (int i = 0; i < 4; i++) xv[i] = *(const float4*)&os[4*ty+i][k];
#pragma unroll
            for (int j = 0; j < 4; j++) wv[j] = *(const float4*)&wb[tx+16*j][k];
#pragma unroll
            for (int i = 0; i < 4; i++)
#pragma unroll
                for (int j = 0; j < 4; j++)
                    acc[i][j] += xv[i].x*wv[j].x + xv[i].y*wv[j].y + xv[i].z*wv[j].z + xv[i].w*wv[j].w;
        }
        __syncthreads();
#pragma unroll
        for (int i = 0; i < 4; i++)
#pragma unroll
            for (int j = 0; j < 4; j++)
                xs[4*ty+i][tx+16*j] += acc[i][j];
    }
    __syncthreads();
    // ---- LN ----
    int w = tid >> 5, lane = tid & 31;
#pragma unroll
    for (int rr = 0; rr < 8; rr++) {
        int r = w*8 + rr;
        float v0 = xs[r][lane], v1 = xs[r][lane+32];
        float ssum = v0 + v1, q = v0*v0 + v1*v1;
#pragma unroll
        for (int off = 16; off; off >>= 1) { ssum += __shfl_xor_sync(0xffffffffu, ssum, off); q += __shfl_xor_sync(0xffffffffu, q, off); }
        float mean = ssum * (1.f/64.f);
        float var  = q * (1.f/64.f) - mean*mean;
        float rstd = rsqrtf(var + 1e-5f);
        zb[(size_t)r*64 + lane]      = (v0 - mean)*rstd*g1[lane]    + b1[lane];
        zb[(size_t)r*64 + lane + 32] = (v1 - mean)*rstd*g1[lane+32] + b1[lane+32];
    }
}

// ---------------- fused FF + residual + LN: tf32 tensor cores, 128 tokens/block ----------------
// smem: xs[128][68] fp32 | hs[128][132] tf32 | w1s[128][68] tf32 | w2s[64][132] tf32
#define FF_SMEM_FLOATS (8704 + 16896 + 8704 + 8448)
__global__ __launch_bounds__(256) void ff_ln_kernel(float* __restrict__ Z,
        const float* __restrict__ w1_, const float* __restrict__ b1_,
        const float* __restrict__ w2_, const float* __restrict__ b2_,
        const float* __restrict__ g_, const float* __restrict__ bb_, int layer) {
    extern __shared__ float sm[];
    float (*xs)[68]   = (float(*)[68])sm;
    float (*hs)[132]  = (float(*)[132])(sm + 8704);
    float (*w1s)[68]  = (float(*)[68])(sm + 8704 + 16896);
    float (*w2s)[132] = (float(*)[132])(sm + 8704 + 16896 + 8704);

    int tid = threadIdx.x;
    int s   = blockIdx.x >> 7;           // 256 blocks, 128 per stream
    int o   = s*LAY + layer;
    const float* w1 = w1_ + (size_t)o*FFD*64;
    const float* b1 = b1_ + (size_t)o*FFD;
    const float* w2 = w2_ + (size_t)o*64*FFD;
    const float* b2 = b2_ + (size_t)o*64;
    const float* g  = g_  + (size_t)o*64;
    const float* bb = bb_ + (size_t)o*64;
    size_t t0 = (size_t)blockIdx.x * 128;

    int wid  = tid >> 5, lane = tid & 31;
    int lr = lane >> 2, lc = lane & 3;           // fragment row/col
    int wm = wid >> 2, wn = wid & 3;             // warp grid 2 x 4
    int mb = wm*64, nbh = wn*32, nbo = wn*16;

    for (int idx = tid; idx < 128*16; idx += 256) {
        int r = idx >> 4, c4 = idx & 15;
        *(float4*)&xs[r][4*c4] = *(const float4*)&Z[(t0 + r)*64 + 4*c4];
    }

    float oacc[4][2][4];
#pragma unroll
    for (int t = 0; t < 4; t++)
#pragma unroll
        for (int j = 0; j < 2; j++)
#pragma unroll
            for (int q = 0; q < 4; q++) oacc[t][j][q] = 0.f;

    for (int fc = 0; fc < FFD; fc += 128) {
        __syncthreads();
        // stage weights, pre-rounded to tf32
        for (int idx = tid; idx < 128*16; idx += 256) {
            int r = idx >> 4, c4 = idx & 15;
            float4 v = *(const float4*)&w1[(size_t)(fc+r)*64 + 4*c4];
            w1s[r][4*c4+0] = __uint_as_float(f2tf32(v.x));
            w1s[r][4*c4+1] = __uint_as_float(f2tf32(v.y));
            w1s[r][4*c4+2] = __uint_as_float(f2tf32(v.z));
            w1s[r][4*c4+3] = __uint_as_float(f2tf32(v.w));
        }
        for (int idx = tid; idx < 64*32; idx += 256) {
            int r = idx >> 5, c4 = idx & 31;
            float4 v = *(const float4*)&w2[(size_t)r*FFD + fc + 4*c4];
            w2s[r][4*c4+0] = __uint_as_float(f2tf32(v.x));
            w2s[r][4*c4+1] = __uint_as_float(f2tf32(v.y));
            w2s[r][4*c4+2] = __uint_as_float(f2tf32(v.z));
            w2s[r][4*c4+3] = __uint_as_float(f2tf32(v.w));
        }
        __syncthreads();

        // ---- H[128][128] = relu(X @ W1c^T + b1c), tf32 mma ----
        float hacc[4][4][4];
#pragma unroll
        for (int t = 0; t < 4; t++)
#pragma unroll
            for (int j = 0; j < 4; j++)
#pragma unroll
                for (int q = 0; q < 4; q++) hacc[t][j][q] = 0.f;

#pragma unroll
        for (int k0 = 0; k0 < 64; k0 += 8) {
            unsigned a[4][4];
#pragma unroll
            for (int t = 0; t < 4; t++) {
                int r = mb + 16*t + lr;
                a[t][0] = f2tf32(xs[r][k0+lc]);
                a[t][1] = f2tf32(xs[r+8][k0+lc]);
                a[t][2] = f2tf32(xs[r][k0+lc+4]);
                a[t][3] = f2tf32(xs[r+8][k0+lc+4]);
            }
#pragma unroll
            for (int j = 0; j < 4; j++) {
                unsigned b0 = __float_as_uint(w1s[nbh+8*j+lr][k0+lc]);
                unsigned bq = __float_as_uint(w1s[nbh+8*j+lr][k0+lc+4]);
#pragma unroll
                for (int t = 0; t < 4; t++)
                    mma_tf32(hacc[t][j], a[t][0], a[t][1], a[t][2], a[t][3], b0, bq);
            }
        }
        // bias + relu, store to hs pre-rounded to tf32 (hs only feeds GEMM2)
#pragma unroll
        for (int j = 0; j < 4; j++) {
            int c = nbh + 8*j + 2*lc;
            float bv0 = b1[fc + c], bv1 = b1[fc + c + 1];
#pragma unroll
            for (int t = 0; t < 4; t++) {
                int r = mb + 16*t + lr;
                hs[r][c]     = __uint_as_float(f2tf32(fmaxf(hacc[t][j][0] + bv0, 0.f)));
                hs[r][c+1]   = __uint_as_float(f2tf32(fmaxf(hacc[t][j][1] + bv1, 0.f)));
                hs[r+8][c]   = __uint_as_float(f2tf32(fmaxf(hacc[t][j][2] + bv0, 0.f)));
                hs[r+8][c+1] = __uint_as_float(f2tf32(fmaxf(hacc[t][j][3] + bv1, 0.f)));
            }
        }
        __syncthreads();

        // ---- O[128][64] += H @ W2c^T, tf32 mma ----
#pragma unroll
        for (int k0 = 0; k0 < 128; k0 += 8) {
            unsigned a[4][4];
#pragma unroll
            for (int t = 0; t < 4; t++) {
                int r = mb + 16*t + lr;
                a[t][0] = __float_as_uint(hs[r][k0+lc]);
                a[t][1] = __float_as_uint(hs[r+8][k0+lc]);
                a[t][2] = __float_as_uint(hs[r][k0+lc+4]);
                a[t][3] = __float_as_uint(hs[r+8][k0+lc+4]);
            }
#pragma unroll
            for (int j = 0; j < 2; j++) {
                unsigned b0 = __float_as_uint(w2s[nbo+8*j+lr][k0+lc]);
                unsigned bq = __float_as_uint(w2s[nbo+8*j+lr][k0+lc+4]);
#pragma unroll
                for (int t = 0; t < 4; t++)
                    mma_tf32(oacc[t][j], a[t][0], a[t][1], a[t][2], a[t][3], b0, bq);
            }
        }
    }
    __syncthreads();
    // residual: each (r,c) has exactly one owner thread
#pragma unroll
    for (int j = 0; j < 2; j++) {
        int c = nbo + 8*j + 2*lc;
        float bv0 = b2[c], bv1 = b2[c+1];
#pragma unroll
        for (int t = 0; t < 4; t++) {
            int r = mb + 16*t + lr;
            xs[r][c]     += oacc[t][j][0] + bv0;
            xs[r][c+1]   += oacc[t][j][1] + bv1;
            xs[r+8][c]   += oacc[t][j][2] + bv0;
            xs[r+8][c+1] += oacc[t][j][3] + bv1;
        }
    }
    __syncthreads();
    int w = tid >> 5, lane2 = tid & 31;
#pragma unroll
    for (int rr = 0; rr < 16; rr++) {
        int r = w*16 + rr;
        float v0 = xs[r][lane2], v1 = xs[r][lane2+32];
        float ssum = v0 + v1, q = v0*v0 + v1*v1;
#pragma unroll
        for (int off = 16; off; off >>= 1) { ssum += __shfl_xor_sync(0xffffffffu, ssum, off); q += __shfl_xor_sync(0xffffffffu, q, off); }
        float mean = ssum * (1.f/64.f);
        float var  = q * (1.f/64.f) - mean*mean;
        float rstd = rsqrtf(var + 1e-5f);
        Z[(t0+r)*64 + lane2]      = (v0 - mean)*rstd*g[lane2]    + bb[lane2];
        Z[(t0+r)*64 + lane2 + 32] = (v1 - mean)*rstd*g[lane2+32] + bb[lane2+32];
    }
}

// ---------------- graph-attention QKV projection: 64 rows/block ----------------
__global__ __launch_bounds__(256) void ga_qkv_kernel(const float* __restrict__ Z,
        const float* __restrict__ wq_, const float* __restrict__ wk_, const float* __restrict__ wv_,
        float* __restrict__ Q, float* __restrict__ K, float* __restrict__ V, int layer) {
    __shared__ float xs[64][68];
    __shared__ float ws[64][68];
    int tid = threadIdx.x;
    int r0 = blockIdx.x * 64;
    int s  = r0 >> 14;
    int o  = s*LAY + layer;
    const float* wq = wq_ + (size_t)o*DKk*64;
    const float* wk = wk_ + (size_t)o*DKk*64;
    const float* wv = wv_ + (size_t)o*64*64;
    int ty = tid >> 4, tx = tid & 15;

    for (int idx = tid; idx < 64*64; idx += 256) {
        int r = idx >> 6, c = idx & 63;
        int gr = r0 + r;
        int q  = gr & 16383;
        int g2 = q >> 10, n = q & 1023;
        int b = g2 >> 2, seg = g2 & 3;
        xs[r][c] = Z[(size_t)(s*TOK + ((b<<10)+n)*SG + seg)*HID + c];
    }
    for (int chunk = 0; chunk < 2; chunk++) {
        __syncthreads();
        for (int idx = tid; idx < 64*64; idx += 256) {
            int r = idx >> 6, c = idx & 63;
            ws[r][c] = (chunk == 0) ? (r < 32 ? wq[r*64 + c] : wk[(r-32)*64 + c])
                                    : wv[r*64 + c];
        }
        __syncthreads();
        float acc[4][4];
#pragma unroll
        for (int i = 0; i < 4; i++)
#pragma unroll
            for (int j = 0; j < 4; j++) acc[i][j] = 0.f;
#pragma unroll 4
        for (int k = 0; k < 64; k += 4) {
            float4 xv[4], wv4[4];
#pragma unroll
            for (int i = 0; i < 4; i++) xv[i] = *(const float4*)&xs[4*ty+i][k];
#pragma unroll
            for (int j = 0; j < 4; j++) wv4[j] = *(const float4*)&ws[tx+16*j][k];
#pragma unroll
            for (int i = 0; i < 4; i++)
#pragma unroll
                for (int j = 0; j < 4; j++)
                    acc[i][j] += xv[i].x*wv4[j].x + xv[i].y*wv4[j].y + xv[i].z*wv4[j].z + xv[i].w*wv4[j].w;
        }
#pragma unroll
        for (int i = 0; i < 4; i++) {
            int gr = r0 + 4*ty + i;
#pragma unroll
            for (int j = 0; j < 4; j++) {
                int c = tx + 16*j;
                if (chunk == 0) {
                    if (c < 32) Q[(size_t)gr*32 + c] = acc[i][j];
                    else        K[(size_t)gr*32 + (c-32)] = acc[i][j];
                } else V[(size_t)gr*64 + c] = acc[i][j];
            }
        }
    }
}

// ---------------- attention: single-pass online softmax; dk=32, dv=64, N=1024/group ----------------
__global__ __launch_bounds__(256) void attn_kernel(const float* __restrict__ Q,
        const float* __restrict__ K, const float* __restrict__ V,
        float* __restrict__ O, float scale) {
    __shared__ float qs[64][32];
    __shared__ float ks[32][36];
    __shared__ float vs[32][64];
    __shared__ float ps[64][33];
    int g2 = blockIdx.x;
    int q0 = blockIdx.y * 64;
    int tid = threadIdx.x;
    int ty = tid >> 4, tx = tid & 15;
    const float* Qg = Q + (size_t)g2*NN*32;
    const float* Kg = K + (size_t)g2*NN*32;
    const float* Vg = V + (size_t)g2*NN*64;

    for (int idx = tid; idx < 64*32; idx += 256) qs[idx>>5][idx&31] = Qg[(size_t)q0*32 + idx];

    float m[4]   = {-1e30f, -1e30f, -1e30f, -1e30f};
    float l[4]   = {0.f, 0.f, 0.f, 0.f};
    float acc[4][4];
#pragma unroll
    for (int i = 0; i < 4; i++)
#pragma unroll
        for (int j = 0; j < 4; j++) acc[i][j] = 0.f;

    for (int kt = 0; kt < NN; kt += 32) {
        __syncthreads();
        for (int idx = tid; idx < 32*32; idx += 256) ks[idx>>5][idx&31] = Kg[(size_t)kt*32 + idx];
        for (int idx = tid; idx < 32*64; idx += 256) vs[idx>>6][idx&63] = Vg[(size_t)kt*64 + idx];
        __syncthreads();
        float sv[4][2];
#pragma unroll
        for (int i = 0; i < 4; i++) {
            int r = 4*ty + i;
#pragma unroll
            for (int j = 0; j < 2; j++) {
                int c = tx + 16*j;
                float a = 0.f;
#pragma unroll
                for (int d = 0; d < 32; d += 4) {
                    float4 qv = *(const float4*)&qs[r][d];
                    float4 kv = *(const float4*)&ks[c][d];
                    a += qv.x*kv.x + qv.y*kv.y + qv.z*kv.z + qv.w*kv.w;
                }
                sv[i][j] = a * scale;
            }
        }
#pragma unroll
        for (int i = 0; i < 4; i++) {
            float tm = fmaxf(sv[i][0], sv[i][1]);
#pragma unroll
            for (int off = 8; off; off >>= 1) tm = fmaxf(tm, __shfl_xor_sync(0xffffffffu, tm, off));
            float newm = fmaxf(m[i], tm);
            float factor = __expf(m[i] - newm);
            m[i] = newm;
            l[i] *= factor;
#pragma unroll
            for (int j = 0; j < 4; j++) acc[i][j] *= factor;
            int r = 4*ty + i;
#pragma unroll
            for (int j = 0; j < 2; j++) {
                float p = __expf(sv[i][j] - newm);
                ps[r][tx + 16*j] = p;
                l[i] += p;
            }
        }
        __syncthreads();
#pragma unroll 4
        for (int c = 0; c < 32; c++) {
            float hv0 = ps[4*ty+0][c], hv1 = ps[4*ty+1][c], hv2 = ps[4*ty+2][c], hv3 = ps[4*ty+3][c];
            float wv0 = vs[c][tx], wv1 = vs[c][tx+16], wv2 = vs[c][tx+32], wv3 = vs[c][tx+48];
            acc[0][0]+=hv0*wv0; acc[0][1]+=hv0*wv1; acc[0][2]+=hv0*wv2; acc[0][3]+=hv0*wv3;
            acc[1][0]+=hv1*wv0; acc[1][1]+=hv1*wv1; acc[1][2]+=hv1*wv2; acc[1][3]+=hv1*wv3;
            acc[2][0]+=hv2*wv0; acc[2][1]+=hv2*wv1; acc[2][2]+=hv2*wv2; acc[2][3]+=hv2*wv3;
            acc[3][0]+=hv3*wv0; acc[3][1]+=hv3*wv1; acc[3][2]+=hv3*wv2; acc[3][3]+=hv3*wv3;
        }
    }
#pragma unroll
    for (int off = 8; off; off >>= 1)
#pragma unroll
        for (int i = 0; i < 4; i++) l[i] += __shfl_xor_sync(0xffffffffu, l[i], off);
#pragma unroll
    for (int i = 0; i < 4; i++) {
        float inv = 1.f / l[i];
#pragma unroll
        for (int j = 0; j < 4; j++)
            O[(size_t)(g2*NN + q0 + 4*ty + i)*64 + tx + 16*j] = acc[i][j] * inv;
    }
}

// ---------------- GA epilogue: att = LN(att)*g+b + x ----------------
__global__ __launch_bounds__(256) void ga_epi_kernel(const float* __restrict__ ATT,
        float* __restrict__ Z, const float* __restrict__ g_, const float* __restrict__ bb_, int layer) {
    int w = threadIdx.x >> 5, lane = threadIdx.x & 31;
    int r = blockIdx.x * 8 + w;               // 0..32767
    int s = r >> 14;
    int o = s*LAY + layer;
    const float* g  = g_  + (size_t)o*64;
    const float* bb = bb_ + (size_t)o*64;
    int q = r & 16383;
    int g2 = q >> 10, n = q & 1023, b = g2 >> 2, seg = g2 & 3;
    float* zp = Z + (size_t)(s*TOK + ((b<<10)+n)*SG + seg)*HID;
    const float* ap = ATT + (size_t)r*HID;
    float v0 = ap[lane], v1 = ap[lane+32];
    float ssum = v0 + v1, qq = v0*v0 + v1*v1;
#pragma unroll
    for (int off = 16; off; off >>= 1) { ssum += __shfl_xor_sync(0xffffffffu, ssum, off); qq += __shfl_xor_sync(0xffffffffu, qq, off); }
    float mean = ssum * (1.f/64.f);
    float var  = qq * (1.f/64.f) - mean*mean;
    float rstd = rsqrtf(var + 1e-5f);
    zp[lane]      = (v0 - mean)*rstd*g[lane]    + bb[lane]    + zp[lane];
    zp[lane + 32] = (v1 - mean)*rstd*g[lane+32] + bb[lane+32] + zp[lane+32];
}

// ---------------- mean-pool over segments + concat (both streams) ----------------
__global__ __launch_bounds__(256) void pool_kernel(const float* __restrict__ Z,
        float* __restrict__ ENC) {
    int idx = blockIdx.x * 256 + threadIdx.x;   // over 2*B*NN*64
    int s  = idx >> 18;
    int rem = idx & 262143;
    int bn = rem >> 6, h = rem & 63;
    const float* zp = Z + (size_t)(s*TOK + bn*4)*64;
    float a = 0.25f * (zp[0*64+h] + zp[1*64+h] + zp[2*64+h] + zp[3*64+h]);
    ENC[(size_t)bn*128 + s*64 + h] = a;
}

// ---------------- final cross-attention projections (in dim = 128) ----------------
__global__ __launch_bounds__(256) void fproj_kernel(const float* __restrict__ ENC,
        const float* __restrict__ wq, const float* __restrict__ wk, const float* __restrict__ wv,
        float* __restrict__ Q, float* __restrict__ K, float* __restrict__ V) {
    __shared__ float xs[64][68];
    __shared__ float ws[64][68];
    int tid = threadIdx.x;
    int r0 = blockIdx.x * 64;
    int ty = tid >> 4, tx = tid & 15;
    float acc[2][4][4];
#pragma unroll
    for (int oc = 0; oc < 2; oc++)
#pragma unroll
        for (int i = 0; i < 4; i++)
#pragma unroll
            for (int j = 0; j < 4; j++) acc[oc][i][j] = 0.f;

    for (int kc = 0; kc < 2; kc++) {
        __syncthreads();
        for (int idx = tid; idx < 64*64; idx += 256) {
            int r = idx >> 6, c = idx & 63;
            xs[r][c] = ENC[(size_t)(r0+r)*128 + kc*64 + c];
        }
        for (int oc = 0; oc < 2; oc++) {
            __syncthreads();
            for (int idx = tid; idx < 64*64; idx += 256) {
                int r = idx >> 6, c = idx & 63;
                int gc = oc*64 + r;
                int k  = kc*64 + c;
                ws[r][c] = (gc < 32) ? wq[gc*128 + k] : (gc < 64) ? wk[(gc-32)*128 + k] : wv[(gc-64)*128 + k];
            }
            __syncthreads();
#pragma unroll 4
            for (int k = 0; k < 64; k += 4) {
                float4 xv[4], wv4[4];
#pragma unroll
                for (int i = 0; i < 4; i++) xv[i] = *(const float4*)&xs[4*ty+i][k];
#pragma unroll
                for (int j = 0; j < 4; j++) wv4[j] = *(const float4*)&ws[tx+16*j][k];
#pragma unroll
                for (int i = 0; i < 4; i++)
#pragma unroll
                    for (int j = 0; j < 4; j++)
                        acc[oc][i][j] += xv[i].x*wv4[j].x + xv[i].y*wv4[j].y + xv[i].z*wv4[j].z + xv[i].w*wv4[j].w;
            }
        }
    }
#pragma unroll
    for (int oc = 0; oc < 2; oc++)
#pragma unroll
        for (int i = 0; i < 4; i++) {
            int gr = r0 + 4*ty + i;
#pragma unroll
            for (int j = 0; j < 4; j++) {
                int gc = oc*64 + tx + 16*j;
                float v = acc[oc][i][j];
                if (gc < 32)      Q[(size_t)gr*32 + gc] = v;
                else if (gc < 64) K[(size_t)gr*32 + gc - 32] = v;
                else              V[(size_t)gr*64 + gc - 64] = v;
            }
        }
}

// ---------------- host launcher ----------------
extern "C" void kernel_launch(void* const* d_in, const int* in_sizes, int n_in,
                              void* d_out, int out_size) {
    const float* traffic  = (const float*)d_in[0];
    const float* user     = (const float*)d_in[1];
    const float* patch_w  = (const float*)d_in[2];
    const float* patch_b  = (const float*)d_in[3];
    const float* mha_w    = (const float*)d_in[4];
    const float* mha_b    = (const float*)d_in[5];
    const float* out_w    = (const float*)d_in[6];
    const float* out_b    = (const float*)d_in[7];
    const float* ff1_w    = (const float*)d_in[8];
    const float* ff1_b    = (const float*)d_in[9];
    const float* ff2_w    = (const float*)d_in[10];
    const float* ff2_b    = (const float*)d_in[11];
    const float* ln1_g    = (const float*)d_in[12];
    const float* ln1_b    = (const float*)d_in[13];
    const float* ln2_g    = (const float*)d_in[14];
    const float* ln2_b    = (const float*)d_in[15];
    const float* ga_wq    = (const float*)d_in[16];
    const float* ga_wk    = (const float*)d_in[17];
    const float* ga_wv    = (const float*)d_in[18];
    const float* ga_ff1_w = (const float*)d_in[19];
    const float* ga_ff1_b = (const float*)d_in[20];
    const float* ga_ff2_w = (const float*)d_in[21];
    const float* ga_ff2_b = (const float*)d_in[22];
    const float* ga_ln1_g = (const float*)d_in[23];
    const float* ga_ln1_b = (const float*)d_in[24];
    const float* ga_ln2_g = (const float*)d_in[25];
    const float* ga_ln2_b = (const float*)d_in[26];
    const float* ca_wq    = (const float*)d_in[27];
    const float* ca_wk    = (const float*)d_in[28];
    const float* ca_wv    = (const float*)d_in[29];

    float *Z, *Qb, *Kb, *Vb, *ATT, *ENC, *Q2, *K2, *V2;
    cudaGetSymbolAddress((void**)&Z,   d_Z);
    cudaGetSymbolAddress((void**)&Qb,  d_Qb);
    cudaGetSymbolAddress((void**)&Kb,  d_Kb);
    cudaGetSymbolAddress((void**)&Vb,  d_Vb);
    cudaGetSymbolAddress((void**)&ATT, d_ATT);
    cudaGetSymbolAddress((void**)&ENC, d_ENC);
    cudaGetSymbolAddress((void**)&Q2,  d_Q2);
    cudaGetSymbolAddress((void**)&K2,  d_K2);
    cudaGetSymbolAddress((void**)&V2,  d_V2);

    const int MHA_SMEM = MHA_SMEM_FLOATS * 4;   // 111,616 B
    const int FF_SMEM  = FF_SMEM_FLOATS * 4;    // 171,008 B
    cudaFuncSetAttribute(mha_kernel,   cudaFuncAttributeMaxDynamicSharedMemorySize, MHA_SMEM);
    cudaFuncSetAttribute(ff_ln_kernel, cudaFuncAttributeMaxDynamicSharedMemorySize, FF_SMEM);

    const float SCALE32 = 0.17677669529663687f;   // 1/sqrt(32)

    patch_kernel<<<2*B_*NN, 256>>>(traffic, user, patch_w, patch_b, Z);
    for (int i = 0; i < LAY; i++) {
        mha_kernel<<<2*TOK/64, 256, MHA_SMEM>>>(Z, mha_w, mha_b, out_w, out_b, ln1_g, ln1_b, i);
        ff_ln_kernel<<<2*TOK/128, 256, FF_SMEM>>>(Z, ff1_w, ff1_b, ff2_w, ff2_b, ln2_g, ln2_b, i);
        ga_qkv_kernel<<<2*TOK/64, 256>>>(Z, ga_wq, ga_wk, ga_wv, Qb, Kb, Vb, i);
        attn_kernel<<<dim3(2*GRP, NN/64), 256>>>(Qb, Kb, Vb, ATT, SCALE32);
        ga_epi_kernel<<<2*TOK/8, 256>>>(ATT, Z, ga_ln1_g, ga_ln1_b, i);
        ff_ln_kernel<<<2*TOK/128, 256, FF_SMEM>>>(Z, ga_ff1_w, ga_ff1_b, ga_ff2_w, ga_ff2_b, ga_ln2_g, ga_ln2_b, i);
    }
    pool_kernel<<<2*B_*NN*HID/256, 256>>>(Z, ENC);
    fproj_kernel<<<B_*NN/64, 256>>>(ENC, ca_wq, ca_wk, ca_wv, Q2, K2, V2);
    attn_kernel<<<dim3(B_, NN/64), 256>>>(Q2, K2, V2, (float*)d_out, SCALE32);
}

// round 9
// speedup vs baseline: 8.2627x; 1.3050x over previous
#include <cuda_runtime.h>
#include <math.h>

#define B_   4
#define SEQ_ 12
#define NN   1024
#define SL   3
#define SG   4
#define HID  64
#define FFD  2048
#define DKk  32
#define LAY  2
#define TOK  (B_*NN*SG)   /* 16384 per stream */
#define GRP  (B_*SG)      /* 16 per stream */

// ---------------- scratch (static device memory) ----------------
__device__ float d_Z[2*TOK*HID];          // [s][b][n][seg][h]
__device__ float d_Qb[2*GRP*NN*DKk];
__device__ float d_Kb[2*GRP*NN*DKk];
__device__ float d_Vb[2*GRP*NN*HID];
__device__ float d_ENC[B_*NN*2*HID];
__device__ float d_Q2[B_*NN*DKk];
__device__ float d_K2[B_*NN*DKk];
__device__ float d_V2[B_*NN*HID];

// ---------------- tf32 helpers ----------------
__device__ __forceinline__ unsigned f2tf32(float x) {
    unsigned r;
    asm("cvt.rna.tf32.f32 %0, %1;" : "=r"(r) : "f"(x));
    return r;
}
__device__ __forceinline__ void mma_tf32(float* c,
        unsigned a0, unsigned a1, unsigned a2, unsigned a3,
        unsigned b0, unsigned b1) {
    asm volatile("mma.sync.aligned.m16n8k8.row.col.f32.tf32.tf32.f32 "
        "{%0,%1,%2,%3}, {%4,%5,%6,%7}, {%8,%9}, {%0,%1,%2,%3};"
        : "+f"(c[0]), "+f"(c[1]), "+f"(c[2]), "+f"(c[3])
        : "r"(a0), "r"(a1), "r"(a2), "r"(a3), "r"(b0), "r"(b1));
}

// ---------------- patch embedding + positional encoding (both streams) ----------------
__global__ __launch_bounds__(256) void patch_kernel(const float* __restrict__ traffic,
                                                    const float* __restrict__ user,
                                                    const float* __restrict__ pw,
                                                    const float* __restrict__ pb,
                                                    float* __restrict__ Z) {
    int blk = blockIdx.x;                // 0..8191
    int s   = blk >> 12;
    int bn  = blk & 4095;
    int b   = bn >> 10, n = bn & 1023;
    const float* x = s ? user : traffic;
    const float* pws = pw + s*HID*SL;
    const float* pbs = pb + s*HID;
    int t   = threadIdx.x;
    int seg = t >> 6, h = t & 63;
    float acc = pbs[h];
#pragma unroll
    for (int l = 0; l < SL; l++)
        acc += pws[h*SL + l] * x[(b*SEQ_ + seg*SL + l)*NN + n];
    int he = h & ~1;
    float dv = expf(-(float)he * (9.210340371976184f / (float)HID));
    float ang = (float)seg * dv;
    acc += (h & 1) ? cosf(ang) : sinf(ang);
    Z[(size_t)(s*TOK + bn*SG + seg)*HID + h] = acc;
}

// ---------------- temporal encoder: MHA + residual + LN1; 64 tokens / block ----------------
#define MHA_SMEM_FLOATS (4352 + 4352 + 12800 + 2048 + 4352)
__global__ __launch_bounds__(256) void mha_kernel(float* __restrict__ Z,
        const float* __restrict__ mw_, const float* __restrict__ mb_,
        const float* __restrict__ ow_, const float* __restrict__ ob_,
        const float* __restrict__ g1_, const float* __restrict__ b1_, int layer) {
    extern __shared__ float sm[];
    float (*xs)[68]  = (float(*)[68])sm;
    float (*wb)[68]  = (float(*)[68])(sm + 4352);
    float (*qkv)[200]= (float(*)[200])(sm + 8704);
    float *ps        = sm + 21504;
    float (*os)[68]  = (float(*)[68])(sm + 23552);

    int tid = threadIdx.x;
    int ty = tid >> 4, tx = tid & 15;
    int s  = blockIdx.x >> 8;                 // 512 blocks, 256 per stream
    int o  = s*LAY + layer;
    const float* mw = mw_ + (size_t)o*192*64;
    const float* mb = mb_ + (size_t)o*192;
    const float* ow = ow_ + (size_t)o*64*64;
    const float* ob = ob_ + (size_t)o*64;
    const float* g1 = g1_ + (size_t)o*64;
    const float* b1 = b1_ + (size_t)o*64;
    size_t t0 = (size_t)blockIdx.x * 64;
    float* zb = Z + t0 * HID;

    for (int idx = tid; idx < 64*16; idx += 256) {
        int r = idx >> 4, c4 = idx & 15;
        *(float4*)&xs[r][4*c4] = *(const float4*)&zb[(size_t)r*64 + 4*c4];
    }

    // ---- QKV = X @ W^T + b ----
    for (int cc = 0; cc < 3; cc++) {
        __syncthreads();
        for (int idx = tid; idx < 64*16; idx += 256) {
            int r = idx >> 4, c4 = idx & 15;
            *(float4*)&wb[r][4*c4] = *(const float4*)&mw[(size_t)(cc*64 + r)*64 + 4*c4];
        }
        __syncthreads();
        float acc[4][4];
#pragma unroll
        for (int j = 0; j < 4; j++) {
            float bv = mb[cc*64 + tx + 16*j];
#pragma unroll
            for (int i = 0; i < 4; i++) acc[i][j] = bv;
        }
#pragma unroll 4
        for (int k = 0; k < 64; k += 4) {
            float4 xv[4], wv[4];
#pragma unroll
            for (int i = 0; i < 4; i++) xv[i] = *(const float4*)&xs[4*ty+i][k];
#pragma unroll
            for (int j = 0; j < 4; j++) wv[j] = *(const float4*)&wb[tx+16*j][k];
#pragma unroll
            for (int i = 0; i < 4; i++)
#pragma unroll
                for (int j = 0; j < 4; j++)
                    acc[i][j] += xv[i].x*wv[j].x + xv[i].y*wv[j].y + xv[i].z*wv[j].z + xv[i].w*wv[j].w;
        }
#pragma unroll
        for (int i = 0; i < 4; i++)
#pragma unroll
            for (int j = 0; j < 4; j++)
                qkv[4*ty+i][cc*64 + tx + 16*j] = acc[i][j];
    }
    __syncthreads();

    // ---- scores + softmax ----
    for (int T = tid; T < 512; T += 256) {
        int g = T >> 5, h = (T >> 2) & 7, i = T & 3;
        const float* q = &qkv[g*4 + i][h*8];
        float sc[4];
#pragma unroll
        for (int j = 0; j < 4; j++) {
            const float* kk = &qkv[g*4 + j][64 + h*8];
            float a = 0.f;
#pragma unroll
            for (int d = 0; d < 8; d++) a += q[d] * kk[d];
            sc[j] = a * 0.3535533905932738f;
        }
        float m = fmaxf(fmaxf(sc[0], sc[1]), fmaxf(sc[2], sc[3]));
        float e0 = __expf(sc[0]-m), e1 = __expf(sc[1]-m), e2 = __expf(sc[2]-m), e3 = __expf(sc[3]-m);
        float inv = 1.f / (e0+e1+e2+e3);
        ps[T*4+0] = e0*inv; ps[T*4+1] = e1*inv; ps[T*4+2] = e2*inv; ps[T*4+3] = e3*inv;
    }
    __syncthreads();

    // ---- O = att @ V ----
#pragma unroll
    for (int i = 0; i < 4; i++) {
        int r = 4*ty + i;
        int g = r >> 2, ii = r & 3;
#pragma unroll
        for (int j = 0; j < 4; j++) {
            int c = tx + 16*j;
            int h = c >> 3;
            const float* a = ps + (((g*8 + h)*4) + ii)*4;
            os[r][c] = a[0]*qkv[g*4+0][128+c] + a[1]*qkv[g*4+1][128+c]
                     + a[2]*qkv[g*4+2][128+c] + a[3]*qkv[g*4+3][128+c];
        }
    }
    __syncthreads();

    // ---- out proj + residual ----
    for (int idx = tid; idx < 64*16; idx += 256) {
        int r = idx >> 4, c4 = idx & 15;
        *(float4*)&wb[r][4*c4] = *(const float4*)&ow[(size_t)r*64 + 4*c4];
    }
    __syncthreads();
    {
        float acc[4][4];
#pragma unroll
        for (int j = 0; j < 4; j++) {
            float bv = ob[tx + 16*j];
#pragma unroll
            for (int i = 0; i < 4; i++) acc[i][j] = bv;
        }
#pragma unroll 4
        for (int k = 0; k < 64; k += 4) {
            float4 xv[4], wv[4];
#pragma unroll
            for (int i = 0; i < 4; i++) xv[i] = *(const float4*)&os[4*ty+i][k];
#pragma unroll
            for (int j = 0; j < 4; j++) wv[j] = *(const float4*)&wb[tx+16*j][k];
#pragma unroll
            for (int i = 0; i < 4; i++)
#pragma unroll
                for (int j = 0; j < 4; j++)
                    acc[i][j] += xv[i].x*wv[j].x + xv[i].y*wv[j].y + xv[i].z*wv[j].z + xv[i].w*wv[j].w;
        }
        __syncthreads();
#pragma unroll
        for (int i = 0; i < 4; i++)
#pragma unroll
            for (int j = 0; j < 4; j++)
                xs[4*ty+i][tx+16*j] += acc[i][j];
    }
    __syncthreads();
    // ---- LN ----
    int w = tid >> 5, lane = tid & 31;
#pragma unroll
    for (int rr = 0; rr < 8; rr++) {
        int r = w*8 + rr;
        float v0 = xs[r][lane], v1 = xs[r][lane+32];
        float ssum = v0 + v1, q = v0*v0 + v1*v1;
#pragma unroll
        for (int off = 16; off; off >>= 1) { ssum += __shfl_xor_sync(0xffffffffu, ssum, off); q += __shfl_xor_sync(0xffffffffu, q, off); }
        float mean = ssum * (1.f/64.f);
        float var  = q * (1.f/64.f) - mean*mean;
        float rstd = rsqrtf(var + 1e-5f);
        zb[(size_t)r*64 + lane]      = (v0 - mean)*rstd*g1[lane]    + b1[lane];
        zb[(size_t)r*64 + lane + 32] = (v1 - mean)*rstd*g1[lane+32] + b1[lane+32];
    }
}

// ---------------- fused FF + residual + LN: tf32 tensor cores, 128 tokens/block ----------------
#define FF_SMEM_FLOATS (8704 + 16896 + 8704 + 8448)
__global__ __launch_bounds__(256) void ff_ln_kernel(float* __restrict__ Z,
        const float* __restrict__ w1_, const float* __restrict__ b1_,
        const float* __restrict__ w2_, const float* __restrict__ b2_,
        const float* __restrict__ g_, const float* __restrict__ bb_, int layer) {
    extern __shared__ float sm[];
    float (*xs)[68]   = (float(*)[68])sm;
    float (*hs)[132]  = (float(*)[132])(sm + 8704);
    float (*w1s)[68]  = (float(*)[68])(sm + 8704 + 16896);
    float (*w2s)[132] = (float(*)[132])(sm + 8704 + 16896 + 8704);

    int tid = threadIdx.x;
    int s   = blockIdx.x >> 7;           // 256 blocks, 128 per stream
    int o   = s*LAY + layer;
    const float* w1 = w1_ + (size_t)o*FFD*64;
    const float* b1 = b1_ + (size_t)o*FFD;
    const float* w2 = w2_ + (size_t)o*64*FFD;
    const float* b2 = b2_ + (size_t)o*64;
    const float* g  = g_  + (size_t)o*64;
    const float* bb = bb_ + (size_t)o*64;
    size_t t0 = (size_t)blockIdx.x * 128;

    int wid  = tid >> 5, lane = tid & 31;
    int lr = lane >> 2, lc = lane & 3;           // fragment row/col
    int wm = wid >> 2, wn = wid & 3;             // warp grid 2 x 4
    int mb = wm*64, nbh = wn*32, nbo = wn*16;

    for (int idx = tid; idx < 128*16; idx += 256) {
        int r = idx >> 4, c4 = idx & 15;
        *(float4*)&xs[r][4*c4] = *(const float4*)&Z[(t0 + r)*64 + 4*c4];
    }

    float oacc[4][2][4];
#pragma unroll
    for (int t = 0; t < 4; t++)
#pragma unroll
        for (int j = 0; j < 2; j++)
#pragma unroll
            for (int q = 0; q < 4; q++) oacc[t][j][q] = 0.f;

    for (int fc = 0; fc < FFD; fc += 128) {
        __syncthreads();
        for (int idx = tid; idx < 128*16; idx += 256) {
            int r = idx >> 4, c4 = idx & 15;
            float4 v = *(const float4*)&w1[(size_t)(fc+r)*64 + 4*c4];
            w1s[r][4*c4+0] = __uint_as_float(f2tf32(v.x));
            w1s[r][4*c4+1] = __uint_as_float(f2tf32(v.y));
            w1s[r][4*c4+2] = __uint_as_float(f2tf32(v.z));
            w1s[r][4*c4+3] = __uint_as_float(f2tf32(v.w));
        }
        for (int idx = tid; idx < 64*32; idx += 256) {
            int r = idx >> 5, c4 = idx & 31;
            float4 v = *(const float4*)&w2[(size_t)r*FFD + fc + 4*c4];
            w2s[r][4*c4+0] = __uint_as_float(f2tf32(v.x));
            w2s[r][4*c4+1] = __uint_as_float(f2tf32(v.y));
            w2s[r][4*c4+2] = __uint_as_float(f2tf32(v.z));
            w2s[r][4*c4+3] = __uint_as_float(f2tf32(v.w));
        }
        __syncthreads();

        // ---- H[128][128] = relu(X @ W1c^T + b1c), tf32 mma ----
        float hacc[4][4][4];
#pragma unroll
        for (int t = 0; t < 4; t++)
#pragma unroll
            for (int j = 0; j < 4; j++)
#pragma unroll
                for (int q = 0; q < 4; q++) hacc[t][j][q] = 0.f;

#pragma unroll
        for (int k0 = 0; k0 < 64; k0 += 8) {
            unsigned a[4][4];
#pragma unroll
            for (int t = 0; t < 4; t++) {
                int r = mb + 16*t + lr;
                a[t][0] = f2tf32(xs[r][k0+lc]);
                a[t][1] = f2tf32(xs[r+8][k0+lc]);
                a[t][2] = f2tf32(xs[r][k0+lc+4]);
                a[t][3] = f2tf32(xs[r+8][k0+lc+4]);
            }
#pragma unroll
            for (int j = 0; j < 4; j++) {
                unsigned b0 = __float_as_uint(w1s[nbh+8*j+lr][k0+lc]);
                unsigned bq = __float_as_uint(w1s[nbh+8*j+lr][k0+lc+4]);
#pragma unroll
                for (int t = 0; t < 4; t++)
                    mma_tf32(hacc[t][j], a[t][0], a[t][1], a[t][2], a[t][3], b0, bq);
            }
        }
#pragma unroll
        for (int j = 0; j < 4; j++) {
            int c = nbh + 8*j + 2*lc;
            float bv0 = b1[fc + c], bv1 = b1[fc + c + 1];
#pragma unroll
            for (int t = 0; t < 4; t++) {
                int r = mb + 16*t + lr;
                hs[r][c]     = __uint_as_float(f2tf32(fmaxf(hacc[t][j][0] + bv0, 0.f)));
                hs[r][c+1]   = __uint_as_float(f2tf32(fmaxf(hacc[t][j][1] + bv1, 0.f)));
                hs[r+8][c]   = __uint_as_float(f2tf32(fmaxf(hacc[t][j][2] + bv0, 0.f)));
                hs[r+8][c+1] = __uint_as_float(f2tf32(fmaxf(hacc[t][j][3] + bv1, 0.f)));
            }
        }
        __syncthreads();

        // ---- O[128][64] += H @ W2c^T, tf32 mma ----
#pragma unroll
        for (int k0 = 0; k0 < 128; k0 += 8) {
            unsigned a[4][4];
#pragma unroll
            for (int t = 0; t < 4; t++) {
                int r = mb + 16*t + lr;
                a[t][0] = __float_as_uint(hs[r][k0+lc]);
                a[t][1] = __float_as_uint(hs[r+8][k0+lc]);
                a[t][2] = __float_as_uint(hs[r][k0+lc+4]);
                a[t][3] = __float_as_uint(hs[r+8][k0+lc+4]);
            }
#pragma unroll
            for (int j = 0; j < 2; j++) {
                unsigned b0 = __float_as_uint(w2s[nbo+8*j+lr][k0+lc]);
                unsigned bq = __float_as_uint(w2s[nbo+8*j+lr][k0+lc+4]);
#pragma unroll
                for (int t = 0; t < 4; t++)
                    mma_tf32(oacc[t][j], a[t][0], a[t][1], a[t][2], a[t][3], b0, bq);
            }
        }
    }
    __syncthreads();
#pragma unroll
    for (int j = 0; j < 2; j++) {
        int c = nbo + 8*j + 2*lc;
        float bv0 = b2[c], bv1 = b2[c+1];
#pragma unroll
        for (int t = 0; t < 4; t++) {
            int r = mb + 16*t + lr;
            xs[r][c]     += oacc[t][j][0] + bv0;
            xs[r][c+1]   += oacc[t][j][1] + bv1;
            xs[r+8][c]   += oacc[t][j][2] + bv0;
            xs[r+8][c+1] += oacc[t][j][3] + bv1;
        }
    }
    __syncthreads();
    int w = tid >> 5, lane2 = tid & 31;
#pragma unroll
    for (int rr = 0; rr < 16; rr++) {
        int r = w*16 + rr;
        float v0 = xs[r][lane2], v1 = xs[r][lane2+32];
        float ssum = v0 + v1, q = v0*v0 + v1*v1;
#pragma unroll
        for (int off = 16; off; off >>= 1) { ssum += __shfl_xor_sync(0xffffffffu, ssum, off); q += __shfl_xor_sync(0xffffffffu, q, off); }
        float mean = ssum * (1.f/64.f);
        float var  = q * (1.f/64.f) - mean*mean;
        float rstd = rsqrtf(var + 1e-5f);
        Z[(t0+r)*64 + lane2]      = (v0 - mean)*rstd*g[lane2]    + bb[lane2];
        Z[(t0+r)*64 + lane2 + 32] = (v1 - mean)*rstd*g[lane2+32] + bb[lane2+32];
    }
}

// ---------------- graph-attention QKV projection: 64 rows/block ----------------
__global__ __launch_bounds__(256) void ga_qkv_kernel(const float* __restrict__ Z,
        const float* __restrict__ wq_, const float* __restrict__ wk_, const float* __restrict__ wv_,
        float* __restrict__ Q, float* __restrict__ K, float* __restrict__ V, int layer) {
    __shared__ float xs[64][68];
    __shared__ float ws[64][68];
    int tid = threadIdx.x;
    int r0 = blockIdx.x * 64;
    int s  = r0 >> 14;
    int o  = s*LAY + layer;
    const float* wq = wq_ + (size_t)o*DKk*64;
    const float* wk = wk_ + (size_t)o*DKk*64;
    const float* wv = wv_ + (size_t)o*64*64;
    int ty = tid >> 4, tx = tid & 15;

    for (int idx = tid; idx < 64*64; idx += 256) {
        int r = idx >> 6, c = idx & 63;
        int gr = r0 + r;
        int q  = gr & 16383;
        int g2 = q >> 10, n = q & 1023;
        int b = g2 >> 2, seg = g2 & 3;
        xs[r][c] = Z[(size_t)(s*TOK + ((b<<10)+n)*SG + seg)*HID + c];
    }
    for (int chunk = 0; chunk < 2; chunk++) {
        __syncthreads();
        for (int idx = tid; idx < 64*64; idx += 256) {
            int r = idx >> 6, c = idx & 63;
            ws[r][c] = (chunk == 0) ? (r < 32 ? wq[r*64 + c] : wk[(r-32)*64 + c])
                                    : wv[r*64 + c];
        }
        __syncthreads();
        float acc[4][4];
#pragma unroll
        for (int i = 0; i < 4; i++)
#pragma unroll
            for (int j = 0; j < 4; j++) acc[i][j] = 0.f;
#pragma unroll 4
        for (int k = 0; k < 64; k += 4) {
            float4 xv[4], wv4[4];
#pragma unroll
            for (int i = 0; i < 4; i++) xv[i] = *(const float4*)&xs[4*ty+i][k];
#pragma unroll
            for (int j = 0; j < 4; j++) wv4[j] = *(const float4*)&ws[tx+16*j][k];
#pragma unroll
            for (int i = 0; i < 4; i++)
#pragma unroll
                for (int j = 0; j < 4; j++)
                    acc[i][j] += xv[i].x*wv4[j].x + xv[i].y*wv4[j].y + xv[i].z*wv4[j].z + xv[i].w*wv4[j].w;
        }
#pragma unroll
        for (int i = 0; i < 4; i++) {
            int gr = r0 + 4*ty + i;
#pragma unroll
            for (int j = 0; j < 4; j++) {
                int c = tx + 16*j;
                if (chunk == 0) {
                    if (c < 32) Q[(size_t)gr*32 + c] = acc[i][j];
                    else        K[(size_t)gr*32 + (c-32)] = acc[i][j];
                } else V[(size_t)gr*64 + c] = acc[i][j];
            }
        }
    }
}

// ---------------- attention: tf32 tensor-core flash attention; dk=32, dv=64, N=1024/group ----------------
// mode 0: plain write to out[(G*NN+q)*64+c]
// mode 1: GA epilogue — Z = LN(att)*g+b + Z  (out = Z base pointer)
// smem layout (floats): ps[64*36] | fct[64] | linv[64] | qs[64*36] | ks[32*36] | vt[64*36]
//                        (os[64*68] for mode1 aliases qs/ks/vt region after mainloop)
__global__ __launch_bounds__(256) void attn_kernel(const float* __restrict__ Q,
        const float* __restrict__ K, const float* __restrict__ V,
        float* __restrict__ out, const float* __restrict__ g_, const float* __restrict__ bb_,
        int layer, int mode, float scale) {
    __shared__ float sm[8192];
    float* ps   = sm;               // [64][36]
    float* fct  = sm + 2304;        // [64]
    float* linv = sm + 2368;        // [64]
    float* qs   = sm + 2432;        // [64][36] tf32
    float* ks   = sm + 4736;        // [32][36] tf32
    float* vt   = sm + 5888;        // [64][36] tf32 (V transposed)
    float* os   = sm + 2432;        // [64][68] (mode1, aliases qs/ks)

    int G  = blockIdx.x;
    int q0 = blockIdx.y * 64;
    int tid = threadIdx.x, wid = tid >> 5, lane = tid & 31;
    int lr = lane >> 2, lc = lane & 3;
    int wm = wid >> 1, wn = wid & 1;
    int mb = wm * 16;
    const float* Qg = Q + (size_t)G*NN*32;
    const float* Kg = K + (size_t)G*NN*32;
    const float* Vg = V + (size_t)G*NN*64;

    // load Q, pre-scaled + tf32
    for (int idx = tid; idx < 64*32; idx += 256) {
        int r = idx >> 5, d = idx & 31;
        qs[r*36 + d] = __uint_as_float(f2tf32(scale * Qg[(size_t)(q0+r)*32 + d]));
    }

    // softmax ownership: thread owns row sr, cols 8*scg..8*scg+7
    int sr = wid*8 + lr, scg = lc;
    float m8 = -1e30f, l8 = 0.f;

    float oacc[4][4];
#pragma unroll
    for (int t = 0; t < 4; t++)
#pragma unroll
        for (int q = 0; q < 4; q++) oacc[t][q] = 0.f;

    for (int kt = 0; kt < NN; kt += 32) {
        __syncthreads();
        for (int idx = tid; idx < 32*32; idx += 256) {
            int k = idx >> 5, d = idx & 31;
            ks[k*36 + d] = __uint_as_float(f2tf32(Kg[(size_t)(kt+k)*32 + d]));
        }
        for (int idx = tid; idx < 32*64; idx += 256) {
            int k = idx >> 6, c = idx & 63;
            vt[c*36 + k] = __uint_as_float(f2tf32(Vg[(size_t)(kt+k)*64 + c]));
        }
        __syncthreads();

        // ---- S = Q @ K^T (64x32), warp grid 4(m) x 2(n) ----
        float sacc[2][4];
#pragma unroll
        for (int t = 0; t < 2; t++)
#pragma unroll
            for (int q = 0; q < 4; q++) sacc[t][q] = 0.f;
#pragma unroll
        for (int k0 = 0; k0 < 32; k0 += 8) {
            unsigned a0 = __float_as_uint(qs[(mb+lr)*36   + k0+lc]);
            unsigned a1 = __float_as_uint(qs[(mb+lr+8)*36 + k0+lc]);
            unsigned a2 = __float_as_uint(qs[(mb+lr)*36   + k0+lc+4]);
            unsigned a3 = __float_as_uint(qs[(mb+lr+8)*36 + k0+lc+4]);
#pragma unroll
            for (int t = 0; t < 2; t++) {
                int n0 = 16*wn + 8*t;
                unsigned b0 = __float_as_uint(ks[(n0+lr)*36 + k0+lc]);
                unsigned b1 = __float_as_uint(ks[(n0+lr)*36 + k0+lc+4]);
                mma_tf32(sacc[t], a0, a1, a2, a3, b0, b1);
            }
        }
#pragma unroll
        for (int t = 0; t < 2; t++) {
            int col = 16*wn + 8*t + 2*lc;
            ps[(mb+lr)*36   + col]     = sacc[t][0];
            ps[(mb+lr)*36   + col + 1] = sacc[t][1];
            ps[(mb+lr+8)*36 + col]     = sacc[t][2];
            ps[(mb+lr+8)*36 + col + 1] = sacc[t][3];
        }
        __syncthreads();

        // ---- online softmax: each thread handles row sr, 8 cols ----
        {
            float4 v0 = *(const float4*)&ps[sr*36 + 8*scg];
            float4 v1 = *(const float4*)&ps[sr*36 + 8*scg + 4];
            float tm = fmaxf(fmaxf(fmaxf(v0.x, v0.y), fmaxf(v0.z, v0.w)),
                             fmaxf(fmaxf(v1.x, v1.y), fmaxf(v1.z, v1.w)));
            tm = fmaxf(tm, __shfl_xor_sync(0xffffffffu, tm, 1));
            tm = fmaxf(tm, __shfl_xor_sync(0xffffffffu, tm, 2));
            float newm = fmaxf(m8, tm);
            float f = __expf(m8 - newm);
            m8 = newm;
            float p0 = __expf(v0.x - newm), p1 = __expf(v0.y - newm);
            float p2 = __expf(v0.z - newm), p3 = __expf(v0.w - newm);
            float p4 = __expf(v1.x - newm), p5 = __expf(v1.y - newm);
            float p6 = __expf(v1.z - newm), p7 = __expf(v1.w - newm);
            float psum = p0+p1+p2+p3+p4+p5+p6+p7;
            psum += __shfl_xor_sync(0xffffffffu, psum, 1);
            psum += __shfl_xor_sync(0xffffffffu, psum, 2);
            l8 = l8 * f + psum;
            float4 w0, w1;
            w0.x = __uint_as_float(f2tf32(p0)); w0.y = __uint_as_float(f2tf32(p1));
            w0.z = __uint_as_float(f2tf32(p2)); w0.w = __uint_as_float(f2tf32(p3));
            w1.x = __uint_as_float(f2tf32(p4)); w1.y = __uint_as_float(f2tf32(p5));
            w1.z = __uint_as_float(f2tf32(p6)); w1.w = __uint_as_float(f2tf32(p7));
            *(float4*)&ps[sr*36 + 8*scg]     = w0;
            *(float4*)&ps[sr*36 + 8*scg + 4] = w1;
            if (scg == 0) fct[sr] = f;
        }
        __syncthreads();

        // ---- O += P @ V (64x64), warp grid 4(m) x 2(n of 32) ----
        {
            float f0 = fct[mb+lr], f1 = fct[mb+lr+8];
#pragma unroll
            for (int t = 0; t < 4; t++) {
                oacc[t][0] *= f0; oacc[t][1] *= f0;
                oacc[t][2] *= f1; oacc[t][3] *= f1;
            }
        }
#pragma unroll
        for (int k0 = 0; k0 < 32; k0 += 8) {
            unsigned a0 = __float_as_uint(ps[(mb+lr)*36   + k0+lc]);
            unsigned a1 = __float_as_uint(ps[(mb+lr+8)*36 + k0+lc]);
            unsigned a2 = __float_as_uint(ps[(mb+lr)*36   + k0+lc+4]);
            unsigned a3 = __float_as_uint(ps[(mb+lr+8)*36 + k0+lc+4]);
#pragma unroll
            for (int t = 0; t < 4; t++) {
                int n0 = 32*wn + 8*t;
                unsigned b0 = __float_as_uint(vt[(n0+lr)*36 + k0+lc]);
                unsigned b1 = __float_as_uint(vt[(n0+lr)*36 + k0+lc+4]);
                mma_tf32(oacc[t], a0, a1, a2, a3, b0, b1);
            }
        }
    }

    if (scg == 0) linv[sr] = 1.f / l8;
    __syncthreads();

    float i0 = linv[mb+lr], i1 = linv[mb+lr+8];
    if (mode == 0) {
#pragma unroll
        for (int t = 0; t < 4; t++) {
            int col = 32*wn + 8*t + 2*lc;
            float* o0 = &out[(size_t)(G*NN + q0 + mb + lr)*64 + col];
            float* o1 = &out[(size_t)(G*NN + q0 + mb + lr + 8)*64 + col];
            o0[0] = oacc[t][0]*i0; o0[1] = oacc[t][1]*i0;
            o1[0] = oacc[t][2]*i1; o1[1] = oacc[t][3]*i1;
        }
    } else {
#pragma unroll
        for (int t = 0; t < 4; t++) {
            int col = 32*wn + 8*t + 2*lc;
            os[(mb+lr)*68 + col]     = oacc[t][0]*i0;
            os[(mb+lr)*68 + col + 1] = oacc[t][1]*i0;
            os[(mb+lr+8)*68 + col]     = oacc[t][2]*i1;
            os[(mb+lr+8)*68 + col + 1] = oacc[t][3]*i1;
        }
        __syncthreads();
        int sIdx = G >> 4, g2 = G & 15;
        int b = g2 >> 2, seg = g2 & 3;
        int o = sIdx*LAY + layer;
        const float* gg = g_  + (size_t)o*64;
        const float* bbp = bb_ + (size_t)o*64;
#pragma unroll
        for (int rr = 0; rr < 8; rr++) {
            int r = wid*8 + rr;
            int n = q0 + r;
            float* zp = out + (size_t)(sIdx*TOK + ((b<<10)+n)*SG + seg)*HID;
            float v0 = os[r*68 + lane], v1 = os[r*68 + lane + 32];
            float ssum = v0 + v1, qq = v0*v0 + v1*v1;
#pragma unroll
            for (int off = 16; off; off >>= 1) {
                ssum += __shfl_xor_sync(0xffffffffu, ssum, off);
                qq   += __shfl_xor_sync(0xffffffffu, qq, off);
            }
            float mean = ssum * (1.f/64.f);
            float var  = qq * (1.f/64.f) - mean*mean;
            float rstd = rsqrtf(var + 1e-5f);
            zp[lane]      = (v0 - mean)*rstd*gg[lane]    + bbp[lane]    + zp[lane];
            zp[lane + 32] = (v1 - mean)*rstd*gg[lane+32] + bbp[lane+32] + zp[lane + 32];
        }
    }
}

// ---------------- mean-pool over segments + concat (both streams) ----------------
__global__ __launch_bounds__(256) void pool_kernel(const float* __restrict__ Z,
        float* __restrict__ ENC) {
    int idx = blockIdx.x * 256 + threadIdx.x;   // over 2*B*NN*64
    int s  = idx >> 18;
    int rem = idx & 262143;
    int bn = rem >> 6, h = rem & 63;
    const float* zp = Z + (size_t)(s*TOK + bn*4)*64;
    float a = 0.25f * (zp[0*64+h] + zp[1*64+h] + zp[2*64+h] + zp[3*64+h]);
    ENC[(size_t)bn*128 + s*64 + h] = a;
}

// ---------------- final cross-attention projections (in dim = 128) ----------------
__global__ __launch_bounds__(256) void fproj_kernel(const float* __restrict__ ENC,
        const float* __restrict__ wq, const float* __restrict__ wk, const float* __restrict__ wv,
        float* __restrict__ Q, float* __restrict__ K, float* __restrict__ V) {
    __shared__ float xs[64][68];
    __shared__ float ws[64][68];
    int tid = threadIdx.x;
    int r0 = blockIdx.x * 64;
    int ty = tid >> 4, tx = tid & 15;
    float acc[2][4][4];
#pragma unroll
    for (int oc = 0; oc < 2; oc++)
#pragma unroll
        for (int i = 0; i < 4; i++)
#pragma unroll
            for (int j = 0; j < 4; j++) acc[oc][i][j] = 0.f;

    for (int kc = 0; kc < 2; kc++) {
        __syncthreads();
        for (int idx = tid; idx < 64*64; idx += 256) {
            int r = idx >> 6, c = idx & 63;
            xs[r][c] = ENC[(size_t)(r0+r)*128 + kc*64 + c];
        }
        for (int oc = 0; oc < 2; oc++) {
            __syncthreads();
            for (int idx = tid; idx < 64*64; idx += 256) {
                int r = idx >> 6, c = idx & 63;
                int gc = oc*64 + r;
                int k  = kc*64 + c;
                ws[r][c] = (gc < 32) ? wq[gc*128 + k] : (gc < 64) ? wk[(gc-32)*128 + k] : wv[(gc-64)*128 + k];
            }
            __syncthreads();
#pragma unroll 4
            for (int k = 0; k < 64; k += 4) {
                float4 xv[4], wv4[4];
#pragma unroll
                for (int i = 0; i < 4; i++) xv[i] = *(const float4*)&xs[4*ty+i][k];
#pragma unroll
                for (int j = 0; j < 4; j++) wv4[j] = *(const float4*)&ws[tx+16*j][k];
#pragma unroll
                for (int i = 0; i < 4; i++)
#pragma unroll
                    for (int j = 0; j < 4; j++)
                        acc[oc][i][j] += xv[i].x*wv4[j].x + xv[i].y*wv4[j].y + xv[i].z*wv4[j].z + xv[i].w*wv4[j].w;
            }
        }
    }
#pragma unroll
    for (int oc = 0; oc < 2; oc++)
#pragma unroll
        for (int i = 0; i < 4; i++) {
            int gr = r0 + 4*ty + i;
#pragma unroll
            for (int j = 0; j < 4; j++) {
                int gc = oc*64 + tx + 16*j;
                float v = acc[oc][i][j];
                if (gc < 32)      Q[(size_t)gr*32 + gc] = v;
                else if (gc < 64) K[(size_t)gr*32 + gc - 32] = v;
                else              V[(size_t)gr*64 + gc - 64] = v;
            }
        }
}

// ---------------- host launcher ----------------
extern "C" void kernel_launch(void* const* d_in, const int* in_sizes, int n_in,
                              void* d_out, int out_size) {
    const float* traffic  = (const float*)d_in[0];
    const float* user     = (const float*)d_in[1];
    const float* patch_w  = (const float*)d_in[2];
    const float* patch_b  = (const float*)d_in[3];
    const float* mha_w    = (const float*)d_in[4];
    const float* mha_b    = (const float*)d_in[5];
    const float* out_w    = (const float*)d_in[6];
    const float* out_b    = (const float*)d_in[7];
    const float* ff1_w    = (const float*)d_in[8];
    const float* ff1_b    = (const float*)d_in[9];
    const float* ff2_w    = (const float*)d_in[10];
    const float* ff2_b    = (const float*)d_in[11];
    const float* ln1_g    = (const float*)d_in[12];
    const float* ln1_b    = (const float*)d_in[13];
    const float* ln2_g    = (const float*)d_in[14];
    const float* ln2_b    = (const float*)d_in[15];
    const float* ga_wq    = (const float*)d_in[16];
    const float* ga_wk    = (const float*)d_in[17];
    const float* ga_wv    = (const float*)d_in[18];
    const float* ga_ff1_w = (const float*)d_in[19];
    const float* ga_ff1_b = (const float*)d_in[20];
    const float* ga_ff2_w = (const float*)d_in[21];
    const float* ga_ff2_b = (const float*)d_in[22];
    const float* ga_ln1_g = (const float*)d_in[23];
    const float* ga_ln1_b = (const float*)d_in[24];
    const float* ga_ln2_g = (const float*)d_in[25];
    const float* ga_ln2_b = (const float*)d_in[26];
    const float* ca_wq    = (const float*)d_in[27];
    const float* ca_wk    = (const float*)d_in[28];
    const float* ca_wv    = (const float*)d_in[29];

    float *Z, *Qb, *Kb, *Vb, *ENC, *Q2, *K2, *V2;
    cudaGetSymbolAddress((void**)&Z,   d_Z);
    cudaGetSymbolAddress((void**)&Qb,  d_Qb);
    cudaGetSymbolAddress((void**)&Kb,  d_Kb);
    cudaGetSymbolAddress((void**)&Vb,  d_Vb);
    cudaGetSymbolAddress((void**)&ENC, d_ENC);
    cudaGetSymbolAddress((void**)&Q2,  d_Q2);
    cudaGetSymbolAddress((void**)&K2,  d_K2);
    cudaGetSymbolAddress((void**)&V2,  d_V2);

    const int MHA_SMEM = MHA_SMEM_FLOATS * 4;   // 111,616 B
    const int FF_SMEM  = FF_SMEM_FLOATS * 4;    // 171,008 B
    cudaFuncSetAttribute(mha_kernel,   cudaFuncAttributeMaxDynamicSharedMemorySize, MHA_SMEM);
    cudaFuncSetAttribute(ff_ln_kernel, cudaFuncAttributeMaxDynamicSharedMemorySize, FF_SMEM);

    const float SCALE32 = 0.17677669529663687f;   // 1/sqrt(32)

    patch_kernel<<<2*B_*NN, 256>>>(traffic, user, patch_w, patch_b, Z);
    for (int i = 0; i < LAY; i++) {
        mha_kernel<<<2*TOK/64, 256, MHA_SMEM>>>(Z, mha_w, mha_b, out_w, out_b, ln1_g, ln1_b, i);
        ff_ln_kernel<<<2*TOK/128, 256, FF_SMEM>>>(Z, ff1_w, ff1_b, ff2_w, ff2_b, ln2_g, ln2_b, i);
        ga_qkv_kernel<<<2*TOK/64, 256>>>(Z, ga_wq, ga_wk, ga_wv, Qb, Kb, Vb, i);
        attn_kernel<<<dim3(2*GRP, NN/64), 256>>>(Qb, Kb, Vb, Z, ga_ln1_g, ga_ln1_b, i, 1, SCALE32);
        ff_ln_kernel<<<2*TOK/128, 256, FF_SMEM>>>(Z, ga_ff1_w, ga_ff1_b, ga_ff2_w, ga_ff2_b, ga_ln2_g, ga_ln2_b, i);
    }
    pool_kernel<<<2*B_*NN*HID/256, 256>>>(Z, ENC);
    fproj_kernel<<<B_*NN/64, 256>>>(ENC, ca_wq, ca_wk, ca_wv, Q2, K2, V2);
    attn_kernel<<<dim3(B_, NN/64), 256>>>(Q2, K2, V2, (float*)d_out, (const float*)0, (const float*)0, 0, 0, SCALE32);
}

// round 10
// speedup vs baseline: 8.6960x; 1.0524x over previous
#include <cuda_runtime.h>
#include <math.h>

#define B_   4
#define SEQ_ 12
#define NN   1024
#define SL   3
#define SG   4
#define HID  64
#define FFD  2048
#define DKk  32
#define LAY  2
#define TOK  (B_*NN*SG)   /* 16384 per stream */
#define GRP  (B_*SG)      /* 16 per stream */

// ---------------- scratch (static device memory) ----------------
__device__ float d_Z[2*TOK*HID];          // [s][b][n][seg][h]
__device__ float d_Qb[2*GRP*NN*DKk];
__device__ float d_Kb[2*GRP*NN*DKk];
__device__ float d_Vb[2*GRP*NN*HID];
__device__ float d_ENC[B_*NN*2*HID];
__device__ float d_Q2[B_*NN*DKk];
__device__ float d_K2[B_*NN*DKk];
__device__ float d_V2[B_*NN*HID];

// ---------------- tf32 helpers ----------------
__device__ __forceinline__ unsigned f2tf32(float x) {
    unsigned r;
    asm("cvt.rna.tf32.f32 %0, %1;" : "=r"(r) : "f"(x));
    return r;
}
__device__ __forceinline__ void mma_tf32(float* c,
        unsigned a0, unsigned a1, unsigned a2, unsigned a3,
        unsigned b0, unsigned b1) {
    asm volatile("mma.sync.aligned.m16n8k8.row.col.f32.tf32.tf32.f32 "
        "{%0,%1,%2,%3}, {%4,%5,%6,%7}, {%8,%9}, {%0,%1,%2,%3};"
        : "+f"(c[0]), "+f"(c[1]), "+f"(c[2]), "+f"(c[3])
        : "r"(a0), "r"(a1), "r"(a2), "r"(a3), "r"(b0), "r"(b1));
}

// ---------------- patch embedding + positional encoding (both streams) ----------------
__global__ __launch_bounds__(256) void patch_kernel(const float* __restrict__ traffic,
                                                    const float* __restrict__ user,
                                                    const float* __restrict__ pw,
                                                    const float* __restrict__ pb,
                                                    float* __restrict__ Z) {
    int blk = blockIdx.x;                // 0..8191
    int s   = blk >> 12;
    int bn  = blk & 4095;
    int b   = bn >> 10, n = bn & 1023;
    const float* x = s ? user : traffic;
    const float* pws = pw + s*HID*SL;
    const float* pbs = pb + s*HID;
    int t   = threadIdx.x;
    int seg = t >> 6, h = t & 63;
    float acc = pbs[h];
#pragma unroll
    for (int l = 0; l < SL; l++)
        acc += pws[h*SL + l] * x[(b*SEQ_ + seg*SL + l)*NN + n];
    int he = h & ~1;
    float dv = expf(-(float)he * (9.210340371976184f / (float)HID));
    float ang = (float)seg * dv;
    acc += (h & 1) ? cosf(ang) : sinf(ang);
    Z[(size_t)(s*TOK + bn*SG + seg)*HID + h] = acc;
}

// ---------------- temporal encoder: MHA + residual + LN1; 64 tokens / block ----------------
// GEMMs (QKV, out-proj) on tf32 tensor cores; 4x4 attention core scalar.
#define MHA_SMEM_FLOATS (4352 + 4352 + 12800 + 2048 + 4352)
__global__ __launch_bounds__(256) void mha_kernel(float* __restrict__ Z,
        const float* __restrict__ mw_, const float* __restrict__ mb_,
        const float* __restrict__ ow_, const float* __restrict__ ob_,
        const float* __restrict__ g1_, const float* __restrict__ b1_, int layer) {
    extern __shared__ float sm[];
    float (*xs)[68]  = (float(*)[68])sm;
    float (*wb)[68]  = (float(*)[68])(sm + 4352);
    float (*qkv)[200]= (float(*)[200])(sm + 8704);
    float *ps        = sm + 21504;
    float (*os)[68]  = (float(*)[68])(sm + 23552);

    int tid = threadIdx.x;
    int s  = blockIdx.x >> 8;                 // 512 blocks, 256 per stream
    int o  = s*LAY + layer;
    const float* mw = mw_ + (size_t)o*192*64;
    const float* mb = mb_ + (size_t)o*192;
    const float* ow = ow_ + (size_t)o*64*64;
    const float* ob = ob_ + (size_t)o*64;
    const float* g1 = g1_ + (size_t)o*64;
    const float* b1 = b1_ + (size_t)o*64;
    size_t t0 = (size_t)blockIdx.x * 64;
    float* zb = Z + t0 * HID;

    int wid = tid >> 5, lane = tid & 31;
    int lr = lane >> 2, lc = lane & 3;
    int wm = wid >> 2, wn = wid & 3;          // warp grid 2(m) x 4(n)
    int mb2 = wm*32, nb = wn*16;

    for (int idx = tid; idx < 64*16; idx += 256) {
        int r = idx >> 4, c4 = idx & 15;
        *(float4*)&xs[r][4*c4] = *(const float4*)&zb[(size_t)r*64 + 4*c4];
    }

    // ---- QKV = X @ W^T + b  (3 chunks of 64 cols), tf32 mma ----
    for (int cc = 0; cc < 3; cc++) {
        __syncthreads();
        for (int idx = tid; idx < 64*16; idx += 256) {
            int r = idx >> 4, c4 = idx & 15;
            float4 v = *(const float4*)&mw[(size_t)(cc*64 + r)*64 + 4*c4];
            wb[r][4*c4+0] = __uint_as_float(f2tf32(v.x));
            wb[r][4*c4+1] = __uint_as_float(f2tf32(v.y));
            wb[r][4*c4+2] = __uint_as_float(f2tf32(v.z));
            wb[r][4*c4+3] = __uint_as_float(f2tf32(v.w));
        }
        __syncthreads();
        float acc[2][2][4];
#pragma unroll
        for (int j = 0; j < 2; j++) {
            int c = nb + 8*j + 2*lc;
            float bv0 = mb[cc*64 + c], bv1 = mb[cc*64 + c + 1];
#pragma unroll
            for (int t = 0; t < 2; t++) {
                acc[t][j][0] = bv0; acc[t][j][1] = bv1;
                acc[t][j][2] = bv0; acc[t][j][3] = bv1;
            }
        }
#pragma unroll
        for (int k0 = 0; k0 < 64; k0 += 8) {
            unsigned a[2][4];
#pragma unroll
            for (int t = 0; t < 2; t++) {
                int r = mb2 + 16*t + lr;
                a[t][0] = f2tf32(xs[r][k0+lc]);
                a[t][1] = f2tf32(xs[r+8][k0+lc]);
                a[t][2] = f2tf32(xs[r][k0+lc+4]);
                a[t][3] = f2tf32(xs[r+8][k0+lc+4]);
            }
#pragma unroll
            for (int j = 0; j < 2; j++) {
                unsigned b0 = __float_as_uint(wb[nb+8*j+lr][k0+lc]);
                unsigned bq = __float_as_uint(wb[nb+8*j+lr][k0+lc+4]);
#pragma unroll
                for (int t = 0; t < 2; t++)
                    mma_tf32(acc[t][j], a[t][0], a[t][1], a[t][2], a[t][3], b0, bq);
            }
        }
#pragma unroll
        for (int t = 0; t < 2; t++)
#pragma unroll
            for (int j = 0; j < 2; j++) {
                int r = mb2 + 16*t + lr, c = cc*64 + nb + 8*j + 2*lc;
                qkv[r][c]     = acc[t][j][0];
                qkv[r][c+1]   = acc[t][j][1];
                qkv[r+8][c]   = acc[t][j][2];
                qkv[r+8][c+1] = acc[t][j][3];
            }
    }
    __syncthreads();

    // ---- scores + softmax (scalar; tiny) ----
    for (int T = tid; T < 512; T += 256) {
        int g = T >> 5, h = (T >> 2) & 7, i = T & 3;
        const float* q = &qkv[g*4 + i][h*8];
        float sc[4];
#pragma unroll
        for (int j = 0; j < 4; j++) {
            const float* kk = &qkv[g*4 + j][64 + h*8];
            float a = 0.f;
#pragma unroll
            for (int d = 0; d < 8; d++) a += q[d] * kk[d];
            sc[j] = a * 0.3535533905932738f;
        }
        float m = fmaxf(fmaxf(sc[0], sc[1]), fmaxf(sc[2], sc[3]));
        float e0 = __expf(sc[0]-m), e1 = __expf(sc[1]-m), e2 = __expf(sc[2]-m), e3 = __expf(sc[3]-m);
        float inv = 1.f / (e0+e1+e2+e3);
        ps[T*4+0] = e0*inv; ps[T*4+1] = e1*inv; ps[T*4+2] = e2*inv; ps[T*4+3] = e3*inv;
    }
    __syncthreads();

    // ---- O = att @ V (scalar; tiny) ----
    {
        int ty = tid >> 4, tx = tid & 15;
#pragma unroll
        for (int i = 0; i < 4; i++) {
            int r = 4*ty + i;
            int g = r >> 2, ii = r & 3;
#pragma unroll
            for (int j = 0; j < 4; j++) {
                int c = tx + 16*j;
                int h = c >> 3;
                const float* a = ps + (((g*8 + h)*4) + ii)*4;
                os[r][c] = a[0]*qkv[g*4+0][128+c] + a[1]*qkv[g*4+1][128+c]
                         + a[2]*qkv[g*4+2][128+c] + a[3]*qkv[g*4+3][128+c];
            }
        }
    }
    __syncthreads();

    // ---- out proj + residual, tf32 mma ----
    for (int idx = tid; idx < 64*16; idx += 256) {
        int r = idx >> 4, c4 = idx & 15;
        float4 v = *(const float4*)&ow[(size_t)r*64 + 4*c4];
        wb[r][4*c4+0] = __uint_as_float(f2tf32(v.x));
        wb[r][4*c4+1] = __uint_as_float(f2tf32(v.y));
        wb[r][4*c4+2] = __uint_as_float(f2tf32(v.z));
        wb[r][4*c4+3] = __uint_as_float(f2tf32(v.w));
    }
    __syncthreads();
    {
        float acc[2][2][4];
#pragma unroll
        for (int j = 0; j < 2; j++) {
            int c = nb + 8*j + 2*lc;
            float bv0 = ob[c], bv1 = ob[c+1];
#pragma unroll
            for (int t = 0; t < 2; t++) {
                acc[t][j][0] = bv0; acc[t][j][1] = bv1;
                acc[t][j][2] = bv0; acc[t][j][3] = bv1;
            }
        }
#pragma unroll
        for (int k0 = 0; k0 < 64; k0 += 8) {
            unsigned a[2][4];
#pragma unroll
            for (int t = 0; t < 2; t++) {
                int r = mb2 + 16*t + lr;
                a[t][0] = f2tf32(os[r][k0+lc]);
                a[t][1] = f2tf32(os[r+8][k0+lc]);
                a[t][2] = f2tf32(os[r][k0+lc+4]);
                a[t][3] = f2tf32(os[r+8][k0+lc+4]);
            }
#pragma unroll
            for (int j = 0; j < 2; j++) {
                unsigned b0 = __float_as_uint(wb[nb+8*j+lr][k0+lc]);
                unsigned bq = __float_as_uint(wb[nb+8*j+lr][k0+lc+4]);
#pragma unroll
                for (int t = 0; t < 2; t++)
                    mma_tf32(acc[t][j], a[t][0], a[t][1], a[t][2], a[t][3], b0, bq);
            }
        }
        __syncthreads();
#pragma unroll
        for (int t = 0; t < 2; t++)
#pragma unroll
            for (int j = 0; j < 2; j++) {
                int r = mb2 + 16*t + lr, c = nb + 8*j + 2*lc;
                xs[r][c]     += acc[t][j][0];
                xs[r][c+1]   += acc[t][j][1];
                xs[r+8][c]   += acc[t][j][2];
                xs[r+8][c+1] += acc[t][j][3];
            }
    }
    __syncthreads();
    // ---- LN ----
    int w = tid >> 5, lane2 = tid & 31;
#pragma unroll
    for (int rr = 0; rr < 8; rr++) {
        int r = w*8 + rr;
        float v0 = xs[r][lane2], v1 = xs[r][lane2+32];
        float ssum = v0 + v1, q = v0*v0 + v1*v1;
#pragma unroll
        for (int off = 16; off; off >>= 1) { ssum += __shfl_xor_sync(0xffffffffu, ssum, off); q += __shfl_xor_sync(0xffffffffu, q, off); }
        float mean = ssum * (1.f/64.f);
        float var  = q * (1.f/64.f) - mean*mean;
        float rstd = rsqrtf(var + 1e-5f);
        zb[(size_t)r*64 + lane2]      = (v0 - mean)*rstd*g1[lane2]    + b1[lane2];
        zb[(size_t)r*64 + lane2 + 32] = (v1 - mean)*rstd*g1[lane2+32] + b1[lane2+32];
    }
}

// ---------------- fused FF + residual + LN: tf32 tensor cores, 128 tokens/block ----------------
#define FF_SMEM_FLOATS (8704 + 16896 + 8704 + 8448)
__global__ __launch_bounds__(256) void ff_ln_kernel(float* __restrict__ Z,
        const float* __restrict__ w1_, const float* __restrict__ b1_,
        const float* __restrict__ w2_, const float* __restrict__ b2_,
        const float* __restrict__ g_, const float* __restrict__ bb_, int layer) {
    extern __shared__ float sm[];
    float (*xs)[68]   = (float(*)[68])sm;
    float (*hs)[132]  = (float(*)[132])(sm + 8704);
    float (*w1s)[68]  = (float(*)[68])(sm + 8704 + 16896);
    float (*w2s)[132] = (float(*)[132])(sm + 8704 + 16896 + 8704);

    int tid = threadIdx.x;
    int s   = blockIdx.x >> 7;           // 256 blocks, 128 per stream
    int o   = s*LAY + layer;
    const float* w1 = w1_ + (size_t)o*FFD*64;
    const float* b1 = b1_ + (size_t)o*FFD;
    const float* w2 = w2_ + (size_t)o*64*FFD;
    const float* b2 = b2_ + (size_t)o*64;
    const float* g  = g_  + (size_t)o*64;
    const float* bb = bb_ + (size_t)o*64;
    size_t t0 = (size_t)blockIdx.x * 128;

    int wid  = tid >> 5, lane = tid & 31;
    int lr = lane >> 2, lc = lane & 3;           // fragment row/col
    int wm = wid >> 2, wn = wid & 3;             // warp grid 2 x 4
    int mb = wm*64, nbh = wn*32, nbo = wn*16;

    for (int idx = tid; idx < 128*16; idx += 256) {
        int r = idx >> 4, c4 = idx & 15;
        *(float4*)&xs[r][4*c4] = *(const float4*)&Z[(t0 + r)*64 + 4*c4];
    }

    float oacc[4][2][4];
#pragma unroll
    for (int t = 0; t < 4; t++)
#pragma unroll
        for (int j = 0; j < 2; j++)
#pragma unroll
            for (int q = 0; q < 4; q++) oacc[t][j][q] = 0.f;

    for (int fc = 0; fc < FFD; fc += 128) {
        __syncthreads();
        for (int idx = tid; idx < 128*16; idx += 256) {
            int r = idx >> 4, c4 = idx & 15;
            float4 v = *(const float4*)&w1[(size_t)(fc+r)*64 + 4*c4];
            w1s[r][4*c4+0] = __uint_as_float(f2tf32(v.x));
            w1s[r][4*c4+1] = __uint_as_float(f2tf32(v.y));
            w1s[r][4*c4+2] = __uint_as_float(f2tf32(v.z));
            w1s[r][4*c4+3] = __uint_as_float(f2tf32(v.w));
        }
        for (int idx = tid; idx < 64*32; idx += 256) {
            int r = idx >> 5, c4 = idx & 31;
            float4 v = *(const float4*)&w2[(size_t)r*FFD + fc + 4*c4];
            w2s[r][4*c4+0] = __uint_as_float(f2tf32(v.x));
            w2s[r][4*c4+1] = __uint_as_float(f2tf32(v.y));
            w2s[r][4*c4+2] = __uint_as_float(f2tf32(v.z));
            w2s[r][4*c4+3] = __uint_as_float(f2tf32(v.w));
        }
        __syncthreads();

        // ---- H[128][128] = relu(X @ W1c^T + b1c), tf32 mma ----
        float hacc[4][4][4];
#pragma unroll
        for (int t = 0; t < 4; t++)
#pragma unroll
            for (int j = 0; j < 4; j++)
#pragma unroll
                for (int q = 0; q < 4; q++) hacc[t][j][q] = 0.f;

#pragma unroll
        for (int k0 = 0; k0 < 64; k0 += 8) {
            unsigned a[4][4];
#pragma unroll
            for (int t = 0; t < 4; t++) {
                int r = mb + 16*t + lr;
                a[t][0] = f2tf32(xs[r][k0+lc]);
                a[t][1] = f2tf32(xs[r+8][k0+lc]);
                a[t][2] = f2tf32(xs[r][k0+lc+4]);
                a[t][3] = f2tf32(xs[r+8][k0+lc+4]);
            }
#pragma unroll
            for (int j = 0; j < 4; j++) {
                unsigned b0 = __float_as_uint(w1s[nbh+8*j+lr][k0+lc]);
                unsigned bq = __float_as_uint(w1s[nbh+8*j+lr][k0+lc+4]);
#pragma unroll
                for (int t = 0; t < 4; t++)
                    mma_tf32(hacc[t][j], a[t][0], a[t][1], a[t][2], a[t][3], b0, bq);
            }
        }
#pragma unroll
        for (int j = 0; j < 4; j++) {
            int c = nbh + 8*j + 2*lc;
            float bv0 = b1[fc + c], bv1 = b1[fc + c + 1];
#pragma unroll
            for (int t = 0; t < 4; t++) {
                int r = mb + 16*t + lr;
                hs[r][c]     = __uint_as_float(f2tf32(fmaxf(hacc[t][j][0] + bv0, 0.f)));
                hs[r][c+1]   = __uint_as_float(f2tf32(fmaxf(hacc[t][j][1] + bv1, 0.f)));
                hs[r+8][c]   = __uint_as_float(f2tf32(fmaxf(hacc[t][j][2] + bv0, 0.f)));
                hs[r+8][c+1] = __uint_as_float(f2tf32(fmaxf(hacc[t][j][3] + bv1, 0.f)));
            }
        }
        __syncthreads();

        // ---- O[128][64] += H @ W2c^T, tf32 mma ----
#pragma unroll
        for (int k0 = 0; k0 < 128; k0 += 8) {
            unsigned a[4][4];
#pragma unroll
            for (int t = 0; t < 4; t++) {
                int r = mb + 16*t + lr;
                a[t][0] = __float_as_uint(hs[r][k0+lc]);
                a[t][1] = __float_as_uint(hs[r+8][k0+lc]);
                a[t][2] = __float_as_uint(hs[r][k0+lc+4]);
                a[t][3] = __float_as_uint(hs[r+8][k0+lc+4]);
            }
#pragma unroll
            for (int j = 0; j < 2; j++) {
                unsigned b0 = __float_as_uint(w2s[nbo+8*j+lr][k0+lc]);
                unsigned bq = __float_as_uint(w2s[nbo+8*j+lr][k0+lc+4]);
#pragma unroll
                for (int t = 0; t < 4; t++)
                    mma_tf32(oacc[t][j], a[t][0], a[t][1], a[t][2], a[t][3], b0, bq);
            }
        }
    }
    __syncthreads();
#pragma unroll
    for (int j = 0; j < 2; j++) {
        int c = nbo + 8*j + 2*lc;
        float bv0 = b2[c], bv1 = b2[c+1];
#pragma unroll
        for (int t = 0; t < 4; t++) {
            int r = mb + 16*t + lr;
            xs[r][c]     += oacc[t][j][0] + bv0;
            xs[r][c+1]   += oacc[t][j][1] + bv1;
            xs[r+8][c]   += oacc[t][j][2] + bv0;
            xs[r+8][c+1] += oacc[t][j][3] + bv1;
        }
    }
    __syncthreads();
    int w = tid >> 5, lane2 = tid & 31;
#pragma unroll
    for (int rr = 0; rr < 16; rr++) {
        int r = w*16 + rr;
        float v0 = xs[r][lane2], v1 = xs[r][lane2+32];
        float ssum = v0 + v1, q = v0*v0 + v1*v1;
#pragma unroll
        for (int off = 16; off; off >>= 1) { ssum += __shfl_xor_sync(0xffffffffu, ssum, off); q += __shfl_xor_sync(0xffffffffu, q, off); }
        float mean = ssum * (1.f/64.f);
        float var  = q * (1.f/64.f) - mean*mean;
        float rstd = rsqrtf(var + 1e-5f);
        Z[(t0+r)*64 + lane2]      = (v0 - mean)*rstd*g[lane2]    + bb[lane2];
        Z[(t0+r)*64 + lane2 + 32] = (v1 - mean)*rstd*g[lane2+32] + bb[lane2+32];
    }
}

// ---------------- graph-attention QKV projection: tf32 mma, 64 rows/block ----------------
__global__ __launch_bounds__(256) void ga_qkv_kernel(const float* __restrict__ Z,
        const float* __restrict__ wq_, const float* __restrict__ wk_, const float* __restrict__ wv_,
        float* __restrict__ Q, float* __restrict__ K, float* __restrict__ V, int layer) {
    __shared__ float xs[64][68];   // tf32
    __shared__ float ws[64][68];   // tf32
    int tid = threadIdx.x;
    int r0 = blockIdx.x * 64;
    int s  = r0 >> 14;
    int o  = s*LAY + layer;
    const float* wq = wq_ + (size_t)o*DKk*64;
    const float* wk = wk_ + (size_t)o*DKk*64;
    const float* wv = wv_ + (size_t)o*64*64;

    int wid = tid >> 5, lane = tid & 31;
    int lr = lane >> 2, lc = lane & 3;
    int wm = wid >> 2, wn = wid & 3;          // 2(m) x 4(n)
    int mb = wm*32, nb = wn*16;

    for (int idx = tid; idx < 64*64; idx += 256) {
        int r = idx >> 6, c = idx & 63;
        int gr = r0 + r;
        int q  = gr & 16383;
        int g2 = q >> 10, n = q & 1023;
        int b = g2 >> 2, seg = g2 & 3;
        xs[r][c] = __uint_as_float(f2tf32(Z[(size_t)(s*TOK + ((b<<10)+n)*SG + seg)*HID + c]));
    }
    for (int chunk = 0; chunk < 2; chunk++) {
        __syncthreads();
        for (int idx = tid; idx < 64*64; idx += 256) {
            int r = idx >> 6, c = idx & 63;
            float v = (chunk == 0) ? (r < 32 ? wq[r*64 + c] : wk[(r-32)*64 + c]) : wv[r*64 + c];
            ws[r][c] = __uint_as_float(f2tf32(v));
        }
        __syncthreads();
        float acc[2][2][4];
#pragma unroll
        for (int t = 0; t < 2; t++)
#pragma unroll
            for (int j = 0; j < 2; j++)
#pragma unroll
                for (int q = 0; q < 4; q++) acc[t][j][q] = 0.f;
#pragma unroll
        for (int k0 = 0; k0 < 64; k0 += 8) {
            unsigned a[2][4];
#pragma unroll
            for (int t = 0; t < 2; t++) {
                int r = mb + 16*t + lr;
                a[t][0] = __float_as_uint(xs[r][k0+lc]);
                a[t][1] = __float_as_uint(xs[r+8][k0+lc]);
                a[t][2] = __float_as_uint(xs[r][k0+lc+4]);
                a[t][3] = __float_as_uint(xs[r+8][k0+lc+4]);
            }
#pragma unroll
            for (int j = 0; j < 2; j++) {
                unsigned b0 = __float_as_uint(ws[nb+8*j+lr][k0+lc]);
                unsigned bq = __float_as_uint(ws[nb+8*j+lr][k0+lc+4]);
#pragma unroll
                for (int t = 0; t < 2; t++)
                    mma_tf32(acc[t][j], a[t][0], a[t][1], a[t][2], a[t][3], b0, bq);
            }
        }
#pragma unroll
        for (int t = 0; t < 2; t++)
#pragma unroll
            for (int j = 0; j < 2; j++) {
                int c = nb + 8*j + 2*lc;
                int gr0 = r0 + mb + 16*t + lr;
#pragma unroll
                for (int half = 0; half < 2; half++) {
                    int gr = gr0 + 8*half;
                    float v0 = acc[t][j][2*half], v1 = acc[t][j][2*half+1];
                    if (chunk == 0) {
                        if (c < 32) { Q[(size_t)gr*32 + c] = v0;      Q[(size_t)gr*32 + c + 1] = v1; }
                        else        { K[(size_t)gr*32 + c - 32] = v0; K[(size_t)gr*32 + c - 31] = v1; }
                    } else        { V[(size_t)gr*64 + c] = v0;      V[(size_t)gr*64 + c + 1] = v1; }
                }
            }
    }
}

// ---------------- attention: tf32 tensor-core flash attention; dk=32, dv=64, N=1024/group ----------------
// mode 0: plain write to out[(G*NN+q)*64+c] ; mode 1: GA epilogue — Z = LN(att)*g+b + Z
__global__ __launch_bounds__(256) void attn_kernel(const float* __restrict__ Q,
        const float* __restrict__ K, const float* __restrict__ V,
        float* __restrict__ out, const float* __restrict__ g_, const float* __restrict__ bb_,
        int layer, int mode, float scale) {
    __shared__ float sm[8192];
    float* ps   = sm;               // [64][36]
    float* fct  = sm + 2304;        // [64]
    float* linv = sm + 2368;        // [64]
    float* qs   = sm + 2432;        // [64][36] tf32
    float* ks   = sm + 4736;        // [32][36] tf32
    float* vt   = sm + 5888;        // [64][36] tf32 (V transposed)
    float* os   = sm + 2432;        // [64][68] (mode1, aliases qs/ks)

    int G  = blockIdx.x;
    int q0 = blockIdx.y * 64;
    int tid = threadIdx.x, wid = tid >> 5, lane = tid & 31;
    int lr = lane >> 2, lc = lane & 3;
    int wm = wid >> 1, wn = wid & 1;
    int mb = wm * 16;
    const float* Qg = Q + (size_t)G*NN*32;
    const float* Kg = K + (size_t)G*NN*32;
    const float* Vg = V + (size_t)G*NN*64;

    for (int idx = tid; idx < 64*32; idx += 256) {
        int r = idx >> 5, d = idx & 31;
        qs[r*36 + d] = __uint_as_float(f2tf32(scale * Qg[(size_t)(q0+r)*32 + d]));
    }

    int sr = wid*8 + lr, scg = lc;
    float m8 = -1e30f, l8 = 0.f;

    float oacc[4][4];
#pragma unroll
    for (int t = 0; t < 4; t++)
#pragma unroll
        for (int q = 0; q < 4; q++) oacc[t][q] = 0.f;

    for (int kt = 0; kt < NN; kt += 32) {
        __syncthreads();
        for (int idx = tid; idx < 32*32; idx += 256) {
            int k = idx >> 5, d = idx & 31;
            ks[k*36 + d] = __uint_as_float(f2tf32(Kg[(size_t)(kt+k)*32 + d]));
        }
        for (int idx = tid; idx < 32*64; idx += 256) {
            int k = idx >> 6, c = idx & 63;
            vt[c*36 + k] = __uint_as_float(f2tf32(Vg[(size_t)(kt+k)*64 + c]));
        }
        __syncthreads();

        float sacc[2][4];
#pragma unroll
        for (int t = 0; t < 2; t++)
#pragma unroll
            for (int q = 0; q < 4; q++) sacc[t][q] = 0.f;
#pragma unroll
        for (int k0 = 0; k0 < 32; k0 += 8) {
            unsigned a0 = __float_as_uint(qs[(mb+lr)*36   + k0+lc]);
            unsigned a1 = __float_as_uint(qs[(mb+lr+8)*36 + k0+lc]);
            unsigned a2 = __float_as_uint(qs[(mb+lr)*36   + k0+lc+4]);
            unsigned a3 = __float_as_uint(qs[(mb+lr+8)*36 + k0+lc+4]);
#pragma unroll
            for (int t = 0; t < 2; t++) {
                int n0 = 16*wn + 8*t;
                unsigned b0 = __float_as_uint(ks[(n0+lr)*36 + k0+lc]);
                unsigned b1 = __float_as_uint(ks[(n0+lr)*36 + k0+lc+4]);
                mma_tf32(sacc[t], a0, a1, a2, a3, b0, b1);
            }
        }
#pragma unroll
        for (int t = 0; t < 2; t++) {
            int col = 16*wn + 8*t + 2*lc;
            ps[(mb+lr)*36   + col]     = sacc[t][0];
            ps[(mb+lr)*36   + col + 1] = sacc[t][1];
            ps[(mb+lr+8)*36 + col]     = sacc[t][2];
            ps[(mb+lr+8)*36 + col + 1] = sacc[t][3];
        }
        __syncthreads();

        {
            float4 v0 = *(const float4*)&ps[sr*36 + 8*scg];
            float4 v1 = *(const float4*)&ps[sr*36 + 8*scg + 4];
            float tm = fmaxf(fmaxf(fmaxf(v0.x, v0.y), fmaxf(v0.z, v0.w)),
                             fmaxf(fmaxf(v1.x, v1.y), fmaxf(v1.z, v1.w)));
            tm = fmaxf(tm, __shfl_xor_sync(0xffffffffu, tm, 1));
            tm = fmaxf(tm, __shfl_xor_sync(0xffffffffu, tm, 2));
            float newm = fmaxf(m8, tm);
            float f = __expf(m8 - newm);
            m8 = newm;
            float p0 = __expf(v0.x - newm), p1 = __expf(v0.y - newm);
            float p2 = __expf(v0.z - newm), p3 = __expf(v0.w - newm);
            float p4 = __expf(v1.x - newm), p5 = __expf(v1.y - newm);
            float p6 = __expf(v1.z - newm), p7 = __expf(v1.w - newm);
            float psum = p0+p1+p2+p3+p4+p5+p6+p7;
            psum += __shfl_xor_sync(0xffffffffu, psum, 1);
            psum += __shfl_xor_sync(0xffffffffu, psum, 2);
            l8 = l8 * f + psum;
            float4 w0, w1;
            w0.x = __uint_as_float(f2tf32(p0)); w0.y = __uint_as_float(f2tf32(p1));
            w0.z = __uint_as_float(f2tf32(p2)); w0.w = __uint_as_float(f2tf32(p3));
            w1.x = __uint_as_float(f2tf32(p4)); w1.y = __uint_as_float(f2tf32(p5));
            w1.z = __uint_as_float(f2tf32(p6)); w1.w = __uint_as_float(f2tf32(p7));
            *(float4*)&ps[sr*36 + 8*scg]     = w0;
            *(float4*)&ps[sr*36 + 8*scg + 4] = w1;
            if (scg == 0) fct[sr] = f;
        }
        __syncthreads();

        {
            float f0 = fct[mb+lr], f1 = fct[mb+lr+8];
#pragma unroll
            for (int t = 0; t < 4; t++) {
                oacc[t][0] *= f0; oacc[t][1] *= f0;
                oacc[t][2] *= f1; oacc[t][3] *= f1;
            }
        }
#pragma unroll
        for (int k0 = 0; k0 < 32; k0 += 8) {
            unsigned a0 = __float_as_uint(ps[(mb+lr)*36   + k0+lc]);
            unsigned a1 = __float_as_uint(ps[(mb+lr+8)*36 + k0+lc]);
            unsigned a2 = __float_as_uint(ps[(mb+lr)*36   + k0+lc+4]);
            unsigned a3 = __float_as_uint(ps[(mb+lr+8)*36 + k0+lc+4]);
#pragma unroll
            for (int t = 0; t < 4; t++) {
                int n0 = 32*wn + 8*t;
                unsigned b0 = __float_as_uint(vt[(n0+lr)*36 + k0+lc]);
                unsigned b1 = __float_as_uint(vt[(n0+lr)*36 + k0+lc+4]);
                mma_tf32(oacc[t], a0, a1, a2, a3, b0, b1);
            }
        }
    }

    if (scg == 0) linv[sr] = 1.f / l8;
    __syncthreads();

    float i0 = linv[mb+lr], i1 = linv[mb+lr+8];
    if (mode == 0) {
#pragma unroll
        for (int t = 0; t < 4; t++) {
            int col = 32*wn + 8*t + 2*lc;
            float* o0 = &out[(size_t)(G*NN + q0 + mb + lr)*64 + col];
            float* o1 = &out[(size_t)(G*NN + q0 + mb + lr + 8)*64 + col];
            o0[0] = oacc[t][0]*i0; o0[1] = oacc[t][1]*i0;
            o1[0] = oacc[t][2]*i1; o1[1] = oacc[t][3]*i1;
        }
    } else {
#pragma unroll
        for (int t = 0; t < 4; t++) {
            int col = 32*wn + 8*t + 2*lc;
            os[(mb+lr)*68 + col]     = oacc[t][0]*i0;
            os[(mb+lr)*68 + col + 1] = oacc[t][1]*i0;
            os[(mb+lr+8)*68 + col]     = oacc[t][2]*i1;
            os[(mb+lr+8)*68 + col + 1] = oacc[t][3]*i1;
        }
        __syncthreads();
        int sIdx = G >> 4, g2 = G & 15;
        int b = g2 >> 2, seg = g2 & 3;
        int o = sIdx*LAY + layer;
        const float* gg = g_  + (size_t)o*64;
        const float* bbp = bb_ + (size_t)o*64;
#pragma unroll
        for (int rr = 0; rr < 8; rr++) {
            int r = wid*8 + rr;
            int n = q0 + r;
            float* zp = out + (size_t)(sIdx*TOK + ((b<<10)+n)*SG + seg)*HID;
            float v0 = os[r*68 + lane], v1 = os[r*68 + lane + 32];
            float ssum = v0 + v1, qq = v0*v0 + v1*v1;
#pragma unroll
            for (int off = 16; off; off >>= 1) {
                ssum += __shfl_xor_sync(0xffffffffu, ssum, off);
                qq   += __shfl_xor_sync(0xffffffffu, qq, off);
            }
            float mean = ssum * (1.f/64.f);
            float var  = qq * (1.f/64.f) - mean*mean;
            float rstd = rsqrtf(var + 1e-5f);
            zp[lane]      = (v0 - mean)*rstd*gg[lane]    + bbp[lane]    + zp[lane];
            zp[lane + 32] = (v1 - mean)*rstd*gg[lane+32] + bbp[lane+32] + zp[lane + 32];
        }
    }
}

// ---------------- mean-pool over segments + concat (both streams) ----------------
__global__ __launch_bounds__(256) void pool_kernel(const float* __restrict__ Z,
        float* __restrict__ ENC) {
    int idx = blockIdx.x * 256 + threadIdx.x;   // over 2*B*NN*64
    int s  = idx >> 18;
    int rem = idx & 262143;
    int bn = rem >> 6, h = rem & 63;
    const float* zp = Z + (size_t)(s*TOK + bn*4)*64;
    float a = 0.25f * (zp[0*64+h] + zp[1*64+h] + zp[2*64+h] + zp[3*64+h]);
    ENC[(size_t)bn*128 + s*64 + h] = a;
}

// ---------------- final cross-attention projections (in dim = 128) ----------------
__global__ __launch_bounds__(256) void fproj_kernel(const float* __restrict__ ENC,
        const float* __restrict__ wq, const float* __restrict__ wk, const float* __restrict__ wv,
        float* __restrict__ Q, float* __restrict__ K, float* __restrict__ V) {
    __shared__ float xs[64][68];
    __shared__ float ws[64][68];
    int tid = threadIdx.x;
    int r0 = blockIdx.x * 64;
    int ty = tid >> 4, tx = tid & 15;
    float acc[2][4][4];
#pragma unroll
    for (int oc = 0; oc < 2; oc++)
#pragma unroll
        for (int i = 0; i < 4; i++)
#pragma unroll
            for (int j = 0; j < 4; j++) acc[oc][i][j] = 0.f;

    for (int kc = 0; kc < 2; kc++) {
        __syncthreads();
        for (int idx = tid; idx < 64*64; idx += 256) {
            int r = idx >> 6, c = idx & 63;
            xs[r][c] = ENC[(size_t)(r0+r)*128 + kc*64 + c];
        }
        for (int oc = 0; oc < 2; oc++) {
            __syncthreads();
            for (int idx = tid; idx < 64*64; idx += 256) {
                int r = idx >> 6, c = idx & 63;
                int gc = oc*64 + r;
                int k  = kc*64 + c;
                ws[r][c] = (gc < 32) ? wq[gc*128 + k] : (gc < 64) ? wk[(gc-32)*128 + k] : wv[(gc-64)*128 + k];
            }
            __syncthreads();
#pragma unroll 4
            for (int k = 0; k < 64; k += 4) {
                float4 xv[4], wv4[4];
#pragma unroll
                for (int i = 0; i < 4; i++) xv[i] = *(const float4*)&xs[4*ty+i][k];
#pragma unroll
                for (int j = 0; j < 4; j++) wv4[j] = *(const float4*)&ws[tx+16*j][k];
#pragma unroll
                for (int i = 0; i < 4; i++)
#pragma unroll
                    for (int j = 0; j < 4; j++)
                        acc[oc][i][j] += xv[i].x*wv4[j].x + xv[i].y*wv4[j].y + xv[i].z*wv4[j].z + xv[i].w*wv4[j].w;
            }
        }
    }
#pragma unroll
    for (int oc = 0; oc < 2; oc++)
#pragma unroll
        for (int i = 0; i < 4; i++) {
            int gr = r0 + 4*ty + i;
#pragma unroll
            for (int j = 0; j < 4; j++) {
                int gc = oc*64 + tx + 16*j;
                float v = acc[oc][i][j];
                if (gc < 32)      Q[(size_t)gr*32 + gc] = v;
                else if (gc < 64) K[(size_t)gr*32 + gc - 32] = v;
                else              V[(size_t)gr*64 + gc - 64] = v;
            }
        }
}

// ---------------- host launcher ----------------
extern "C" void kernel_launch(void* const* d_in, const int* in_sizes, int n_in,
                              void* d_out, int out_size) {
    const float* traffic  = (const float*)d_in[0];
    const float* user     = (const float*)d_in[1];
    const float* patch_w  = (const float*)d_in[2];
    const float* patch_b  = (const float*)d_in[3];
    const float* mha_w    = (const float*)d_in[4];
    const float* mha_b    = (const float*)d_in[5];
    const float* out_w    = (const float*)d_in[6];
    const float* out_b    = (const float*)d_in[7];
    const float* ff1_w    = (const float*)d_in[8];
    const float* ff1_b    = (const float*)d_in[9];
    const float* ff2_w    = (const float*)d_in[10];
    const float* ff2_b    = (const float*)d_in[11];
    const float* ln1_g    = (const float*)d_in[12];
    const float* ln1_b    = (const float*)d_in[13];
    const float* ln2_g    = (const float*)d_in[14];
    const float* ln2_b    = (const float*)d_in[15];
    const float* ga_wq    = (const float*)d_in[16];
    const float* ga_wk    = (const float*)d_in[17];
    const float* ga_wv    = (const float*)d_in[18];
    const float* ga_ff1_w = (const float*)d_in[19];
    const float* ga_ff1_b = (const float*)d_in[20];
    const float* ga_ff2_w = (const float*)d_in[21];
    const float* ga_ff2_b = (const float*)d_in[22];
    const float* ga_ln1_g = (const float*)d_in[23];
    const float* ga_ln1_b = (const float*)d_in[24];
    const float* ga_ln2_g = (const float*)d_in[25];
    const float* ga_ln2_b = (const float*)d_in[26];
    const float* ca_wq    = (const float*)d_in[27];
    const float* ca_wk    = (const float*)d_in[28];
    const float* ca_wv    = (const float*)d_in[29];

    float *Z, *Qb, *Kb, *Vb, *ENC, *Q2, *K2, *V2;
    cudaGetSymbolAddress((void**)&Z,   d_Z);
    cudaGetSymbolAddress((void**)&Qb,  d_Qb);
    cudaGetSymbolAddress((void**)&Kb,  d_Kb);
    cudaGetSymbolAddress((void**)&Vb,  d_Vb);
    cudaGetSymbolAddress((void**)&ENC, d_ENC);
    cudaGetSymbolAddress((void**)&Q2,  d_Q2);
    cudaGetSymbolAddress((void**)&K2,  d_K2);
    cudaGetSymbolAddress((void**)&V2,  d_V2);

    const int MHA_SMEM = MHA_SMEM_FLOATS * 4;   // 111,616 B
    const int FF_SMEM  = FF_SMEM_FLOATS * 4;    // 171,008 B
    cudaFuncSetAttribute(mha_kernel,   cudaFuncAttributeMaxDynamicSharedMemorySize, MHA_SMEM);
    cudaFuncSetAttribute(ff_ln_kernel, cudaFuncAttributeMaxDynamicSharedMemorySize, FF_SMEM);

    const float SCALE32 = 0.17677669529663687f;   // 1/sqrt(32)

    patch_kernel<<<2*B_*NN, 256>>>(traffic, user, patch_w, patch_b, Z);
    for (int i = 0; i < LAY; i++) {
        mha_kernel<<<2*TOK/64, 256, MHA_SMEM>>>(Z, mha_w, mha_b, out_w, out_b, ln1_g, ln1_b, i);
        ff_ln_kernel<<<2*TOK/128, 256, FF_SMEM>>>(Z, ff1_w, ff1_b, ff2_w, ff2_b, ln2_g, ln2_b, i);
        ga_qkv_kernel<<<2*TOK/64, 256>>>(Z, ga_wq, ga_wk, ga_wv, Qb, Kb, Vb, i);
        attn_kernel<<<dim3(2*GRP, NN/64), 256>>>(Qb, Kb, Vb, Z, ga_ln1_g, ga_ln1_b, i, 1, SCALE32);
        ff_ln_kernel<<<2*TOK/128, 256, FF_SMEM>>>(Z, ga_ff1_w, ga_ff1_b, ga_ff2_w, ga_ff2_b, ga_ln2_g, ga_ln2_b, i);
    }
    pool_kernel<<<2*B_*NN*HID/256, 256>>>(Z, ENC);
    fproj_kernel<<<B_*NN/64, 256>>>(ENC, ca_wq, ca_wk, ca_wv, Q2, K2, V2);
    attn_kernel<<<dim3(B_, NN/64), 256>>>(Q2, K2, V2, (float*)d_out, (const float*)0, (const float*)0, 0, 0, SCALE32);
}